// round 1
// baseline (speedup 1.0000x reference)
#include <cuda_runtime.h>
#include <math.h>
#include <stdint.h>

#define N_TOK 2048
#define D_DIM 1024
#define F_DIM 2048
#define N_EXP 8
#define N_HEAD 16
#define S_LEN 1024

// ---------------- scratch (device globals; no allocation allowed) ----------
__device__ float g_q[N_TOK * D_DIM];
__device__ float g_k[N_TOK * D_DIM];
__device__ float g_v[N_TOK * D_DIM];
__device__ float g_attno[N_TOK * D_DIM];
__device__ float g_gated[N_TOK * D_DIM];
__device__ float g_attnp[N_TOK * D_DIM];
__device__ float g_x[N_TOK * D_DIM];
__device__ float g_hh[N_TOK * F_DIM];
__device__ float g_moe[N_TOK * D_DIM];
__device__ int   g_chosen[N_TOK];
__device__ int   g_counts[N_EXP];
__device__ int   g_offsets[N_EXP];
__device__ int   g_cursor[N_EXP];
__device__ int   g_p2t[N_TOK];
__device__ int   g_p2e[N_TOK];

// ---------------- generic tiled SGEMM: C[M,N] = A[M,K] @ B[K,N] ------------
// mode 0: C = acc + bias(optional)
// mode 1: C = sigmoid(acc + bias) * aux[r,c]
__global__ void gemm_kernel(const float* __restrict__ A, const float* __restrict__ B,
                            const float* __restrict__ bias, const float* __restrict__ aux,
                            float* __restrict__ C, int M, int N, int K, int mode)
{
    __shared__ float As[16][64];  // [k][row]
    __shared__ float Bs[16][64];  // [k][col]
    const int t = threadIdx.x;
    const int tx = t & 15, ty = t >> 4;
    const int row0 = blockIdx.y * 64, col0 = blockIdx.x * 64;
    const int alr = t >> 2, akseg = (t & 3) * 4;   // A loader: row, k-offset
    const int bkr = t >> 4, bcs = (t & 15) * 4;    // B loader: k-row, col-offset
    float acc[4][4] = {};
    for (int k0 = 0; k0 < K; k0 += 16) {
        float4 av = make_float4(0.f, 0.f, 0.f, 0.f);
        if (row0 + alr < M)
            av = *(const float4*)&A[(size_t)(row0 + alr) * K + k0 + akseg];
        As[akseg + 0][alr] = av.x; As[akseg + 1][alr] = av.y;
        As[akseg + 2][alr] = av.z; As[akseg + 3][alr] = av.w;
        *(float4*)&Bs[bkr][bcs] = *(const float4*)&B[(size_t)(k0 + bkr) * N + col0 + bcs];
        __syncthreads();
#pragma unroll
        for (int kk = 0; kk < 16; ++kk) {
            float4 a4 = *(const float4*)&As[kk][ty * 4];
            float4 b4 = *(const float4*)&Bs[kk][tx * 4];
            float a[4] = {a4.x, a4.y, a4.z, a4.w};
            float b[4] = {b4.x, b4.y, b4.z, b4.w};
#pragma unroll
            for (int i = 0; i < 4; ++i)
#pragma unroll
                for (int j = 0; j < 4; ++j) acc[i][j] += a[i] * b[j];
        }
        __syncthreads();
    }
#pragma unroll
    for (int i = 0; i < 4; ++i) {
        int r = row0 + ty * 4 + i;
        if (r >= M) continue;
#pragma unroll
        for (int j = 0; j < 4; ++j) {
            int c = col0 + tx * 4 + j;
            float v = acc[i][j] + (bias ? bias[c] : 0.f);
            if (mode == 1) v = aux[(size_t)r * N + c] / (1.f + expf(-v));
            C[(size_t)r * N + c] = v;
        }
    }
}

// ---------------- flash-style attention, 64 q-rows per CTA ------------------
// q,k,v: [N_TOK, D] with head h occupying cols [h*64, h*64+64)
#define ATTN_SMEM ((68*64*2 + 64*64 + 65*64 + 5*64) * 4)
__global__ void attn_kernel(const float* __restrict__ q, const float* __restrict__ k,
                            const float* __restrict__ v, const float* __restrict__ scale_w,
                            float* __restrict__ out)
{
    extern __shared__ float sm[];
    float* QsT = sm;               // [d][row] pitch 68
    float* KsT = QsT + 68 * 64;    // [d][row] pitch 68
    float* Vs  = KsT + 68 * 64;    // [krow][d] pitch 64
    float* Ps  = Vs + 64 * 64;     // [qrow][k] pitch 65
    float* mrow = Ps + 65 * 64;
    float* lrow = mrow + 64;
    float* frow = lrow + 64;
    float* qsc  = frow + 64;
    float* sw   = qsc + 64;

    const int t = threadIdx.x;
    const int tx = t & 15, ty = t >> 4;
    const int bh = blockIdx.y;
    const int h = bh & 15, b = bh >> 4;
    const int q0 = blockIdx.x * 64;
    const int qtok0 = b * S_LEN + q0;

    if (t < 64) sw[t] = scale_w[h * 64 + t];
#pragma unroll
    for (int it = 0; it < 16; ++it) {
        int idx = t + it * 256;
        int r = idx >> 6, d = idx & 63;
        QsT[d * 68 + r] = q[(size_t)(qtok0 + r) * D_DIM + h * 64 + d];
    }
    __syncthreads();
    if (t < 64) {
        float s = 0.f;
        for (int d = 0; d < 64; ++d) s += QsT[d * 68 + t] * sw[d];
        qsc[t] = 2.f / (1.f + expf(-s));
        mrow[t] = -1e30f;
        lrow[t] = 0.f;
    }
    float o[4][4] = {};
    for (int kt = 0; kt < 16; ++kt) {
        __syncthreads();
        const int ktok0 = b * S_LEN + kt * 64;
#pragma unroll
        for (int it = 0; it < 16; ++it) {
            int idx = t + it * 256;
            int r = idx >> 6, d = idx & 63;
            KsT[d * 68 + r] = k[(size_t)(ktok0 + r) * D_DIM + h * 64 + d];
            Vs[r * 64 + d]  = v[(size_t)(ktok0 + r) * D_DIM + h * 64 + d];
        }
        __syncthreads();
        float s[4][4] = {};
#pragma unroll 8
        for (int kk = 0; kk < 64; ++kk) {
            float4 a4 = *(const float4*)&QsT[kk * 68 + ty * 4];
            float4 b4 = *(const float4*)&KsT[kk * 68 + tx * 4];
            float a[4] = {a4.x, a4.y, a4.z, a4.w};
            float bb[4] = {b4.x, b4.y, b4.z, b4.w};
#pragma unroll
            for (int i = 0; i < 4; ++i)
#pragma unroll
                for (int j = 0; j < 4; ++j) s[i][j] += a[i] * bb[j];
        }
#pragma unroll
        for (int i = 0; i < 4; ++i) {
            float sc = qsc[ty * 4 + i] * 0.125f;
#pragma unroll
            for (int j = 0; j < 4; ++j)
                Ps[(ty * 4 + i) * 65 + tx * 4 + j] = s[i][j] * sc;
        }
        __syncthreads();
        if (t < 64) {
            float m0 = mrow[t], rm = -1e30f;
            for (int kk = 0; kk < 64; ++kk) rm = fmaxf(rm, Ps[t * 65 + kk]);
            float nm = fmaxf(m0, rm);
            float f = expf(m0 - nm);
            float sum = 0.f;
            for (int kk = 0; kk < 64; ++kk) {
                float p = expf(Ps[t * 65 + kk] - nm);
                Ps[t * 65 + kk] = p;
                sum += p;
            }
            lrow[t] = lrow[t] * f + sum;
            mrow[t] = nm;
            frow[t] = f;
        }
        __syncthreads();
#pragma unroll
        for (int i = 0; i < 4; ++i) {
            float f = frow[ty * 4 + i];
#pragma unroll
            for (int j = 0; j < 4; ++j) o[i][j] *= f;
        }
#pragma unroll 8
        for (int kk = 0; kk < 64; ++kk) {
            float4 v4 = *(const float4*)&Vs[kk * 64 + tx * 4];
#pragma unroll
            for (int i = 0; i < 4; ++i) {
                float p = Ps[(ty * 4 + i) * 65 + kk];
                o[i][0] += p * v4.x; o[i][1] += p * v4.y;
                o[i][2] += p * v4.z; o[i][3] += p * v4.w;
            }
        }
    }
#pragma unroll
    for (int i = 0; i < 4; ++i) {
        float inv = 1.f / lrow[ty * 4 + i];
#pragma unroll
        for (int j = 0; j < 4; ++j)
            out[(size_t)(qtok0 + ty * 4 + i) * D_DIM + h * 64 + tx * 4 + j] = o[i][j] * inv;
    }
}

// ---------------- layernorm over residual sum -------------------------------
__global__ void ln2_kernel(const float* __restrict__ a, const float* __restrict__ b,
                           const float* __restrict__ g, const float* __restrict__ be,
                           float* __restrict__ out, int D)
{
    const int row = blockIdx.x, t = threadIdx.x;
    __shared__ float red[256];
    __shared__ float s_mean, s_rstd;
    float s1 = 0.f, s2 = 0.f;
    for (int i = t; i < D; i += 256) {
        float v = a[(size_t)row * D + i] + b[(size_t)row * D + i];
        s1 += v; s2 += v * v;
    }
    red[t] = s1; __syncthreads();
    for (int o = 128; o; o >>= 1) { if (t < o) red[t] += red[t + o]; __syncthreads(); }
    if (t == 0) s_mean = red[0] / D;
    __syncthreads();
    red[t] = s2; __syncthreads();
    for (int o = 128; o; o >>= 1) { if (t < o) red[t] += red[t + o]; __syncthreads(); }
    if (t == 0) {
        float var = red[0] / D - s_mean * s_mean;
        s_rstd = rsqrtf(var + 1e-5f);
    }
    __syncthreads();
    for (int i = t; i < D; i += 256) {
        float v = a[(size_t)row * D + i] + b[(size_t)row * D + i];
        out[(size_t)row * D + i] = (v - s_mean) * s_rstd * g[i] + be[i];
    }
}

// ---------------- MoE routing ------------------------------------------------
__global__ void reset_kernel() { if (threadIdx.x < N_EXP) g_counts[threadIdx.x] = 0; }

__global__ void moe_gate_kernel(const float* __restrict__ x, const float* __restrict__ W,
                                const float* __restrict__ bias)
{
    const int n = blockIdx.x, t = threadIdx.x;
    const int e = t >> 5, lane = t & 31;
    float acc = 0.f;
    for (int d = lane; d < D_DIM; d += 32) acc += x[(size_t)n * D_DIM + d] * W[d * N_EXP + e];
    for (int o = 16; o; o >>= 1) acc += __shfl_down_sync(0xffffffffu, acc, o);
    __shared__ float lg[N_EXP];
    if (lane == 0) lg[e] = acc + bias[e];
    __syncthreads();
    if (t == 0) {
        int i1 = 0; float v1 = lg[0];
        for (int i = 1; i < N_EXP; ++i) if (lg[i] > v1) { v1 = lg[i]; i1 = i; }
        int i2 = -1; float v2 = -1e30f;
        for (int i = 0; i < N_EXP; ++i) {
            if (i == i1) continue;
            if (lg[i] > v2) { v2 = lg[i]; i2 = i; }
        }
        int c = (i1 > i2) ? i1 : i2;          // torch loop: max-index expert wins
        g_chosen[n] = c;
        atomicAdd(&g_counts[c], 1);
    }
}

__global__ void scan_kernel()
{
    if (threadIdx.x == 0) {
        int s = 0;
        for (int e = 0; e < N_EXP; ++e) { g_offsets[e] = s; g_cursor[e] = s; s += g_counts[e]; }
    }
}

__global__ void scatter_kernel()
{
    int n = blockIdx.x * 256 + threadIdx.x;
    if (n < N_TOK) {
        int c = g_chosen[n];
        int p = atomicAdd(&g_cursor[c], 1);
        g_p2t[p] = n;
        g_p2e[p] = c;
    }
}

// ---------------- expert GEMM 1: hh[p,F] = x[tok] @ w1[e] + b1[e] ----------
__global__ void expert1_kernel(const float* __restrict__ x, const float* __restrict__ w1,
                               const float* __restrict__ b1, float* __restrict__ hh)
{
    const int e = blockIdx.z;
    const int cnt = g_counts[e];
    const int rt = blockIdx.y * 64;
    if (rt >= cnt) return;
    const int off = g_offsets[e];
    __shared__ int rowtok[64];
    __shared__ float As[16][64];
    __shared__ float Bs[16][64];
    const int t = threadIdx.x;
    if (t < 64) rowtok[t] = (rt + t < cnt) ? g_p2t[off + rt + t] : -1;
    const int tx = t & 15, ty = t >> 4;
    const int col0 = blockIdx.x * 64;
    const int alr = t >> 2, akseg = (t & 3) * 4;
    const int bkr = t >> 4, bcs = (t & 15) * 4;
    const float* B = w1 + (size_t)e * D_DIM * F_DIM;
    float acc[4][4] = {};
    __syncthreads();
    for (int k0 = 0; k0 < D_DIM; k0 += 16) {
        int tok = rowtok[alr];
        float4 av = make_float4(0.f, 0.f, 0.f, 0.f);
        if (tok >= 0) av = *(const float4*)&x[(size_t)tok * D_DIM + k0 + akseg];
        As[akseg + 0][alr] = av.x; As[akseg + 1][alr] = av.y;
        As[akseg + 2][alr] = av.z; As[akseg + 3][alr] = av.w;
        *(float4*)&Bs[bkr][bcs] = *(const float4*)&B[(size_t)(k0 + bkr) * F_DIM + col0 + bcs];
        __syncthreads();
#pragma unroll
        for (int kk = 0; kk < 16; ++kk) {
            float4 a4 = *(const float4*)&As[kk][ty * 4];
            float4 b4 = *(const float4*)&Bs[kk][tx * 4];
            float a[4] = {a4.x, a4.y, a4.z, a4.w};
            float bb[4] = {b4.x, b4.y, b4.z, b4.w};
#pragma unroll
            for (int i = 0; i < 4; ++i)
#pragma unroll
                for (int j = 0; j < 4; ++j) acc[i][j] += a[i] * bb[j];
        }
        __syncthreads();
    }
#pragma unroll
    for (int i = 0; i < 4; ++i) {
        int lr = rt + ty * 4 + i;
        if (lr >= cnt) continue;
        int p = off + lr;
#pragma unroll
        for (int j = 0; j < 4; ++j) {
            int c = col0 + tx * 4 + j;
            hh[(size_t)p * F_DIM + c] = acc[i][j] + b1[(size_t)e * F_DIM + c];
        }
    }
}

// ---------------- per-expert LN + exact GELU over hh rows -------------------
__global__ void ln_gelu_kernel(float* __restrict__ hh, const float* __restrict__ ln_g,
                               const float* __restrict__ ln_b)
{
    const int p = blockIdx.x, t = threadIdx.x;
    const int e = g_p2e[p];
    float* row = hh + (size_t)p * F_DIM;
    const float* gg = ln_g + (size_t)e * F_DIM;
    const float* bb = ln_b + (size_t)e * F_DIM;
    __shared__ float red[256];
    __shared__ float s_mean, s_rstd;
    float s1 = 0.f, s2 = 0.f;
    for (int i = t; i < F_DIM; i += 256) { float v = row[i]; s1 += v; s2 += v * v; }
    red[t] = s1; __syncthreads();
    for (int o = 128; o; o >>= 1) { if (t < o) red[t] += red[t + o]; __syncthreads(); }
    if (t == 0) s_mean = red[0] / F_DIM;
    __syncthreads();
    red[t] = s2; __syncthreads();
    for (int o = 128; o; o >>= 1) { if (t < o) red[t] += red[t + o]; __syncthreads(); }
    if (t == 0) {
        float var = red[0] / F_DIM - s_mean * s_mean;
        s_rstd = rsqrtf(var + 1e-5f);
    }
    __syncthreads();
    for (int i = t; i < F_DIM; i += 256) {
        float tv = (row[i] - s_mean) * s_rstd * gg[i] + bb[i];
        row[i] = 0.5f * tv * (1.f + erff(tv * 0.70710678118654752f));
    }
}

// ---------------- expert GEMM 2 + residual scatter --------------------------
__global__ void expert2_kernel(const float* __restrict__ hh, const float* __restrict__ w2,
                               const float* __restrict__ b2, const float* __restrict__ res_scale,
                               const float* __restrict__ x, float* __restrict__ moe)
{
    const int e = blockIdx.z;
    const int cnt = g_counts[e];
    const int rt = blockIdx.y * 64;
    if (rt >= cnt) return;
    const int off = g_offsets[e];
    __shared__ int rowtok[64];
    __shared__ float As[16][64];
    __shared__ float Bs[16][64];
    const int t = threadIdx.x;
    if (t < 64) rowtok[t] = (rt + t < cnt) ? g_p2t[off + rt + t] : -1;
    const int tx = t & 15, ty = t >> 4;
    const int col0 = blockIdx.x * 64;
    const int alr = t >> 2, akseg = (t & 3) * 4;
    const int bkr = t >> 4, bcs = (t & 15) * 4;
    const float* B = w2 + (size_t)e * F_DIM * D_DIM;
    const float rsc = res_scale[e];
    float acc[4][4] = {};
    __syncthreads();
    for (int k0 = 0; k0 < F_DIM; k0 += 16) {
        float4 av = make_float4(0.f, 0.f, 0.f, 0.f);
        if (rt + alr < cnt)
            av = *(const float4*)&hh[(size_t)(off + rt + alr) * F_DIM + k0 + akseg];
        As[akseg + 0][alr] = av.x; As[akseg + 1][alr] = av.y;
        As[akseg + 2][alr] = av.z; As[akseg + 3][alr] = av.w;
        *(float4*)&Bs[bkr][bcs] = *(const float4*)&B[(size_t)(k0 + bkr) * D_DIM + col0 + bcs];
        __syncthreads();
#pragma unroll
        for (int kk = 0; kk < 16; ++kk) {
            float4 a4 = *(const float4*)&As[kk][ty * 4];
            float4 b4 = *(const float4*)&Bs[kk][tx * 4];
            float a[4] = {a4.x, a4.y, a4.z, a4.w};
            float bb[4] = {b4.x, b4.y, b4.z, b4.w};
#pragma unroll
            for (int i = 0; i < 4; ++i)
#pragma unroll
                for (int j = 0; j < 4; ++j) acc[i][j] += a[i] * bb[j];
        }
        __syncthreads();
    }
#pragma unroll
    for (int i = 0; i < 4; ++i) {
        int lr = rt + ty * 4 + i;
        if (lr >= cnt) continue;
        int tok = rowtok[ty * 4 + i];
#pragma unroll
        for (int j = 0; j < 4; ++j) {
            int c = col0 + tx * 4 + j;
            float v = (acc[i][j] + b2[(size_t)e * D_DIM + c]) * rsc + x[(size_t)tok * D_DIM + c];
            moe[(size_t)tok * D_DIM + c] = v;
        }
    }
}

// ---------------- host launcher ---------------------------------------------
extern "C" void kernel_launch(void* const* d_in, const int* in_sizes, int n_in,
                              void* d_out, int out_size)
{
    (void)in_sizes; (void)n_in; (void)out_size;
    const float* src        = (const float*)d_in[0];
    const float* q_w        = (const float*)d_in[1];
    const float* k_w        = (const float*)d_in[2];
    const float* v_w        = (const float*)d_in[3];
    const float* out_w      = (const float*)d_in[4];
    const float* gate_w     = (const float*)d_in[5];
    const float* gate_b     = (const float*)d_in[6];
    const float* scale_w    = (const float*)d_in[7];
    const float* n1_g       = (const float*)d_in[8];
    const float* n1_b       = (const float*)d_in[9];
    const float* n2_g       = (const float*)d_in[10];
    const float* n2_b       = (const float*)d_in[11];
    const float* moe_gate_w = (const float*)d_in[12];
    const float* moe_gate_b = (const float*)d_in[13];
    const float* w1         = (const float*)d_in[14];
    const float* b1         = (const float*)d_in[15];
    const float* ln_g       = (const float*)d_in[16];
    const float* ln_b       = (const float*)d_in[17];
    const float* w2         = (const float*)d_in[18];
    const float* b2         = (const float*)d_in[19];
    const float* res_scale  = (const float*)d_in[20];

    float *qb, *kb, *vb, *attno, *gated, *attnp, *xb, *hhb, *moeb;
    cudaGetSymbolAddress((void**)&qb, g_q);
    cudaGetSymbolAddress((void**)&kb, g_k);
    cudaGetSymbolAddress((void**)&vb, g_v);
    cudaGetSymbolAddress((void**)&attno, g_attno);
    cudaGetSymbolAddress((void**)&gated, g_gated);
    cudaGetSymbolAddress((void**)&attnp, g_attnp);
    cudaGetSymbolAddress((void**)&xb, g_x);
    cudaGetSymbolAddress((void**)&hhb, g_hh);
    cudaGetSymbolAddress((void**)&moeb, g_moe);

    cudaFuncSetAttribute(attn_kernel, cudaFuncAttributeMaxDynamicSharedMemorySize, ATTN_SMEM);

    reset_kernel<<<1, 32>>>();

    // QKV projections
    gemm_kernel<<<dim3(16, 32), 256>>>(src, q_w, nullptr, nullptr, qb, N_TOK, D_DIM, D_DIM, 0);
    gemm_kernel<<<dim3(16, 32), 256>>>(src, k_w, nullptr, nullptr, kb, N_TOK, D_DIM, D_DIM, 0);
    gemm_kernel<<<dim3(16, 32), 256>>>(src, v_w, nullptr, nullptr, vb, N_TOK, D_DIM, D_DIM, 0);

    // gated / dynamically-scaled attention
    attn_kernel<<<dim3(16, 32), 256, ATTN_SMEM>>>(qb, kb, vb, scale_w, attno);

    // gate = sigmoid(out@gate_w + gate_b); gated = out * gate; attn = gated @ out_w
    gemm_kernel<<<dim3(16, 32), 256>>>(attno, gate_w, gate_b, attno, gated, N_TOK, D_DIM, D_DIM, 1);
    gemm_kernel<<<dim3(16, 32), 256>>>(gated, out_w, nullptr, nullptr, attnp, N_TOK, D_DIM, D_DIM, 0);

    // x = LN(src + attn)
    ln2_kernel<<<N_TOK, 256>>>(src, attnp, n1_g, n1_b, xb, D_DIM);

    // MoE routing (top-2 weights sum to 1 -> only max-index expert runs)
    moe_gate_kernel<<<N_TOK, 256>>>(xb, moe_gate_w, moe_gate_b);
    scan_kernel<<<1, 32>>>();
    scatter_kernel<<<N_TOK / 256, 256>>>();

    // expert FFN on routed tokens
    expert1_kernel<<<dim3(F_DIM / 64, N_TOK / 64, N_EXP), 256>>>(xb, w1, b1, hhb);
    ln_gelu_kernel<<<N_TOK, 256>>>(hhb, ln_g, ln_b);
    expert2_kernel<<<dim3(D_DIM / 64, N_TOK / 64, N_EXP), 256>>>(hhb, w2, b2, res_scale, xb, moeb);

    // final LN
    ln2_kernel<<<N_TOK, 256>>>(xb, moeb, n2_g, n2_b, (float*)d_out, D_DIM);
}

// round 2
// speedup vs baseline: 1.0291x; 1.0291x over previous
#include <cuda_runtime.h>
#include <math.h>
#include <stdint.h>

#define N_TOK 2048
#define D_DIM 1024
#define F_DIM 2048
#define N_EXP 8
#define N_HEAD 16
#define S_LEN 1024

// ---------------- scratch (device globals; no allocation allowed) ----------
__device__ float g_q[N_TOK * D_DIM];
__device__ float g_k[N_TOK * D_DIM];
__device__ float g_v[N_TOK * D_DIM];
__device__ float g_attno[N_TOK * D_DIM];
__device__ float g_gated[N_TOK * D_DIM];
__device__ float g_attnp[N_TOK * D_DIM];
__device__ float g_x[N_TOK * D_DIM];
__device__ float g_hh[N_TOK * F_DIM];
__device__ float g_moe[N_TOK * D_DIM];
__device__ int   g_chosen[N_TOK];
__device__ int   g_counts[N_EXP];
__device__ int   g_offsets[N_EXP];
__device__ int   g_cursor[N_EXP];
__device__ int   g_p2t[N_TOK];
__device__ int   g_p2e[N_TOK];

// ============ 128x128 tile SGEMM, 8x8 microtile, double-buffered ============
// C[M,N] = A[M,K] @ B[K,N]; mode 0: +bias(optional); mode 1: sigmoid(.)*aux
// Requires M%128==0, N%128==0, K%16==0 (true for all dense calls here).
__global__ __launch_bounds__(256, 2)
void gemm128_kernel(const float* __restrict__ A, const float* __restrict__ B,
                    const float* __restrict__ bias, const float* __restrict__ aux,
                    float* __restrict__ C, int M, int N, int K, int mode)
{
    __shared__ float As[2][16][132];   // [buf][k][row]
    __shared__ float Bs[2][16][128];   // [buf][k][col]
    const int t = threadIdx.x;
    const int tx = t & 15, ty = t >> 4;
    const int row0 = blockIdx.y * 128, col0 = blockIdx.x * 128;
    const int ar = t >> 2, ak = (t & 3) * 4;   // A loader: row (0..63), k-offset
    const int bk = t >> 5, bc = (t & 31) * 4;  // B loader: k-row (0..7), col-offset

    const float* Ap0 = A + (size_t)(row0 + ar) * K + ak;
    const float* Ap1 = Ap0 + (size_t)64 * K;
    const float* Bp0 = B + (size_t)bk * N + col0 + bc;
    const float* Bp1 = Bp0 + (size_t)8 * N;

    // prologue: chunk 0 -> buf 0
    {
        float4 a0 = *(const float4*)Ap0;
        float4 a1 = *(const float4*)Ap1;
        float4 b0 = *(const float4*)Bp0;
        float4 b1 = *(const float4*)Bp1;
        As[0][ak + 0][ar] = a0.x; As[0][ak + 1][ar] = a0.y; As[0][ak + 2][ar] = a0.z; As[0][ak + 3][ar] = a0.w;
        As[0][ak + 0][ar + 64] = a1.x; As[0][ak + 1][ar + 64] = a1.y; As[0][ak + 2][ar + 64] = a1.z; As[0][ak + 3][ar + 64] = a1.w;
        *(float4*)&Bs[0][bk][bc] = b0;
        *(float4*)&Bs[0][bk + 8][bc] = b1;
    }
    __syncthreads();

    float acc[8][8] = {};
    int buf = 0;
    for (int k0 = 16; k0 <= K; k0 += 16) {
        const bool nx = (k0 < K);
        float4 na0, na1, nb0, nb1;
        if (nx) {
            na0 = *(const float4*)(Ap0 + k0);
            na1 = *(const float4*)(Ap1 + k0);
            nb0 = *(const float4*)(Bp0 + (size_t)k0 * N);
            nb1 = *(const float4*)(Bp1 + (size_t)k0 * N);
        }
#pragma unroll
        for (int kk = 0; kk < 16; ++kk) {
            float a[8], b[8];
            *(float4*)&a[0] = *(const float4*)&As[buf][kk][ty * 8];
            *(float4*)&a[4] = *(const float4*)&As[buf][kk][ty * 8 + 4];
            *(float4*)&b[0] = *(const float4*)&Bs[buf][kk][tx * 8];
            *(float4*)&b[4] = *(const float4*)&Bs[buf][kk][tx * 8 + 4];
#pragma unroll
            for (int i = 0; i < 8; ++i)
#pragma unroll
                for (int j = 0; j < 8; ++j) acc[i][j] += a[i] * b[j];
        }
        if (nx) {
            int nb = buf ^ 1;
            As[nb][ak + 0][ar] = na0.x; As[nb][ak + 1][ar] = na0.y; As[nb][ak + 2][ar] = na0.z; As[nb][ak + 3][ar] = na0.w;
            As[nb][ak + 0][ar + 64] = na1.x; As[nb][ak + 1][ar + 64] = na1.y; As[nb][ak + 2][ar + 64] = na1.z; As[nb][ak + 3][ar + 64] = na1.w;
            *(float4*)&Bs[nb][bk][bc] = nb0;
            *(float4*)&Bs[nb][bk + 8][bc] = nb1;
            __syncthreads();
            buf = nb;
        }
    }

#pragma unroll
    for (int i = 0; i < 8; ++i) {
        const int r = row0 + ty * 8 + i;
        const size_t base = (size_t)r * N + col0 + tx * 8;
        float v[8];
#pragma unroll
        for (int j = 0; j < 8; ++j) {
            v[j] = acc[i][j] + (bias ? bias[col0 + tx * 8 + j] : 0.f);
            if (mode == 1) v[j] = aux[base + j] / (1.f + expf(-v[j]));
        }
        *(float4*)&C[base]     = make_float4(v[0], v[1], v[2], v[3]);
        *(float4*)&C[base + 4] = make_float4(v[4], v[5], v[6], v[7]);
    }
}

// ---------------- flash-style attention, 64 q-rows per CTA ------------------
#define ATTN_SMEM ((68*64*2 + 64*64 + 65*64 + 5*64 + 64*4) * 4)
__global__ void attn_kernel(const float* __restrict__ q, const float* __restrict__ k,
                            const float* __restrict__ v, const float* __restrict__ scale_w,
                            float* __restrict__ out)
{
    extern __shared__ float sm[];
    float* QsT = sm;               // [d][row] pitch 68
    float* KsT = QsT + 68 * 64;    // [d][row] pitch 68
    float* Vs  = KsT + 68 * 64;    // [krow][d] pitch 64
    float* Ps  = Vs + 64 * 64;     // [qrow][k] pitch 65
    float* mrow = Ps + 65 * 64;
    float* lrow = mrow + 64;
    float* frow = lrow + 64;
    float* qsc  = frow + 64;
    float* sw   = qsc + 64;
    float* red4 = sw + 64;         // [row][4]

    const int t = threadIdx.x;
    const int tx = t & 15, ty = t >> 4;
    const int bh = blockIdx.y;
    const int h = bh & 15, b = bh >> 4;
    const int q0 = blockIdx.x * 64;
    const int qtok0 = b * S_LEN + q0;

    if (t < 64) sw[t] = scale_w[h * 64 + t];
#pragma unroll
    for (int it = 0; it < 16; ++it) {
        int idx = t + it * 256;
        int r = idx >> 6, d = idx & 63;
        QsT[d * 68 + r] = q[(size_t)(qtok0 + r) * D_DIM + h * 64 + d];
    }
    __syncthreads();
    if (t < 64) {
        float s = 0.f;
        for (int d = 0; d < 64; ++d) s += QsT[d * 68 + t] * sw[d];
        qsc[t] = 2.f / (1.f + expf(-s));
        mrow[t] = -1e30f;
        lrow[t] = 0.f;
    }
    float o[4][4] = {};
    for (int kt = 0; kt < 16; ++kt) {
        __syncthreads();
        const int ktok0 = b * S_LEN + kt * 64;
#pragma unroll
        for (int it = 0; it < 16; ++it) {
            int idx = t + it * 256;
            int r = idx >> 6, d = idx & 63;
            KsT[d * 68 + r] = k[(size_t)(ktok0 + r) * D_DIM + h * 64 + d];
            Vs[r * 64 + d]  = v[(size_t)(ktok0 + r) * D_DIM + h * 64 + d];
        }
        __syncthreads();
        float s[4][4] = {};
#pragma unroll 8
        for (int kk = 0; kk < 64; ++kk) {
            float4 a4 = *(const float4*)&QsT[kk * 68 + ty * 4];
            float4 b4 = *(const float4*)&KsT[kk * 68 + tx * 4];
            float a[4] = {a4.x, a4.y, a4.z, a4.w};
            float bb[4] = {b4.x, b4.y, b4.z, b4.w};
#pragma unroll
            for (int i = 0; i < 4; ++i)
#pragma unroll
                for (int j = 0; j < 4; ++j) s[i][j] += a[i] * bb[j];
        }
#pragma unroll
        for (int i = 0; i < 4; ++i) {
            float sc = qsc[ty * 4 + i] * 0.125f;
#pragma unroll
            for (int j = 0; j < 4; ++j)
                Ps[(ty * 4 + i) * 65 + tx * 4 + j] = s[i][j] * sc;
        }
        __syncthreads();
        // --- softmax: 4 threads per row ---
        {
            const int r = t >> 2, part = t & 3;
            float* prow = &Ps[r * 65 + part * 16];
            float pm = -1e30f;
#pragma unroll
            for (int i = 0; i < 16; ++i) pm = fmaxf(pm, prow[i]);
            red4[r * 4 + part] = pm;
            __syncthreads();
            float nm = fmaxf(fmaxf(red4[r * 4 + 0], red4[r * 4 + 1]),
                             fmaxf(red4[r * 4 + 2], red4[r * 4 + 3]));
            nm = fmaxf(nm, mrow[r]);
            float sum = 0.f;
#pragma unroll
            for (int i = 0; i < 16; ++i) {
                float p = __expf(prow[i] - nm);
                prow[i] = p;
                sum += p;
            }
            __syncthreads();               // pm reads done before reuse of red4
            red4[r * 4 + part] = sum;
            __syncthreads();
            if (part == 0) {
                float s4 = red4[r * 4] + red4[r * 4 + 1] + red4[r * 4 + 2] + red4[r * 4 + 3];
                float f = __expf(mrow[r] - nm);
                lrow[r] = lrow[r] * f + s4;
                mrow[r] = nm;
                frow[r] = f;
            }
        }
        __syncthreads();
#pragma unroll
        for (int i = 0; i < 4; ++i) {
            float f = frow[ty * 4 + i];
#pragma unroll
            for (int j = 0; j < 4; ++j) o[i][j] *= f;
        }
#pragma unroll 8
        for (int kk = 0; kk < 64; ++kk) {
            float4 v4 = *(const float4*)&Vs[kk * 64 + tx * 4];
#pragma unroll
            for (int i = 0; i < 4; ++i) {
                float p = Ps[(ty * 4 + i) * 65 + kk];
                o[i][0] += p * v4.x; o[i][1] += p * v4.y;
                o[i][2] += p * v4.z; o[i][3] += p * v4.w;
            }
        }
    }
#pragma unroll
    for (int i = 0; i < 4; ++i) {
        float inv = 1.f / lrow[ty * 4 + i];
#pragma unroll
        for (int j = 0; j < 4; ++j)
            out[(size_t)(qtok0 + ty * 4 + i) * D_DIM + h * 64 + tx * 4 + j] = o[i][j] * inv;
    }
}

// ---------------- layernorm over residual sum -------------------------------
__global__ void ln2_kernel(const float* __restrict__ a, const float* __restrict__ b,
                           const float* __restrict__ g, const float* __restrict__ be,
                           float* __restrict__ out, int D)
{
    const int row = blockIdx.x, t = threadIdx.x;
    __shared__ float red[256];
    __shared__ float s_mean, s_rstd;
    float s1 = 0.f, s2 = 0.f;
    for (int i = t; i < D; i += 256) {
        float v = a[(size_t)row * D + i] + b[(size_t)row * D + i];
        s1 += v; s2 += v * v;
    }
    red[t] = s1; __syncthreads();
    for (int o = 128; o; o >>= 1) { if (t < o) red[t] += red[t + o]; __syncthreads(); }
    if (t == 0) s_mean = red[0] / D;
    __syncthreads();
    red[t] = s2; __syncthreads();
    for (int o = 128; o; o >>= 1) { if (t < o) red[t] += red[t + o]; __syncthreads(); }
    if (t == 0) {
        float var = red[0] / D - s_mean * s_mean;
        s_rstd = rsqrtf(var + 1e-5f);
    }
    __syncthreads();
    for (int i = t; i < D; i += 256) {
        float v = a[(size_t)row * D + i] + b[(size_t)row * D + i];
        out[(size_t)row * D + i] = (v - s_mean) * s_rstd * g[i] + be[i];
    }
}

// ---------------- MoE routing ------------------------------------------------
__global__ void reset_kernel() { if (threadIdx.x < N_EXP) g_counts[threadIdx.x] = 0; }

__global__ void moe_gate_kernel(const float* __restrict__ x, const float* __restrict__ W,
                                const float* __restrict__ bias)
{
    const int n = blockIdx.x, t = threadIdx.x;
    const int e = t >> 5, lane = t & 31;
    float acc = 0.f;
    for (int d = lane; d < D_DIM; d += 32) acc += x[(size_t)n * D_DIM + d] * W[d * N_EXP + e];
    for (int o = 16; o; o >>= 1) acc += __shfl_down_sync(0xffffffffu, acc, o);
    __shared__ float lg[N_EXP];
    if (lane == 0) lg[e] = acc + bias[e];
    __syncthreads();
    if (t == 0) {
        int i1 = 0; float v1 = lg[0];
        for (int i = 1; i < N_EXP; ++i) if (lg[i] > v1) { v1 = lg[i]; i1 = i; }
        int i2 = -1; float v2 = -1e30f;
        for (int i = 0; i < N_EXP; ++i) {
            if (i == i1) continue;
            if (lg[i] > v2) { v2 = lg[i]; i2 = i; }
        }
        int c = (i1 > i2) ? i1 : i2;          // torch loop: max-index expert wins
        g_chosen[n] = c;
        atomicAdd(&g_counts[c], 1);
    }
}

__global__ void scan_kernel()
{
    if (threadIdx.x == 0) {
        int s = 0;
        for (int e = 0; e < N_EXP; ++e) { g_offsets[e] = s; g_cursor[e] = s; s += g_counts[e]; }
    }
}

__global__ void scatter_kernel()
{
    int n = blockIdx.x * 256 + threadIdx.x;
    if (n < N_TOK) {
        int c = g_chosen[n];
        int p = atomicAdd(&g_cursor[c], 1);
        g_p2t[p] = n;
        g_p2e[p] = c;
    }
}

// ======== expert GEMM 1: hh[p, F] = x[tok] @ w1[e] + b1[e] (128x128) ========
__global__ __launch_bounds__(256, 2)
void expert1_kernel(const float* __restrict__ x, const float* __restrict__ w1,
                    const float* __restrict__ b1, float* __restrict__ hh)
{
    const int e = blockIdx.z;
    const int cnt = g_counts[e];
    const int rt = blockIdx.y * 128;
    if (rt >= cnt) return;
    const int off = g_offsets[e];
    __shared__ int rowtok[128];
    __shared__ float As[2][16][132];
    __shared__ float Bs[2][16][128];
    const int t = threadIdx.x;
    const int tx = t & 15, ty = t >> 4;
    const int col0 = blockIdx.x * 128;
    const int ar = t >> 2, ak = (t & 3) * 4;
    const int bk = t >> 5, bc = (t & 31) * 4;
    if (t < 128) rowtok[t] = (rt + t < cnt) ? g_p2t[off + rt + t] : 0;  // 0 = dummy valid row
    __syncthreads();
    const int tok0 = rowtok[ar], tok1 = rowtok[ar + 64];
    const float* Ap0 = x + (size_t)tok0 * D_DIM + ak;
    const float* Ap1 = x + (size_t)tok1 * D_DIM + ak;
    const float* B = w1 + (size_t)e * D_DIM * F_DIM;
    const float* Bp0 = B + (size_t)bk * F_DIM + col0 + bc;
    const float* Bp1 = Bp0 + (size_t)8 * F_DIM;
    {
        float4 a0 = *(const float4*)Ap0;
        float4 a1 = *(const float4*)Ap1;
        As[0][ak + 0][ar] = a0.x; As[0][ak + 1][ar] = a0.y; As[0][ak + 2][ar] = a0.z; As[0][ak + 3][ar] = a0.w;
        As[0][ak + 0][ar + 64] = a1.x; As[0][ak + 1][ar + 64] = a1.y; As[0][ak + 2][ar + 64] = a1.z; As[0][ak + 3][ar + 64] = a1.w;
        *(float4*)&Bs[0][bk][bc] = *(const float4*)Bp0;
        *(float4*)&Bs[0][bk + 8][bc] = *(const float4*)Bp1;
    }
    __syncthreads();
    float acc[8][8] = {};
    int buf = 0;
    for (int k0 = 16; k0 <= D_DIM; k0 += 16) {
        const bool nx = (k0 < D_DIM);
        float4 na0, na1, nb0, nb1;
        if (nx) {
            na0 = *(const float4*)(Ap0 + k0);
            na1 = *(const float4*)(Ap1 + k0);
            nb0 = *(const float4*)(Bp0 + (size_t)k0 * F_DIM);
            nb1 = *(const float4*)(Bp1 + (size_t)k0 * F_DIM);
        }
#pragma unroll
        for (int kk = 0; kk < 16; ++kk) {
            float a[8], b[8];
            *(float4*)&a[0] = *(const float4*)&As[buf][kk][ty * 8];
            *(float4*)&a[4] = *(const float4*)&As[buf][kk][ty * 8 + 4];
            *(float4*)&b[0] = *(const float4*)&Bs[buf][kk][tx * 8];
            *(float4*)&b[4] = *(const float4*)&Bs[buf][kk][tx * 8 + 4];
#pragma unroll
            for (int i = 0; i < 8; ++i)
#pragma unroll
                for (int j = 0; j < 8; ++j) acc[i][j] += a[i] * b[j];
        }
        if (nx) {
            int nb2 = buf ^ 1;
            As[nb2][ak + 0][ar] = na0.x; As[nb2][ak + 1][ar] = na0.y; As[nb2][ak + 2][ar] = na0.z; As[nb2][ak + 3][ar] = na0.w;
            As[nb2][ak + 0][ar + 64] = na1.x; As[nb2][ak + 1][ar + 64] = na1.y; As[nb2][ak + 2][ar + 64] = na1.z; As[nb2][ak + 3][ar + 64] = na1.w;
            *(float4*)&Bs[nb2][bk][bc] = nb0;
            *(float4*)&Bs[nb2][bk + 8][bc] = nb1;
            __syncthreads();
            buf = nb2;
        }
    }
#pragma unroll
    for (int i = 0; i < 8; ++i) {
        const int lr = rt + ty * 8 + i;
        if (lr >= cnt) continue;
        const size_t base = (size_t)(off + lr) * F_DIM + col0 + tx * 8;
        float v[8];
#pragma unroll
        for (int j = 0; j < 8; ++j) v[j] = acc[i][j] + b1[(size_t)e * F_DIM + col0 + tx * 8 + j];
        *(float4*)&hh[base]     = make_float4(v[0], v[1], v[2], v[3]);
        *(float4*)&hh[base + 4] = make_float4(v[4], v[5], v[6], v[7]);
    }
}

// ---------------- per-expert LN + exact GELU over hh rows -------------------
__global__ void ln_gelu_kernel(float* __restrict__ hh, const float* __restrict__ ln_g,
                               const float* __restrict__ ln_b)
{
    const int p = blockIdx.x, t = threadIdx.x;
    const int e = g_p2e[p];
    float* row = hh + (size_t)p * F_DIM;
    const float* gg = ln_g + (size_t)e * F_DIM;
    const float* bb = ln_b + (size_t)e * F_DIM;
    __shared__ float red[256];
    __shared__ float s_mean, s_rstd;
    float s1 = 0.f, s2 = 0.f;
    for (int i = t; i < F_DIM; i += 256) { float v = row[i]; s1 += v; s2 += v * v; }
    red[t] = s1; __syncthreads();
    for (int o = 128; o; o >>= 1) { if (t < o) red[t] += red[t + o]; __syncthreads(); }
    if (t == 0) s_mean = red[0] / F_DIM;
    __syncthreads();
    red[t] = s2; __syncthreads();
    for (int o = 128; o; o >>= 1) { if (t < o) red[t] += red[t + o]; __syncthreads(); }
    if (t == 0) {
        float var = red[0] / F_DIM - s_mean * s_mean;
        s_rstd = rsqrtf(var + 1e-5f);
    }
    __syncthreads();
    for (int i = t; i < F_DIM; i += 256) {
        float tv = (row[i] - s_mean) * s_rstd * gg[i] + bb[i];
        row[i] = 0.5f * tv * (1.f + erff(tv * 0.70710678118654752f));
    }
}

// ===== expert GEMM 2: moe[tok] = (hh @ w2[e] + b2)*rsc + x[tok] (128x128) ===
__global__ __launch_bounds__(256, 2)
void expert2_kernel(const float* __restrict__ hh, const float* __restrict__ w2,
                    const float* __restrict__ b2, const float* __restrict__ res_scale,
                    const float* __restrict__ x, float* __restrict__ moe)
{
    const int e = blockIdx.z;
    const int cnt = g_counts[e];
    const int rt = blockIdx.y * 128;
    if (rt >= cnt) return;
    const int off = g_offsets[e];
    __shared__ int rowtok[128];
    __shared__ float As[2][16][132];
    __shared__ float Bs[2][16][128];
    const int t = threadIdx.x;
    const int tx = t & 15, ty = t >> 4;
    const int col0 = blockIdx.x * 128;
    const int ar = t >> 2, ak = (t & 3) * 4;
    const int bk = t >> 5, bc = (t & 31) * 4;
    if (t < 128) rowtok[t] = (rt + t < cnt) ? g_p2t[off + rt + t] : 0;
    __syncthreads();
    const int pr0 = off + ((rt + ar      < cnt) ? rt + ar      : 0);
    const int pr1 = off + ((rt + ar + 64 < cnt) ? rt + ar + 64 : 0);
    const float* Ap0 = hh + (size_t)pr0 * F_DIM + ak;
    const float* Ap1 = hh + (size_t)pr1 * F_DIM + ak;
    const float* B = w2 + (size_t)e * F_DIM * D_DIM;
    const float* Bp0 = B + (size_t)bk * D_DIM + col0 + bc;
    const float* Bp1 = Bp0 + (size_t)8 * D_DIM;
    const float rsc = res_scale[e];
    {
        float4 a0 = *(const float4*)Ap0;
        float4 a1 = *(const float4*)Ap1;
        As[0][ak + 0][ar] = a0.x; As[0][ak + 1][ar] = a0.y; As[0][ak + 2][ar] = a0.z; As[0][ak + 3][ar] = a0.w;
        As[0][ak + 0][ar + 64] = a1.x; As[0][ak + 1][ar + 64] = a1.y; As[0][ak + 2][ar + 64] = a1.z; As[0][ak + 3][ar + 64] = a1.w;
        *(float4*)&Bs[0][bk][bc] = *(const float4*)Bp0;
        *(float4*)&Bs[0][bk + 8][bc] = *(const float4*)Bp1;
    }
    __syncthreads();
    float acc[8][8] = {};
    int buf = 0;
    for (int k0 = 16; k0 <= F_DIM; k0 += 16) {
        const bool nx = (k0 < F_DIM);
        float4 na0, na1, nb0, nb1;
        if (nx) {
            na0 = *(const float4*)(Ap0 + k0);
            na1 = *(const float4*)(Ap1 + k0);
            nb0 = *(const float4*)(Bp0 + (size_t)k0 * D_DIM);
            nb1 = *(const float4*)(Bp1 + (size_t)k0 * D_DIM);
        }
#pragma unroll
        for (int kk = 0; kk < 16; ++kk) {
            float a[8], b[8];
            *(float4*)&a[0] = *(const float4*)&As[buf][kk][ty * 8];
            *(float4*)&a[4] = *(const float4*)&As[buf][kk][ty * 8 + 4];
            *(float4*)&b[0] = *(const float4*)&Bs[buf][kk][tx * 8];
            *(float4*)&b[4] = *(const float4*)&Bs[buf][kk][tx * 8 + 4];
#pragma unroll
            for (int i = 0; i < 8; ++i)
#pragma unroll
                for (int j = 0; j < 8; ++j) acc[i][j] += a[i] * b[j];
        }
        if (nx) {
            int nb2 = buf ^ 1;
            As[nb2][ak + 0][ar] = na0.x; As[nb2][ak + 1][ar] = na0.y; As[nb2][ak + 2][ar] = na0.z; As[nb2][ak + 3][ar] = na0.w;
            As[nb2][ak + 0][ar + 64] = na1.x; As[nb2][ak + 1][ar + 64] = na1.y; As[nb2][ak + 2][ar + 64] = na1.z; As[nb2][ak + 3][ar + 64] = na1.w;
            *(float4*)&Bs[nb2][bk][bc] = nb0;
            *(float4*)&Bs[nb2][bk + 8][bc] = nb1;
            __syncthreads();
            buf = nb2;
        }
    }
#pragma unroll
    for (int i = 0; i < 8; ++i) {
        const int lr = rt + ty * 8 + i;
        if (lr >= cnt) continue;
        const int tok = rowtok[ty * 8 + i];
        const size_t base = (size_t)tok * D_DIM + col0 + tx * 8;
        float v[8];
#pragma unroll
        for (int j = 0; j < 8; ++j)
            v[j] = (acc[i][j] + b2[(size_t)e * D_DIM + col0 + tx * 8 + j]) * rsc + x[base + j];
        *(float4*)&moe[base]     = make_float4(v[0], v[1], v[2], v[3]);
        *(float4*)&moe[base + 4] = make_float4(v[4], v[5], v[6], v[7]);
    }
}

// ---------------- host launcher ---------------------------------------------
extern "C" void kernel_launch(void* const* d_in, const int* in_sizes, int n_in,
                              void* d_out, int out_size)
{
    (void)in_sizes; (void)n_in; (void)out_size;
    const float* src        = (const float*)d_in[0];
    const float* q_w        = (const float*)d_in[1];
    const float* k_w        = (const float*)d_in[2];
    const float* v_w        = (const float*)d_in[3];
    const float* out_w      = (const float*)d_in[4];
    const float* gate_w     = (const float*)d_in[5];
    const float* gate_b     = (const float*)d_in[6];
    const float* scale_w    = (const float*)d_in[7];
    const float* n1_g       = (const float*)d_in[8];
    const float* n1_b       = (const float*)d_in[9];
    const float* n2_g       = (const float*)d_in[10];
    const float* n2_b       = (const float*)d_in[11];
    const float* moe_gate_w = (const float*)d_in[12];
    const float* moe_gate_b = (const float*)d_in[13];
    const float* w1         = (const float*)d_in[14];
    const float* b1         = (const float*)d_in[15];
    const float* ln_g       = (const float*)d_in[16];
    const float* ln_b       = (const float*)d_in[17];
    const float* w2         = (const float*)d_in[18];
    const float* b2         = (const float*)d_in[19];
    const float* res_scale  = (const float*)d_in[20];

    float *qb, *kb, *vb, *attno, *gated, *attnp, *xb, *hhb, *moeb;
    cudaGetSymbolAddress((void**)&qb, g_q);
    cudaGetSymbolAddress((void**)&kb, g_k);
    cudaGetSymbolAddress((void**)&vb, g_v);
    cudaGetSymbolAddress((void**)&attno, g_attno);
    cudaGetSymbolAddress((void**)&gated, g_gated);
    cudaGetSymbolAddress((void**)&attnp, g_attnp);
    cudaGetSymbolAddress((void**)&xb, g_x);
    cudaGetSymbolAddress((void**)&hhb, g_hh);
    cudaGetSymbolAddress((void**)&moeb, g_moe);

    cudaFuncSetAttribute(attn_kernel, cudaFuncAttributeMaxDynamicSharedMemorySize, ATTN_SMEM);

    reset_kernel<<<1, 32>>>();

    // QKV projections (128x128 tiles)
    gemm128_kernel<<<dim3(8, 16), 256>>>(src, q_w, nullptr, nullptr, qb, N_TOK, D_DIM, D_DIM, 0);
    gemm128_kernel<<<dim3(8, 16), 256>>>(src, k_w, nullptr, nullptr, kb, N_TOK, D_DIM, D_DIM, 0);
    gemm128_kernel<<<dim3(8, 16), 256>>>(src, v_w, nullptr, nullptr, vb, N_TOK, D_DIM, D_DIM, 0);

    // gated / dynamically-scaled attention
    attn_kernel<<<dim3(16, 32), 256, ATTN_SMEM>>>(qb, kb, vb, scale_w, attno);

    // gate = sigmoid(out@gate_w + gate_b); gated = out * gate; attn = gated @ out_w
    gemm128_kernel<<<dim3(8, 16), 256>>>(attno, gate_w, gate_b, attno, gated, N_TOK, D_DIM, D_DIM, 1);
    gemm128_kernel<<<dim3(8, 16), 256>>>(gated, out_w, nullptr, nullptr, attnp, N_TOK, D_DIM, D_DIM, 0);

    // x = LN(src + attn)
    ln2_kernel<<<N_TOK, 256>>>(src, attnp, n1_g, n1_b, xb, D_DIM);

    // MoE routing (top-2 weights sum to 1 -> only max-index expert runs)
    moe_gate_kernel<<<N_TOK, 256>>>(xb, moe_gate_w, moe_gate_b);
    scan_kernel<<<1, 32>>>();
    scatter_kernel<<<N_TOK / 256, 256>>>();

    // expert FFN on routed tokens
    expert1_kernel<<<dim3(F_DIM / 128, N_TOK / 128, N_EXP), 256>>>(xb, w1, b1, hhb);
    ln_gelu_kernel<<<N_TOK, 256>>>(hhb, ln_g, ln_b);
    expert2_kernel<<<dim3(D_DIM / 128, N_TOK / 128, N_EXP), 256>>>(hhb, w2, b2, res_scale, xb, moeb);

    // final LN
    ln2_kernel<<<N_TOK, 256>>>(xb, moeb, n2_g, n2_b, (float*)d_out, D_DIM);
}

// round 6
// speedup vs baseline: 1.5813x; 1.5366x over previous
#include <cuda_runtime.h>
#include <cuda_bf16.h>
#include <math.h>
#include <stdint.h>

#define N_TOK 2048
#define D_DIM 1024
#define F_DIM 2048
#define N_EXP 8
#define N_HEAD 16
#define S_LEN 1024

// ---------------- fp32 scratch ----------------------------------------------
__device__ float g_q[N_TOK * D_DIM];
__device__ float g_k[N_TOK * D_DIM];
__device__ float g_v[N_TOK * D_DIM];
__device__ float g_attno[N_TOK * D_DIM];
__device__ float g_gated[N_TOK * D_DIM];
__device__ float g_attnp[N_TOK * D_DIM];
__device__ float g_x[N_TOK * D_DIM];
__device__ float g_hh[N_TOK * F_DIM];
__device__ float g_moe[N_TOK * D_DIM];
__device__ int   g_chosen[N_TOK];
__device__ int   g_counts[N_EXP];
__device__ int   g_offsets[N_EXP];
__device__ int   g_cursor[N_EXP];
__device__ int   g_p2t[N_TOK];
__device__ int   g_p2e[N_TOK];

// ---------------- bf16 split scratch (ushort) --------------------------------
__device__ unsigned short g_act_h[N_TOK * F_DIM];
__device__ unsigned short g_act_l[N_TOK * F_DIM];
__device__ unsigned short g_wt_h[5 * D_DIM * D_DIM];
__device__ unsigned short g_wt_l[5 * D_DIM * D_DIM];
__device__ unsigned short g_w1t_h[N_EXP * D_DIM * F_DIM];
__device__ unsigned short g_w1t_l[N_EXP * D_DIM * F_DIM];
__device__ unsigned short g_w2t_h[N_EXP * F_DIM * D_DIM];
__device__ unsigned short g_w2t_l[N_EXP * F_DIM * D_DIM];

// ================= portable tensor-core helpers (sm_80+) =====================
__device__ __forceinline__ uint32_t smem_u32(const void* p) {
    uint32_t a;
    asm("{ .reg .u64 t; cvta.to.shared.u64 t, %1; cvt.u32.u64 %0, t; }" : "=r"(a) : "l"(p));
    return a;
}
#define CP_ASYNC16(dst, src) \
    asm volatile("cp.async.cg.shared.global [%0], [%1], 16;" :: "r"(dst), "l"(src))
#define CP_COMMIT() asm volatile("cp.async.commit_group;" ::: "memory")
#define CP_WAIT0()  asm volatile("cp.async.wait_group 0;" ::: "memory")

__device__ __forceinline__ void ldsm4(uint32_t* r, uint32_t addr) {
    asm volatile("ldmatrix.sync.aligned.m8n8.x4.shared.b16 {%0,%1,%2,%3}, [%4];"
        : "=r"(r[0]), "=r"(r[1]), "=r"(r[2]), "=r"(r[3]) : "r"(addr));
}
__device__ __forceinline__ void mma16816(float* c, const uint32_t* a, uint32_t b0, uint32_t b1) {
    asm volatile("mma.sync.aligned.m16n8k16.row.col.f32.bf16.bf16.f32 "
        "{%0,%1,%2,%3}, {%4,%5,%6,%7}, {%8,%9}, {%0,%1,%2,%3};"
        : "+f"(c[0]), "+f"(c[1]), "+f"(c[2]), "+f"(c[3])
        : "r"(a[0]), "r"(a[1]), "r"(a[2]), "r"(a[3]), "r"(b0), "r"(b1));
}

// smem stage layout (bf16, pitch 40 shorts = 80B; 128 rows x 32 k per matrix)
#define PITCHB 80
#define AH_OFF 0
#define AL_OFF 10240
#define BH_OFF 20480
#define BL_OFF 30720
#define STAGE_BYTES 40960
#define MMA_SMEM (2 * STAGE_BYTES)    // 81920

// ====== core: 128x128 tile, 8 warps (2Mx4N), warp tile 64x32, K stage 32 =====
// Ah/Al: [*,K] rows via arow(r). Bh/Bl: [N,K], rows col0+r.
// epi(m, c, v0, v1): local row m (0..127), local col c (even), two outputs.
template <class AROW, class EPI>
__device__ __forceinline__ void mma_body(const unsigned short* __restrict__ Ah,
                                         const unsigned short* __restrict__ Al,
                                         const unsigned short* __restrict__ Bh,
                                         const unsigned short* __restrict__ Bl,
                                         int K, int col0, AROW arow, EPI epi)
{
    extern __shared__ char smem[];
    const uint32_t sb = smem_u32(smem);
    const int t = threadIdx.x;
    const int lane = t & 31, warp = t >> 5;
    const int warpM = warp >> 2, warpN = warp & 3;

    // ---- loader geometry: row = t>>1, two 16B segs per matrix ----
    const int lrow = t >> 1;
    const int seg0 = (t & 1) * 2;                  // segs {0,1} or {2,3}
    const int aRow = arow(lrow);
    const int bRow = col0 + lrow;
    const unsigned short* srcAh = Ah + (size_t)aRow * K + seg0 * 8;
    const unsigned short* srcAl = Al + (size_t)aRow * K + seg0 * 8;
    const unsigned short* srcBh = Bh + (size_t)bRow * K + seg0 * 8;
    const unsigned short* srcBl = Bl + (size_t)bRow * K + seg0 * 8;
    const uint32_t dstRow = lrow * PITCHB + seg0 * 16;

    auto issue_stage = [&](int k0, int buf) {
        const uint32_t s = sb + buf * STAGE_BYTES + dstRow;
        CP_ASYNC16(s + AH_OFF,      srcAh + k0);
        CP_ASYNC16(s + AH_OFF + 16, srcAh + k0 + 8);
        CP_ASYNC16(s + AL_OFF,      srcAl + k0);
        CP_ASYNC16(s + AL_OFF + 16, srcAl + k0 + 8);
        CP_ASYNC16(s + BH_OFF,      srcBh + k0);
        CP_ASYNC16(s + BH_OFF + 16, srcBh + k0 + 8);
        CP_ASYNC16(s + BL_OFF,      srcBl + k0);
        CP_ASYNC16(s + BL_OFF + 16, srcBl + k0 + 8);
        CP_COMMIT();
    };

    // ---- fragment geometry ----
    const int mrow_l = (lane & 7) + ((lane >> 3) & 1) * 8;   // row within 16
    const int kcol_l = ((lane >> 4) & 1) * 8;                // k within 16

    float acc[4][4][4] = {};

    issue_stage(0, 0);
    const int NS = K >> 5;
    int buf = 0;
    for (int s = 0; s < NS; ++s) {
        CP_WAIT0();
        __syncthreads();
        if (s + 1 < NS) issue_stage((s + 1) * 32, buf ^ 1);

        const uint32_t sbase = sb + buf * STAGE_BYTES;
#pragma unroll
        for (int ks = 0; ks < 2; ++ks) {
            const uint32_t kb = (ks * 16 + kcol_l) * 2;
            uint32_t ah[4][4], al[4][4], bh[2][4], bl[2][4];
#pragma unroll
            for (int mi = 0; mi < 4; ++mi) {
                const uint32_t ro = (uint32_t)(warpM * 64 + mi * 16 + mrow_l) * PITCHB + kb;
                ldsm4(ah[mi], sbase + AH_OFF + ro);
                ldsm4(al[mi], sbase + AL_OFF + ro);
            }
#pragma unroll
            for (int p = 0; p < 2; ++p) {
                const uint32_t ro = (uint32_t)(warpN * 32 + p * 16 + mrow_l) * PITCHB + kb;
                ldsm4(bh[p], sbase + BH_OFF + ro);
                ldsm4(bl[p], sbase + BL_OFF + ro);
            }
#pragma unroll
            for (int mi = 0; mi < 4; ++mi)
#pragma unroll
                for (int nj = 0; nj < 4; ++nj) {
                    const int pr = nj >> 1, hi = nj & 1;
                    mma16816(acc[mi][nj], ah[mi], bh[pr][hi], bh[pr][hi + 2]);
                    mma16816(acc[mi][nj], ah[mi], bl[pr][hi], bl[pr][hi + 2]);
                    mma16816(acc[mi][nj], al[mi], bh[pr][hi], bh[pr][hi + 2]);
                }
        }
        __syncthreads();
        buf ^= 1;
    }

    // ---- epilogue ----
#pragma unroll
    for (int mi = 0; mi < 4; ++mi)
#pragma unroll
        for (int nj = 0; nj < 4; ++nj) {
            const int r0 = warpM * 64 + mi * 16 + (lane >> 2);
            const int c  = warpN * 32 + nj * 8 + (lane & 3) * 2;
            epi(r0,     c, acc[mi][nj][0], acc[mi][nj][1]);
            epi(r0 + 8, c, acc[mi][nj][2], acc[mi][nj][3]);
        }
}

// ---------------- dense GEMM (batched up to 3 via z) -------------------------
struct DenseArgs {
    const unsigned short* Bh[3];
    const unsigned short* Bl[3];
    const float* bias[3];
    const float* aux[3];
    float* C[3];
    int mode[3];
};
__global__ __launch_bounds__(256)
void gemm_mma_dense(const unsigned short* __restrict__ Ah, const unsigned short* __restrict__ Al,
                    DenseArgs da, int N, int K)
{
    const int z = blockIdx.z;
    const int row0 = blockIdx.y * 128, col0 = blockIdx.x * 128;
    const unsigned short* Bh = da.Bh[z];
    const unsigned short* Bl = da.Bl[z];
    const float* bias = da.bias[z];
    const float* aux = da.aux[z];
    float* C = da.C[z];
    const int mode = da.mode[z];
    auto arow = [&](int r) { return row0 + r; };
    auto epi = [&](int m, int c, float v0, float v1) {
        const int gc = col0 + c;
        if (bias) { v0 += bias[gc]; v1 += bias[gc + 1]; }
        const size_t base = (size_t)(row0 + m) * N + gc;
        if (mode == 1) {
            float2 a = *(const float2*)&aux[base];
            v0 = a.x / (1.f + __expf(-v0));
            v1 = a.y / (1.f + __expf(-v1));
        }
        *(float2*)&C[base] = make_float2(v0, v1);
    };
    mma_body(Ah, Al, Bh, Bl, K, col0, arow, epi);
}

// ---------------- expert GEMM 1 ----------------------------------------------
__global__ __launch_bounds__(256)
void gemm_mma_e1(const unsigned short* __restrict__ xh, const unsigned short* __restrict__ xl,
                 const unsigned short* __restrict__ w1h, const unsigned short* __restrict__ w1l,
                 const float* __restrict__ b1, float* __restrict__ hh)
{
    const int e = blockIdx.z;
    const int cnt = g_counts[e];
    const int rt = blockIdx.y * 128;
    if (rt >= cnt) return;
    const int off = g_offsets[e];
    const int col0 = blockIdx.x * 128;
    const unsigned short* Bh = w1h + (size_t)e * D_DIM * F_DIM;
    const unsigned short* Bl = w1l + (size_t)e * D_DIM * F_DIM;
    const float* b1e = b1 + (size_t)e * F_DIM;
    auto arow = [&](int r) {
        int rr = rt + r; if (rr >= cnt) rr = cnt - 1;
        return g_p2t[off + rr];
    };
    auto epi = [&](int m, int c, float v0, float v1) {
        if (rt + m >= cnt) return;
        const int gc = col0 + c;
        const size_t base = (size_t)(off + rt + m) * F_DIM + gc;
        *(float2*)&hh[base] = make_float2(v0 + b1e[gc], v1 + b1e[gc + 1]);
    };
    mma_body(xh, xl, Bh, Bl, D_DIM, col0, arow, epi);
}

// ---------------- expert GEMM 2 + residual scatter ---------------------------
__global__ __launch_bounds__(256)
void gemm_mma_e2(const unsigned short* __restrict__ hhh, const unsigned short* __restrict__ hhl,
                 const unsigned short* __restrict__ w2h, const unsigned short* __restrict__ w2l,
                 const float* __restrict__ b2, const float* __restrict__ res_scale,
                 const float* __restrict__ x, float* __restrict__ moe)
{
    const int e = blockIdx.z;
    const int cnt = g_counts[e];
    const int rt = blockIdx.y * 128;
    if (rt >= cnt) return;
    const int off = g_offsets[e];
    const int col0 = blockIdx.x * 128;
    const unsigned short* Bh = w2h + (size_t)e * F_DIM * D_DIM;
    const unsigned short* Bl = w2l + (size_t)e * F_DIM * D_DIM;
    const float* b2e = b2 + (size_t)e * D_DIM;
    const float rsc = res_scale[e];
    auto arow = [&](int r) {
        int rr = rt + r; if (rr >= cnt) rr = cnt - 1;
        return off + rr;
    };
    auto epi = [&](int m, int c, float v0, float v1) {
        if (rt + m >= cnt) return;
        const int tok = g_p2t[off + rt + m];
        const int gc = col0 + c;
        const size_t base = (size_t)tok * D_DIM + gc;
        float2 xr = *(const float2*)&x[base];
        *(float2*)&moe[base] = make_float2((v0 + b2e[gc]) * rsc + xr.x,
                                           (v1 + b2e[gc + 1]) * rsc + xr.y);
    };
    mma_body(hhh, hhl, Bh, Bl, F_DIM, col0, arow, epi);
}

// ---------------- conversion kernels -----------------------------------------
__device__ __forceinline__ void split1(float v, unsigned short& h, unsigned short& l) {
    __nv_bfloat16 hb = __float2bfloat16(v);
    float r = v - __bfloat162float(hb);
    __nv_bfloat16 lb = __float2bfloat16(r);
    h = *(unsigned short*)&hb;
    l = *(unsigned short*)&lb;
}

__global__ void twT_kernel(const float* __restrict__ W, unsigned short* __restrict__ oh,
                           unsigned short* __restrict__ ol, int K, int N)
{
    __shared__ float tl[32][33];
    const size_t zoff = (size_t)blockIdx.z * K * N;
    const float* Wz = W + zoff;
    unsigned short* ohz = oh + zoff;
    unsigned short* olz = ol + zoff;
    const int n0 = blockIdx.x * 32, k0 = blockIdx.y * 32;
    const int x = threadIdx.x, y = threadIdx.y;
#pragma unroll
    for (int i = 0; i < 4; ++i)
        tl[y + 8 * i][x] = Wz[(size_t)(k0 + y + 8 * i) * N + n0 + x];
    __syncthreads();
#pragma unroll
    for (int i = 0; i < 4; ++i) {
        float v = tl[x][y + 8 * i];
        unsigned short h, l;
        split1(v, h, l);
        const size_t o = (size_t)(n0 + y + 8 * i) * K + k0 + x;
        ohz[o] = h;
        olz[o] = l;
    }
}

__global__ void cvt_kernel(const float* __restrict__ x, unsigned short* __restrict__ h,
                           unsigned short* __restrict__ l, int n4)
{
    const int i = blockIdx.x * 256 + threadIdx.x;
    if (i >= n4) return;
    float4 v = ((const float4*)x)[i];
    ushort4 hv, lv;
    split1(v.x, hv.x, lv.x);
    split1(v.y, hv.y, lv.y);
    split1(v.z, hv.z, lv.z);
    split1(v.w, hv.w, lv.w);
    ((ushort4*)h)[i] = hv;
    ((ushort4*)l)[i] = lv;
}

// ---------------- flash-style attention (fp32) -------------------------------
#define ATTN_SMEM ((68*64*2 + 64*64 + 65*64 + 5*64 + 64*4) * 4)
__global__ void attn_kernel(const float* __restrict__ q, const float* __restrict__ k,
                            const float* __restrict__ v, const float* __restrict__ scale_w,
                            float* __restrict__ out)
{
    extern __shared__ float sm[];
    float* QsT = sm;
    float* KsT = QsT + 68 * 64;
    float* Vs  = KsT + 68 * 64;
    float* Ps  = Vs + 64 * 64;
    float* mrow = Ps + 65 * 64;
    float* lrow = mrow + 64;
    float* frow = lrow + 64;
    float* qsc  = frow + 64;
    float* sw   = qsc + 64;
    float* red4 = sw + 64;

    const int t = threadIdx.x;
    const int tx = t & 15, ty = t >> 4;
    const int bh = blockIdx.y;
    const int h = bh & 15, b = bh >> 4;
    const int q0 = blockIdx.x * 64;
    const int qtok0 = b * S_LEN + q0;

    if (t < 64) sw[t] = scale_w[h * 64 + t];
#pragma unroll
    for (int it = 0; it < 16; ++it) {
        int idx = t + it * 256;
        int r = idx >> 6, d = idx & 63;
        QsT[d * 68 + r] = q[(size_t)(qtok0 + r) * D_DIM + h * 64 + d];
    }
    __syncthreads();
    if (t < 64) {
        float s = 0.f;
        for (int d = 0; d < 64; ++d) s += QsT[d * 68 + t] * sw[d];
        qsc[t] = 2.f / (1.f + expf(-s));
        mrow[t] = -1e30f;
        lrow[t] = 0.f;
    }
    float o[4][4] = {};
    for (int kt = 0; kt < 16; ++kt) {
        __syncthreads();
        const int ktok0 = b * S_LEN + kt * 64;
#pragma unroll
        for (int it = 0; it < 16; ++it) {
            int idx = t + it * 256;
            int r = idx >> 6, d = idx & 63;
            KsT[d * 68 + r] = k[(size_t)(ktok0 + r) * D_DIM + h * 64 + d];
            Vs[r * 64 + d]  = v[(size_t)(ktok0 + r) * D_DIM + h * 64 + d];
        }
        __syncthreads();
        float s[4][4] = {};
#pragma unroll 8
        for (int kk = 0; kk < 64; ++kk) {
            float4 a4 = *(const float4*)&QsT[kk * 68 + ty * 4];
            float4 b4 = *(const float4*)&KsT[kk * 68 + tx * 4];
            float a[4] = {a4.x, a4.y, a4.z, a4.w};
            float bb[4] = {b4.x, b4.y, b4.z, b4.w};
#pragma unroll
            for (int i = 0; i < 4; ++i)
#pragma unroll
                for (int j = 0; j < 4; ++j) s[i][j] += a[i] * bb[j];
        }
#pragma unroll
        for (int i = 0; i < 4; ++i) {
            float sc = qsc[ty * 4 + i] * 0.125f;
#pragma unroll
            for (int j = 0; j < 4; ++j)
                Ps[(ty * 4 + i) * 65 + tx * 4 + j] = s[i][j] * sc;
        }
        __syncthreads();
        {
            const int r = t >> 2, part = t & 3;
            float* prow = &Ps[r * 65 + part * 16];
            float pm = -1e30f;
#pragma unroll
            for (int i = 0; i < 16; ++i) pm = fmaxf(pm, prow[i]);
            red4[r * 4 + part] = pm;
            __syncthreads();
            float nm = fmaxf(fmaxf(red4[r * 4 + 0], red4[r * 4 + 1]),
                             fmaxf(red4[r * 4 + 2], red4[r * 4 + 3]));
            nm = fmaxf(nm, mrow[r]);
            float sum = 0.f;
#pragma unroll
            for (int i = 0; i < 16; ++i) {
                float p = __expf(prow[i] - nm);
                prow[i] = p;
                sum += p;
            }
            __syncthreads();
            red4[r * 4 + part] = sum;
            __syncthreads();
            if (part == 0) {
                float s4 = red4[r * 4] + red4[r * 4 + 1] + red4[r * 4 + 2] + red4[r * 4 + 3];
                float f = __expf(mrow[r] - nm);
                lrow[r] = lrow[r] * f + s4;
                mrow[r] = nm;
                frow[r] = f;
            }
        }
        __syncthreads();
#pragma unroll
        for (int i = 0; i < 4; ++i) {
            float f = frow[ty * 4 + i];
#pragma unroll
            for (int j = 0; j < 4; ++j) o[i][j] *= f;
        }
#pragma unroll 8
        for (int kk = 0; kk < 64; ++kk) {
            float4 v4 = *(const float4*)&Vs[kk * 64 + tx * 4];
#pragma unroll
            for (int i = 0; i < 4; ++i) {
                float p = Ps[(ty * 4 + i) * 65 + kk];
                o[i][0] += p * v4.x; o[i][1] += p * v4.y;
                o[i][2] += p * v4.z; o[i][3] += p * v4.w;
            }
        }
    }
#pragma unroll
    for (int i = 0; i < 4; ++i) {
        float inv = 1.f / lrow[ty * 4 + i];
#pragma unroll
        for (int j = 0; j < 4; ++j)
            out[(size_t)(qtok0 + ty * 4 + i) * D_DIM + h * 64 + tx * 4 + j] = o[i][j] * inv;
    }
}

// ---------------- layernorm over residual sum -------------------------------
__global__ void ln2_kernel(const float* __restrict__ a, const float* __restrict__ b,
                           const float* __restrict__ g, const float* __restrict__ be,
                           float* __restrict__ out, int D)
{
    const int row = blockIdx.x, t = threadIdx.x;
    __shared__ float red[256];
    __shared__ float s_mean, s_rstd;
    float s1 = 0.f, s2 = 0.f;
    for (int i = t; i < D; i += 256) {
        float v = a[(size_t)row * D + i] + b[(size_t)row * D + i];
        s1 += v; s2 += v * v;
    }
    red[t] = s1; __syncthreads();
    for (int o = 128; o; o >>= 1) { if (t < o) red[t] += red[t + o]; __syncthreads(); }
    if (t == 0) s_mean = red[0] / D;
    __syncthreads();
    red[t] = s2; __syncthreads();
    for (int o = 128; o; o >>= 1) { if (t < o) red[t] += red[t + o]; __syncthreads(); }
    if (t == 0) {
        float var = red[0] / D - s_mean * s_mean;
        s_rstd = rsqrtf(var + 1e-5f);
    }
    __syncthreads();
    for (int i = t; i < D; i += 256) {
        float v = a[(size_t)row * D + i] + b[(size_t)row * D + i];
        out[(size_t)row * D + i] = (v - s_mean) * s_rstd * g[i] + be[i];
    }
}

// ---------------- MoE routing ------------------------------------------------
__global__ void reset_kernel() { if (threadIdx.x < N_EXP) g_counts[threadIdx.x] = 0; }

__global__ void moe_gate_kernel(const float* __restrict__ x, const float* __restrict__ W,
                                const float* __restrict__ bias)
{
    const int n = blockIdx.x, t = threadIdx.x;
    const int e = t >> 5, lane = t & 31;
    float acc = 0.f;
    for (int d = lane; d < D_DIM; d += 32) acc += x[(size_t)n * D_DIM + d] * W[d * N_EXP + e];
    for (int o = 16; o; o >>= 1) acc += __shfl_down_sync(0xffffffffu, acc, o);
    __shared__ float lg[N_EXP];
    if (lane == 0) lg[e] = acc + bias[e];
    __syncthreads();
    if (t == 0) {
        int i1 = 0; float v1 = lg[0];
        for (int i = 1; i < N_EXP; ++i) if (lg[i] > v1) { v1 = lg[i]; i1 = i; }
        int i2 = -1; float v2 = -1e30f;
        for (int i = 0; i < N_EXP; ++i) {
            if (i == i1) continue;
            if (lg[i] > v2) { v2 = lg[i]; i2 = i; }
        }
        int c = (i1 > i2) ? i1 : i2;
        g_chosen[n] = c;
        atomicAdd(&g_counts[c], 1);
    }
}

__global__ void scan_kernel()
{
    if (threadIdx.x == 0) {
        int s = 0;
        for (int e = 0; e < N_EXP; ++e) { g_offsets[e] = s; g_cursor[e] = s; s += g_counts[e]; }
    }
}

__global__ void scatter_kernel()
{
    int n = blockIdx.x * 256 + threadIdx.x;
    if (n < N_TOK) {
        int c = g_chosen[n];
        int p = atomicAdd(&g_cursor[c], 1);
        g_p2t[p] = n;
        g_p2e[p] = c;
    }
}

// ---------------- per-expert LN + exact GELU ---------------------------------
__global__ void ln_gelu_kernel(float* __restrict__ hh, const float* __restrict__ ln_g,
                               const float* __restrict__ ln_b)
{
    const int p = blockIdx.x, t = threadIdx.x;
    const int e = g_p2e[p];
    float* row = hh + (size_t)p * F_DIM;
    const float* gg = ln_g + (size_t)e * F_DIM;
    const float* bb = ln_b + (size_t)e * F_DIM;
    __shared__ float red[256];
    __shared__ float s_mean, s_rstd;
    float s1 = 0.f, s2 = 0.f;
    for (int i = t; i < F_DIM; i += 256) { float v = row[i]; s1 += v; s2 += v * v; }
    red[t] = s1; __syncthreads();
    for (int o = 128; o; o >>= 1) { if (t < o) red[t] += red[t + o]; __syncthreads(); }
    if (t == 0) s_mean = red[0] / F_DIM;
    __syncthreads();
    red[t] = s2; __syncthreads();
    for (int o = 128; o; o >>= 1) { if (t < o) red[t] += red[t + o]; __syncthreads(); }
    if (t == 0) {
        float var = red[0] / F_DIM - s_mean * s_mean;
        s_rstd = rsqrtf(var + 1e-5f);
    }
    __syncthreads();
    for (int i = t; i < F_DIM; i += 256) {
        float tv = (row[i] - s_mean) * s_rstd * gg[i] + bb[i];
        row[i] = 0.5f * tv * (1.f + erff(tv * 0.70710678118654752f));
    }
}

// ---------------- host launcher ---------------------------------------------
extern "C" void kernel_launch(void* const* d_in, const int* in_sizes, int n_in,
                              void* d_out, int out_size)
{
    (void)in_sizes; (void)n_in; (void)out_size;
    const float* src        = (const float*)d_in[0];
    const float* q_w        = (const float*)d_in[1];
    const float* k_w        = (const float*)d_in[2];
    const float* v_w        = (const float*)d_in[3];
    const float* out_w      = (const float*)d_in[4];
    const float* gate_w     = (const float*)d_in[5];
    const float* gate_b     = (const float*)d_in[6];
    const float* scale_w    = (const float*)d_in[7];
    const float* n1_g       = (const float*)d_in[8];
    const float* n1_b       = (const float*)d_in[9];
    const float* n2_g       = (const float*)d_in[10];
    const float* n2_b       = (const float*)d_in[11];
    const float* moe_gate_w = (const float*)d_in[12];
    const float* moe_gate_b = (const float*)d_in[13];
    const float* w1         = (const float*)d_in[14];
    const float* b1         = (const float*)d_in[15];
    const float* ln_g       = (const float*)d_in[16];
    const float* ln_b       = (const float*)d_in[17];
    const float* w2         = (const float*)d_in[18];
    const float* b2         = (const float*)d_in[19];
    const float* res_scale  = (const float*)d_in[20];

    float *qb, *kb, *vb, *attno, *gated, *attnp, *xb, *hhb, *moeb;
    cudaGetSymbolAddress((void**)&qb, g_q);
    cudaGetSymbolAddress((void**)&kb, g_k);
    cudaGetSymbolAddress((void**)&vb, g_v);
    cudaGetSymbolAddress((void**)&attno, g_attno);
    cudaGetSymbolAddress((void**)&gated, g_gated);
    cudaGetSymbolAddress((void**)&attnp, g_attnp);
    cudaGetSymbolAddress((void**)&xb, g_x);
    cudaGetSymbolAddress((void**)&hhb, g_hh);
    cudaGetSymbolAddress((void**)&moeb, g_moe);

    unsigned short *acth, *actl, *wth, *wtl, *w1th, *w1tl, *w2th, *w2tl;
    cudaGetSymbolAddress((void**)&acth, g_act_h);
    cudaGetSymbolAddress((void**)&actl, g_act_l);
    cudaGetSymbolAddress((void**)&wth, g_wt_h);
    cudaGetSymbolAddress((void**)&wtl, g_wt_l);
    cudaGetSymbolAddress((void**)&w1th, g_w1t_h);
    cudaGetSymbolAddress((void**)&w1tl, g_w1t_l);
    cudaGetSymbolAddress((void**)&w2th, g_w2t_h);
    cudaGetSymbolAddress((void**)&w2tl, g_w2t_l);

    cudaFuncSetAttribute(attn_kernel, cudaFuncAttributeMaxDynamicSharedMemorySize, ATTN_SMEM);
    cudaFuncSetAttribute(gemm_mma_dense, cudaFuncAttributeMaxDynamicSharedMemorySize, MMA_SMEM);
    cudaFuncSetAttribute(gemm_mma_e1, cudaFuncAttributeMaxDynamicSharedMemorySize, MMA_SMEM);
    cudaFuncSetAttribute(gemm_mma_e2, cudaFuncAttributeMaxDynamicSharedMemorySize, MMA_SMEM);

    const size_t WSZ = (size_t)D_DIM * D_DIM;

    dim3 tb(32, 8);
    twT_kernel<<<dim3(32, 32, 1), tb>>>(q_w,    wth + 0 * WSZ, wtl + 0 * WSZ, D_DIM, D_DIM);
    twT_kernel<<<dim3(32, 32, 1), tb>>>(k_w,    wth + 1 * WSZ, wtl + 1 * WSZ, D_DIM, D_DIM);
    twT_kernel<<<dim3(32, 32, 1), tb>>>(v_w,    wth + 2 * WSZ, wtl + 2 * WSZ, D_DIM, D_DIM);
    twT_kernel<<<dim3(32, 32, 1), tb>>>(out_w,  wth + 3 * WSZ, wtl + 3 * WSZ, D_DIM, D_DIM);
    twT_kernel<<<dim3(32, 32, 1), tb>>>(gate_w, wth + 4 * WSZ, wtl + 4 * WSZ, D_DIM, D_DIM);
    twT_kernel<<<dim3(F_DIM / 32, D_DIM / 32, N_EXP), tb>>>(w1, w1th, w1tl, D_DIM, F_DIM);
    twT_kernel<<<dim3(D_DIM / 32, F_DIM / 32, N_EXP), tb>>>(w2, w2th, w2tl, F_DIM, D_DIM);

    reset_kernel<<<1, 32>>>();

    // QKV (batched z=3)
    cvt_kernel<<<(N_TOK * D_DIM / 4 + 255) / 256, 256>>>(src, acth, actl, N_TOK * D_DIM / 4);
    {
        DenseArgs da = {};
        for (int z = 0; z < 3; ++z) {
            da.Bh[z] = wth + (size_t)z * WSZ;
            da.Bl[z] = wtl + (size_t)z * WSZ;
            da.bias[z] = nullptr; da.aux[z] = nullptr; da.mode[z] = 0;
        }
        da.C[0] = qb; da.C[1] = kb; da.C[2] = vb;
        gemm_mma_dense<<<dim3(8, 16, 3), 256, MMA_SMEM>>>(acth, actl, da, D_DIM, D_DIM);
    }

    attn_kernel<<<dim3(16, 32), 256, ATTN_SMEM>>>(qb, kb, vb, scale_w, attno);

    // gated = sigmoid(attno @ gate_w + gate_b) * attno
    cvt_kernel<<<(N_TOK * D_DIM / 4 + 255) / 256, 256>>>(attno, acth, actl, N_TOK * D_DIM / 4);
    {
        DenseArgs da = {};
        da.Bh[0] = wth + 4 * WSZ; da.Bl[0] = wtl + 4 * WSZ;
        da.bias[0] = gate_b; da.aux[0] = attno; da.C[0] = gated; da.mode[0] = 1;
        gemm_mma_dense<<<dim3(8, 16, 1), 256, MMA_SMEM>>>(acth, actl, da, D_DIM, D_DIM);
    }

    // attnp = gated @ out_w
    cvt_kernel<<<(N_TOK * D_DIM / 4 + 255) / 256, 256>>>(gated, acth, actl, N_TOK * D_DIM / 4);
    {
        DenseArgs da = {};
        da.Bh[0] = wth + 3 * WSZ; da.Bl[0] = wtl + 3 * WSZ;
        da.bias[0] = nullptr; da.aux[0] = nullptr; da.C[0] = attnp; da.mode[0] = 0;
        gemm_mma_dense<<<dim3(8, 16, 1), 256, MMA_SMEM>>>(acth, actl, da, D_DIM, D_DIM);
    }

    ln2_kernel<<<N_TOK, 256>>>(src, attnp, n1_g, n1_b, xb, D_DIM);

    moe_gate_kernel<<<N_TOK, 256>>>(xb, moe_gate_w, moe_gate_b);
    scan_kernel<<<1, 32>>>();
    scatter_kernel<<<N_TOK / 256, 256>>>();

    cvt_kernel<<<(N_TOK * D_DIM / 4 + 255) / 256, 256>>>(xb, acth, actl, N_TOK * D_DIM / 4);
    gemm_mma_e1<<<dim3(F_DIM / 128, N_TOK / 128, N_EXP), 256, MMA_SMEM>>>(
        acth, actl, w1th, w1tl, b1, hhb);
    ln_gelu_kernel<<<N_TOK, 256>>>(hhb, ln_g, ln_b);
    cvt_kernel<<<(N_TOK * F_DIM / 4 + 255) / 256, 256>>>(hhb, acth, actl, N_TOK * F_DIM / 4);
    gemm_mma_e2<<<dim3(D_DIM / 128, N_TOK / 128, N_EXP), 256, MMA_SMEM>>>(
        acth, actl, w2th, w2tl, b2, res_scale, xb, moeb);

    ln2_kernel<<<N_TOK, 256>>>(xb, moeb, n2_g, n2_b, (float*)d_out, D_DIM);
}

// round 7
// speedup vs baseline: 2.0312x; 1.2846x over previous
#include <cuda_runtime.h>
#include <cuda_bf16.h>
#include <math.h>
#include <stdint.h>

#define N_TOK 2048
#define D_DIM 1024
#define F_DIM 2048
#define N_EXP 8
#define N_HEAD 16
#define S_LEN 1024

// ---------------- fp32 scratch ----------------------------------------------
__device__ float g_attnp[N_TOK * D_DIM];
__device__ float g_x[N_TOK * D_DIM];
__device__ float g_hh[N_TOK * F_DIM];
__device__ float g_moe[N_TOK * D_DIM];
__device__ int   g_chosen[N_TOK];
__device__ int   g_counts[N_EXP];
__device__ int   g_offsets[N_EXP];
__device__ int   g_cursor[N_EXP];
__device__ int   g_p2t[N_TOK];
__device__ int   g_p2e[N_TOK];

// ---------------- bf16 split scratch (ushort) --------------------------------
__device__ unsigned short g_act_h[N_TOK * F_DIM];     // src -> x -> hh (disjoint lifetimes)
__device__ unsigned short g_act_l[N_TOK * F_DIM];
__device__ unsigned short g_qh[N_TOK * D_DIM];
__device__ unsigned short g_ql[N_TOK * D_DIM];
__device__ unsigned short g_kh[N_TOK * D_DIM];
__device__ unsigned short g_kl[N_TOK * D_DIM];
__device__ unsigned short g_vh[N_TOK * D_DIM];
__device__ unsigned short g_vl[N_TOK * D_DIM];
__device__ unsigned short g_ah[N_TOK * D_DIM];        // attn out splits
__device__ unsigned short g_al[N_TOK * D_DIM];
__device__ unsigned short g_gh[N_TOK * D_DIM];        // gated splits
__device__ unsigned short g_gl[N_TOK * D_DIM];
__device__ unsigned short g_wt_h[5 * D_DIM * D_DIM];  // q,k,v,out,gate weights [K,N] split
__device__ unsigned short g_wt_l[5 * D_DIM * D_DIM];
__device__ unsigned short g_w1_h[N_EXP * D_DIM * F_DIM];
__device__ unsigned short g_w1_l[N_EXP * D_DIM * F_DIM];
__device__ unsigned short g_w2_h[N_EXP * F_DIM * D_DIM];
__device__ unsigned short g_w2_l[N_EXP * F_DIM * D_DIM];

// ================= helpers ====================================================
__device__ __forceinline__ uint32_t smem_u32(const void* p) {
    uint32_t a;
    asm("{ .reg .u64 t; cvta.to.shared.u64 t, %1; cvt.u32.u64 %0, t; }" : "=r"(a) : "l"(p));
    return a;
}
#define CP_ASYNC16(dst, src) \
    asm volatile("cp.async.cg.shared.global [%0], [%1], 16;" :: "r"(dst), "l"(src))
#define CP_COMMIT() asm volatile("cp.async.commit_group;" ::: "memory")
#define CP_WAIT0()  asm volatile("cp.async.wait_group 0;" ::: "memory")
#define CP_WAIT1()  asm volatile("cp.async.wait_group 1;" ::: "memory")

__device__ __forceinline__ void ldsm4(uint32_t* r, uint32_t addr) {
    asm volatile("ldmatrix.sync.aligned.m8n8.x4.shared.b16 {%0,%1,%2,%3}, [%4];"
        : "=r"(r[0]), "=r"(r[1]), "=r"(r[2]), "=r"(r[3]) : "r"(addr));
}
__device__ __forceinline__ void ldsm4t(uint32_t* r, uint32_t addr) {
    asm volatile("ldmatrix.sync.aligned.m8n8.x4.trans.shared.b16 {%0,%1,%2,%3}, [%4];"
        : "=r"(r[0]), "=r"(r[1]), "=r"(r[2]), "=r"(r[3]) : "r"(addr));
}
__device__ __forceinline__ void mma16816(float* c, const uint32_t* a, uint32_t b0, uint32_t b1) {
    asm volatile("mma.sync.aligned.m16n8k16.row.col.f32.bf16.bf16.f32 "
        "{%0,%1,%2,%3}, {%4,%5,%6,%7}, {%8,%9}, {%0,%1,%2,%3};"
        : "+f"(c[0]), "+f"(c[1]), "+f"(c[2]), "+f"(c[3])
        : "r"(a[0]), "r"(a[1]), "r"(a[2]), "r"(a[3]), "r"(b0), "r"(b1));
}
__device__ __forceinline__ uint32_t packbf(float lo, float hi) {
    uint32_t r;
    asm("cvt.rn.bf16x2.f32 %0, %1, %2;" : "=r"(r) : "f"(hi), "f"(lo));
    return r;
}
__device__ __forceinline__ float bfu(unsigned short u) {
    return __uint_as_float(((uint32_t)u) << 16);
}
__device__ __forceinline__ void split1(float v, unsigned short& h, unsigned short& l) {
    __nv_bfloat16 hb = __float2bfloat16(v);
    float r = v - __bfloat162float(hb);
    __nv_bfloat16 lb = __float2bfloat16(r);
    h = *(unsigned short*)&hb;
    l = *(unsigned short*)&lb;
}

// ================= GEMM: 128x128 tile, split-bf16, B in natural [K,N] ========
// smem: A 128x32 pitch 40 shorts; B 32x128 pitch 136 shorts
#define A_OFF_H 0
#define A_OFF_L 10240
#define B_OFF_H 20480
#define B_OFF_L 29184
#define STAGE_BYTES 37888
#define MMA_SMEM (2 * STAGE_BYTES)

template <class AROW, class EPI>
__device__ __forceinline__ void mma_body(const unsigned short* __restrict__ Ah,
                                         const unsigned short* __restrict__ Al,
                                         const unsigned short* __restrict__ Bh,
                                         const unsigned short* __restrict__ Bl,
                                         int K, int N, int col0, AROW arow, EPI epi)
{
    extern __shared__ char smem[];
    const uint32_t sb = smem_u32(smem);
    const int t = threadIdx.x;
    const int lane = t & 31, warp = t >> 5;
    const int warpM = warp >> 2, warpN = warp & 3;

    // loaders
    const int lrow = t >> 1, aseg = (t & 1) * 2;
    const int aRow = arow(lrow);
    const unsigned short* srcAh = Ah + (size_t)aRow * K + aseg * 8;
    const unsigned short* srcAl = Al + (size_t)aRow * K + aseg * 8;
    const uint32_t adst = lrow * 80 + aseg * 16;
    const int brow = t >> 3, bcol = (t & 7) * 16;
    const unsigned short* srcBh = Bh + (size_t)brow * N + col0 + bcol;
    const unsigned short* srcBl = Bl + (size_t)brow * N + col0 + bcol;
    const uint32_t bdst = brow * 272 + bcol * 2;

    auto issue_stage = [&](int k0, int buf) {
        const uint32_t s = sb + buf * STAGE_BYTES;
        CP_ASYNC16(s + A_OFF_H + adst,      srcAh + k0);
        CP_ASYNC16(s + A_OFF_H + adst + 16, srcAh + k0 + 8);
        CP_ASYNC16(s + A_OFF_L + adst,      srcAl + k0);
        CP_ASYNC16(s + A_OFF_L + adst + 16, srcAl + k0 + 8);
        const size_t bko = (size_t)k0 * N;
        CP_ASYNC16(s + B_OFF_H + bdst,      srcBh + bko);
        CP_ASYNC16(s + B_OFF_H + bdst + 16, srcBh + bko + 8);
        CP_ASYNC16(s + B_OFF_L + bdst,      srcBl + bko);
        CP_ASYNC16(s + B_OFF_L + bdst + 16, srcBl + bko + 8);
        CP_COMMIT();
    };

    const int mrow_l = (lane & 7) + ((lane >> 3) & 1) * 8;
    const int kcol_l = ((lane >> 4) & 1) * 8;

    float acc[4][4][4] = {};

    issue_stage(0, 0);
    const int NS = K >> 5;
    int buf = 0;
    for (int s = 0; s < NS; ++s) {
        CP_WAIT0();
        __syncthreads();
        if (s + 1 < NS) issue_stage((s + 1) * 32, buf ^ 1);

        const uint32_t sbase = sb + buf * STAGE_BYTES;
#pragma unroll
        for (int ks = 0; ks < 2; ++ks) {
            const int kb = ks * 16;
            uint32_t ah[4][4], al[4][4], bh4[2][4], bl4[2][4];
#pragma unroll
            for (int mi = 0; mi < 4; ++mi) {
                const uint32_t ro = (uint32_t)(warpM * 64 + mi * 16 + mrow_l) * 80 + (kb + kcol_l) * 2;
                ldsm4(ah[mi], sbase + A_OFF_H + ro);
                ldsm4(al[mi], sbase + A_OFF_L + ro);
            }
#pragma unroll
            for (int g = 0; g < 2; ++g) {
                const uint32_t ro = (uint32_t)(kb + (lane & 7) + ((lane >> 4) & 1) * 8) * 272
                                  + (uint32_t)(warpN * 32 + g * 16 + ((lane >> 3) & 1) * 8) * 2;
                ldsm4t(bh4[g], sbase + B_OFF_H + ro);
                ldsm4t(bl4[g], sbase + B_OFF_L + ro);
            }
#pragma unroll
            for (int mi = 0; mi < 4; ++mi)
#pragma unroll
                for (int nj = 0; nj < 4; ++nj) {
                    const int g = nj >> 1, hi = nj & 1;
                    mma16816(acc[mi][nj], ah[mi], bh4[g][hi], bh4[g][hi + 2]);
                    mma16816(acc[mi][nj], ah[mi], bl4[g][hi], bl4[g][hi + 2]);
                    mma16816(acc[mi][nj], al[mi], bh4[g][hi], bh4[g][hi + 2]);
                }
        }
        __syncthreads();
        buf ^= 1;
    }

#pragma unroll
    for (int mi = 0; mi < 4; ++mi)
#pragma unroll
        for (int nj = 0; nj < 4; ++nj) {
            const int r0 = warpM * 64 + mi * 16 + (lane >> 2);
            const int c  = warpN * 32 + nj * 8 + (lane & 3) * 2;
            epi(r0,     c, acc[mi][nj][0], acc[mi][nj][1]);
            epi(r0 + 8, c, acc[mi][nj][2], acc[mi][nj][3]);
        }
}

// ---------------- dense GEMM (batched up to 3 via z) -------------------------
// mode 0: C(fp32) = acc (+bias)
// mode 1: split(sigmoid(acc+bias) * (auxh+auxl)) -> Ch, Cl
// mode 2: split(acc) -> Ch, Cl
struct DenseArgs {
    const unsigned short* Bh[3];
    const unsigned short* Bl[3];
    const float* bias[3];
    const unsigned short* auxh[3];
    const unsigned short* auxl[3];
    float* C[3];
    unsigned short* Ch[3];
    unsigned short* Cl[3];
    int mode[3];
};
__global__ __launch_bounds__(256)
void gemm_mma_dense(const unsigned short* __restrict__ Ah, const unsigned short* __restrict__ Al,
                    DenseArgs da, int N, int K)
{
    const int z = blockIdx.z;
    const int row0 = blockIdx.y * 128, col0 = blockIdx.x * 128;
    const unsigned short* Bh = da.Bh[z];
    const unsigned short* Bl = da.Bl[z];
    const float* bias = da.bias[z];
    const unsigned short* auxh = da.auxh[z];
    const unsigned short* auxl = da.auxl[z];
    float* C = da.C[z];
    unsigned short* Ch = da.Ch[z];
    unsigned short* Cl = da.Cl[z];
    const int mode = da.mode[z];
    auto arow = [&](int r) { return row0 + r; };
    auto epi = [&](int m, int c, float v0, float v1) {
        const int gc = col0 + c;
        const size_t base = (size_t)(row0 + m) * N + gc;
        if (mode == 0) {
            if (bias) { v0 += bias[gc]; v1 += bias[gc + 1]; }
            *(float2*)&C[base] = make_float2(v0, v1);
        } else if (mode == 1) {
            v0 += bias[gc]; v1 += bias[gc + 1];
            float a0 = bfu(auxh[base]) + bfu(auxl[base]);
            float a1 = bfu(auxh[base + 1]) + bfu(auxl[base + 1]);
            v0 = a0 / (1.f + __expf(-v0));
            v1 = a1 / (1.f + __expf(-v1));
            unsigned short h0, l0, h1, l1;
            split1(v0, h0, l0); split1(v1, h1, l1);
            *(ushort2*)&Ch[base] = make_ushort2(h0, h1);
            *(ushort2*)&Cl[base] = make_ushort2(l0, l1);
        } else {
            unsigned short h0, l0, h1, l1;
            split1(v0, h0, l0); split1(v1, h1, l1);
            *(ushort2*)&Ch[base] = make_ushort2(h0, h1);
            *(ushort2*)&Cl[base] = make_ushort2(l0, l1);
        }
    };
    mma_body(Ah, Al, Bh, Bl, K, N, col0, arow, epi);
}

// ---------------- expert GEMM 1: hh = x @ w1[e] + b1 -------------------------
__global__ __launch_bounds__(256)
void gemm_mma_e1(const unsigned short* __restrict__ xh, const unsigned short* __restrict__ xl,
                 const unsigned short* __restrict__ w1h, const unsigned short* __restrict__ w1l,
                 const float* __restrict__ b1, float* __restrict__ hh)
{
    const int e = blockIdx.z;
    const int cnt = g_counts[e];
    const int rt = blockIdx.y * 128;
    if (rt >= cnt) return;
    const int off = g_offsets[e];
    const int col0 = blockIdx.x * 128;
    const unsigned short* Bh = w1h + (size_t)e * D_DIM * F_DIM;
    const unsigned short* Bl = w1l + (size_t)e * D_DIM * F_DIM;
    const float* b1e = b1 + (size_t)e * F_DIM;
    auto arow = [&](int r) {
        int rr = rt + r; if (rr >= cnt) rr = cnt - 1;
        return g_p2t[off + rr];
    };
    auto epi = [&](int m, int c, float v0, float v1) {
        if (rt + m >= cnt) return;
        const int gc = col0 + c;
        const size_t base = (size_t)(off + rt + m) * F_DIM + gc;
        *(float2*)&hh[base] = make_float2(v0 + b1e[gc], v1 + b1e[gc + 1]);
    };
    mma_body(xh, xl, Bh, Bl, D_DIM, F_DIM, col0, arow, epi);
}

// ---------------- expert GEMM 2 + residual scatter ---------------------------
__global__ __launch_bounds__(256)
void gemm_mma_e2(const unsigned short* __restrict__ hhh, const unsigned short* __restrict__ hhl,
                 const unsigned short* __restrict__ w2h, const unsigned short* __restrict__ w2l,
                 const float* __restrict__ b2, const float* __restrict__ res_scale,
                 const float* __restrict__ x, float* __restrict__ moe)
{
    const int e = blockIdx.z;
    const int cnt = g_counts[e];
    const int rt = blockIdx.y * 128;
    if (rt >= cnt) return;
    const int off = g_offsets[e];
    const int col0 = blockIdx.x * 128;
    const unsigned short* Bh = w2h + (size_t)e * F_DIM * D_DIM;
    const unsigned short* Bl = w2l + (size_t)e * F_DIM * D_DIM;
    const float* b2e = b2 + (size_t)e * D_DIM;
    const float rsc = res_scale[e];
    auto arow = [&](int r) {
        int rr = rt + r; if (rr >= cnt) rr = cnt - 1;
        return off + rr;
    };
    auto epi = [&](int m, int c, float v0, float v1) {
        if (rt + m >= cnt) return;
        const int tok = g_p2t[off + rt + m];
        const int gc = col0 + c;
        const size_t base = (size_t)tok * D_DIM + gc;
        float2 xr = *(const float2*)&x[base];
        *(float2*)&moe[base] = make_float2((v0 + b2e[gc]) * rsc + xr.x,
                                           (v1 + b2e[gc + 1]) * rsc + xr.y);
    };
    mma_body(hhh, hhl, Bh, Bl, F_DIM, D_DIM, col0, arow, epi);
}

// ================= bf16 MMA flash attention ==================================
// smem: Q 128x64 (pitch 72 sh) h+l; K,V chunks 64x64 (pitch 72) h+l double-buf
#define AQH 0
#define AQL 18432
#define AKH(b) (36864 + (b) * 18432)
#define AKL(b) (46080 + (b) * 18432)
#define AVH(b) (73728 + (b) * 18432)
#define AVL(b) (82944 + (b) * 18432)
#define AQSC 110592
#define ATTN_SMEM (110592 + 512)

__global__ __launch_bounds__(256, 1)
void attn_mma(const unsigned short* __restrict__ qh, const unsigned short* __restrict__ ql,
              const unsigned short* __restrict__ kh, const unsigned short* __restrict__ kl,
              const unsigned short* __restrict__ vh, const unsigned short* __restrict__ vl,
              const float* __restrict__ scale_w,
              unsigned short* __restrict__ oh_, unsigned short* __restrict__ ol_)
{
    extern __shared__ char smem[];
    const uint32_t sb = smem_u32(smem);
    float* qsc = (float*)(smem + AQSC);
    const int t = threadIdx.x, lane = t & 31, warp = t >> 5;
    const int h = blockIdx.y & 15, b = blockIdx.y >> 4;
    const int qtok0 = b * S_LEN + blockIdx.x * 128;
    const size_t headoff = (size_t)h * 64;

    // Q load (group 0)
    {
        const int row = t >> 1, half = t & 1;
        const size_t so = (size_t)(qtok0 + row) * D_DIM + headoff + half * 32;
        const uint32_t dq = (uint32_t)(row * 144 + half * 64);
#pragma unroll
        for (int i = 0; i < 4; ++i) {
            CP_ASYNC16(sb + AQH + dq + i * 16, qh + so + i * 8);
            CP_ASYNC16(sb + AQL + dq + i * 16, ql + so + i * 8);
        }
        CP_COMMIT();
    }
    auto issueKV = [&](int c, int buf) {
        const int row = t >> 2, q2 = t & 3;
        const size_t so = (size_t)(b * S_LEN + c * 64 + row) * D_DIM + headoff + q2 * 16;
        const uint32_t d = (uint32_t)(row * 144 + q2 * 32);
        CP_ASYNC16(sb + AKH(buf) + d,      kh + so);
        CP_ASYNC16(sb + AKH(buf) + d + 16, kh + so + 8);
        CP_ASYNC16(sb + AKL(buf) + d,      kl + so);
        CP_ASYNC16(sb + AKL(buf) + d + 16, kl + so + 8);
        CP_ASYNC16(sb + AVH(buf) + d,      vh + so);
        CP_ASYNC16(sb + AVH(buf) + d + 16, vh + so + 8);
        CP_ASYNC16(sb + AVL(buf) + d,      vl + so);
        CP_ASYNC16(sb + AVL(buf) + d + 16, vl + so + 8);
        CP_COMMIT();
    };
    issueKV(0, 0);
    CP_WAIT1();
    __syncthreads();

    // per-row scale: 0.25 * sigmoid(q . scale_w[h])
    if (t < 128) {
        float s = 0.f;
        const char* qrow = smem + AQH + t * 144;
        const char* qrowl = smem + AQL + t * 144;
        for (int d = 0; d < 64; ++d) {
            float qv = bfu(((const unsigned short*)qrow)[d]) + bfu(((const unsigned short*)qrowl)[d]);
            s += qv * __ldg(&scale_w[h * 64 + d]);
        }
        qsc[t] = 0.25f / (1.f + __expf(-s));
    }

    const int mrow_l = (lane & 7) + ((lane >> 3) & 1) * 8;
    const int kcol_l = ((lane >> 4) & 1) * 8;
    const int r0loc = warp * 16 + (lane >> 2);

    float s[8][4];
    float o[8][4] = {};
    float m0 = -1e30f, m1 = -1e30f, l0 = 0.f, l1 = 0.f;

    for (int c = 0; c < 16; ++c) {
        CP_WAIT0();
        __syncthreads();
        if (c < 15) issueKV(c + 1, (c + 1) & 1);
        const uint32_t kbh = sb + AKH(c & 1), kbl = sb + AKL(c & 1);
        const uint32_t vbh = sb + AVH(c & 1), vbl = sb + AVL(c & 1);

        // ---- S = Q K^T (split bf16, 3 terms) ----
#pragma unroll
        for (int j = 0; j < 8; ++j) { s[j][0] = s[j][1] = s[j][2] = s[j][3] = 0.f; }
#pragma unroll
        for (int ks = 0; ks < 4; ++ks) {
            uint32_t ah[4], al[4];
            const uint32_t ao = (uint32_t)(warp * 16 + mrow_l) * 144 + (ks * 16 + kcol_l) * 2;
            ldsm4(ah, sb + AQH + ao);
            ldsm4(al, sb + AQL + ao);
#pragma unroll
            for (int g = 0; g < 4; ++g) {
                const uint32_t ro = (uint32_t)(g * 16 + mrow_l) * 144 + (ks * 16 + kcol_l) * 2;
                uint32_t bh4[4], bl4[4];
                ldsm4(bh4, kbh + ro);
                ldsm4(bl4, kbl + ro);
                mma16816(s[2 * g],     ah, bh4[0], bh4[2]);
                mma16816(s[2 * g],     ah, bl4[0], bl4[2]);
                mma16816(s[2 * g],     al, bh4[0], bh4[2]);
                mma16816(s[2 * g + 1], ah, bh4[1], bh4[3]);
                mma16816(s[2 * g + 1], ah, bl4[1], bl4[3]);
                mma16816(s[2 * g + 1], al, bh4[1], bh4[3]);
            }
        }
        // row scale
        const float f0 = qsc[r0loc], f1 = qsc[r0loc + 8];
#pragma unroll
        for (int j = 0; j < 8; ++j) { s[j][0] *= f0; s[j][1] *= f0; s[j][2] *= f1; s[j][3] *= f1; }
        // online softmax
        float rm0 = -1e30f, rm1 = -1e30f;
#pragma unroll
        for (int j = 0; j < 8; ++j) {
            rm0 = fmaxf(rm0, fmaxf(s[j][0], s[j][1]));
            rm1 = fmaxf(rm1, fmaxf(s[j][2], s[j][3]));
        }
        rm0 = fmaxf(rm0, __shfl_xor_sync(0xffffffffu, rm0, 1));
        rm0 = fmaxf(rm0, __shfl_xor_sync(0xffffffffu, rm0, 2));
        rm1 = fmaxf(rm1, __shfl_xor_sync(0xffffffffu, rm1, 1));
        rm1 = fmaxf(rm1, __shfl_xor_sync(0xffffffffu, rm1, 2));
        const float nm0 = fmaxf(m0, rm0), nm1 = fmaxf(m1, rm1);
        const float e0 = __expf(m0 - nm0), e1v = __expf(m1 - nm1);
        float sum0 = 0.f, sum1 = 0.f;
#pragma unroll
        for (int j = 0; j < 8; ++j) {
            s[j][0] = __expf(s[j][0] - nm0); sum0 += s[j][0];
            s[j][1] = __expf(s[j][1] - nm0); sum0 += s[j][1];
            s[j][2] = __expf(s[j][2] - nm1); sum1 += s[j][2];
            s[j][3] = __expf(s[j][3] - nm1); sum1 += s[j][3];
        }
        sum0 += __shfl_xor_sync(0xffffffffu, sum0, 1);
        sum0 += __shfl_xor_sync(0xffffffffu, sum0, 2);
        sum1 += __shfl_xor_sync(0xffffffffu, sum1, 1);
        sum1 += __shfl_xor_sync(0xffffffffu, sum1, 2);
        l0 = l0 * e0 + sum0;
        l1 = l1 * e1v + sum1;
        m0 = nm0; m1 = nm1;
#pragma unroll
        for (int j = 0; j < 8; ++j) { o[j][0] *= e0; o[j][1] *= e0; o[j][2] *= e1v; o[j][3] *= e1v; }

        // ---- O += P V (P split in-register, V split in smem, 3 terms) ----
#pragma unroll
        for (int kk = 0; kk < 4; ++kk) {
            uint32_t ph[4], pl[4];
            ph[0] = packbf(s[2 * kk][0],     s[2 * kk][1]);
            ph[1] = packbf(s[2 * kk][2],     s[2 * kk][3]);
            ph[2] = packbf(s[2 * kk + 1][0], s[2 * kk + 1][1]);
            ph[3] = packbf(s[2 * kk + 1][2], s[2 * kk + 1][3]);
#pragma unroll
            for (int q = 0; q < 4; ++q) {
                const int tj = 2 * kk + (q >> 1);
                const int c0i = (q & 1) * 2;
                const float h0 = __uint_as_float(ph[q] << 16);
                const float h1 = __uint_as_float(ph[q] & 0xffff0000u);
                pl[q] = packbf(s[tj][c0i] - h0, s[tj][c0i + 1] - h1);
            }
#pragma unroll
            for (int g = 0; g < 4; ++g) {
                const uint32_t ro = (uint32_t)(kk * 16 + (lane & 7) + ((lane >> 4) & 1) * 8) * 144
                                  + (uint32_t)(g * 16 + ((lane >> 3) & 1) * 8) * 2;
                uint32_t vh4[4], vl4[4];
                ldsm4t(vh4, vbh + ro);
                ldsm4t(vl4, vbl + ro);
                mma16816(o[2 * g],     ph, vh4[0], vh4[2]);
                mma16816(o[2 * g],     ph, vl4[0], vl4[2]);
                mma16816(o[2 * g],     pl, vh4[0], vh4[2]);
                mma16816(o[2 * g + 1], ph, vh4[1], vh4[3]);
                mma16816(o[2 * g + 1], ph, vl4[1], vl4[3]);
                mma16816(o[2 * g + 1], pl, vh4[1], vh4[3]);
            }
        }
    }

    // epilogue: write split bf16
    const float inv0 = 1.f / l0, inv1 = 1.f / l1;
    const int tok0 = qtok0 + r0loc, tok1 = tok0 + 8;
#pragma unroll
    for (int j = 0; j < 8; ++j) {
        const size_t col = headoff + j * 8 + (lane & 3) * 2;
        unsigned short h0, lo0, h1, lo1;
        split1(o[j][0] * inv0, h0, lo0);
        split1(o[j][1] * inv0, h1, lo1);
        *(ushort2*)&oh_[(size_t)tok0 * D_DIM + col] = make_ushort2(h0, h1);
        *(ushort2*)&ol_[(size_t)tok0 * D_DIM + col] = make_ushort2(lo0, lo1);
        split1(o[j][2] * inv1, h0, lo0);
        split1(o[j][3] * inv1, h1, lo1);
        *(ushort2*)&oh_[(size_t)tok1 * D_DIM + col] = make_ushort2(h0, h1);
        *(ushort2*)&ol_[(size_t)tok1 * D_DIM + col] = make_ushort2(lo0, lo1);
    }
}

// ---------------- streaming fp32 -> hi/lo bf16 split -------------------------
__global__ void cvt_kernel(const float* __restrict__ x, unsigned short* __restrict__ h,
                           unsigned short* __restrict__ l, int n4)
{
    const int i = blockIdx.x * 256 + threadIdx.x;
    if (i >= n4) return;
    float4 v = ((const float4*)x)[i];
    ushort4 hv, lv;
    split1(v.x, hv.x, lv.x);
    split1(v.y, hv.y, lv.y);
    split1(v.z, hv.z, lv.z);
    split1(v.w, hv.w, lv.w);
    ((ushort4*)h)[i] = hv;
    ((ushort4*)l)[i] = lv;
}

// ---------------- layernorm over residual sum -------------------------------
__global__ void ln2_kernel(const float* __restrict__ a, const float* __restrict__ b,
                           const float* __restrict__ g, const float* __restrict__ be,
                           float* __restrict__ out, int D)
{
    const int row = blockIdx.x, t = threadIdx.x;
    __shared__ float red[256];
    __shared__ float s_mean, s_rstd;
    float s1 = 0.f, s2 = 0.f;
    for (int i = t; i < D; i += 256) {
        float v = a[(size_t)row * D + i] + b[(size_t)row * D + i];
        s1 += v; s2 += v * v;
    }
    red[t] = s1; __syncthreads();
    for (int o = 128; o; o >>= 1) { if (t < o) red[t] += red[t + o]; __syncthreads(); }
    if (t == 0) s_mean = red[0] / D;
    __syncthreads();
    red[t] = s2; __syncthreads();
    for (int o = 128; o; o >>= 1) { if (t < o) red[t] += red[t + o]; __syncthreads(); }
    if (t == 0) {
        float var = red[0] / D - s_mean * s_mean;
        s_rstd = rsqrtf(var + 1e-5f);
    }
    __syncthreads();
    for (int i = t; i < D; i += 256) {
        float v = a[(size_t)row * D + i] + b[(size_t)row * D + i];
        out[(size_t)row * D + i] = (v - s_mean) * s_rstd * g[i] + be[i];
    }
}

// ---------------- MoE routing ------------------------------------------------
__global__ void reset_kernel() { if (threadIdx.x < N_EXP) g_counts[threadIdx.x] = 0; }

__global__ void moe_gate_kernel(const float* __restrict__ x, const float* __restrict__ W,
                                const float* __restrict__ bias)
{
    const int n = blockIdx.x, t = threadIdx.x;
    const int e = t >> 5, lane = t & 31;
    float acc = 0.f;
    for (int d = lane; d < D_DIM; d += 32) acc += x[(size_t)n * D_DIM + d] * W[d * N_EXP + e];
    for (int o = 16; o; o >>= 1) acc += __shfl_down_sync(0xffffffffu, acc, o);
    __shared__ float lg[N_EXP];
    if (lane == 0) lg[e] = acc + bias[e];
    __syncthreads();
    if (t == 0) {
        int i1 = 0; float v1 = lg[0];
        for (int i = 1; i < N_EXP; ++i) if (lg[i] > v1) { v1 = lg[i]; i1 = i; }
        int i2 = -1; float v2 = -1e30f;
        for (int i = 0; i < N_EXP; ++i) {
            if (i == i1) continue;
            if (lg[i] > v2) { v2 = lg[i]; i2 = i; }
        }
        int c = (i1 > i2) ? i1 : i2;
        g_chosen[n] = c;
        atomicAdd(&g_counts[c], 1);
    }
}

__global__ void scan_kernel()
{
    if (threadIdx.x == 0) {
        int s = 0;
        for (int e = 0; e < N_EXP; ++e) { g_offsets[e] = s; g_cursor[e] = s; s += g_counts[e]; }
    }
}

__global__ void scatter_kernel()
{
    int n = blockIdx.x * 256 + threadIdx.x;
    if (n < N_TOK) {
        int c = g_chosen[n];
        int p = atomicAdd(&g_cursor[c], 1);
        g_p2t[p] = n;
        g_p2e[p] = c;
    }
}

// ---------------- per-expert LN + exact GELU ---------------------------------
__global__ void ln_gelu_kernel(float* __restrict__ hh, const float* __restrict__ ln_g,
                               const float* __restrict__ ln_b)
{
    const int p = blockIdx.x, t = threadIdx.x;
    const int e = g_p2e[p];
    float* row = hh + (size_t)p * F_DIM;
    const float* gg = ln_g + (size_t)e * F_DIM;
    const float* bb = ln_b + (size_t)e * F_DIM;
    __shared__ float red[256];
    __shared__ float s_mean, s_rstd;
    float s1 = 0.f, s2 = 0.f;
    for (int i = t; i < F_DIM; i += 256) { float v = row[i]; s1 += v; s2 += v * v; }
    red[t] = s1; __syncthreads();
    for (int o = 128; o; o >>= 1) { if (t < o) red[t] += red[t + o]; __syncthreads(); }
    if (t == 0) s_mean = red[0] / F_DIM;
    __syncthreads();
    red[t] = s2; __syncthreads();
    for (int o = 128; o; o >>= 1) { if (t < o) red[t] += red[t + o]; __syncthreads(); }
    if (t == 0) {
        float var = red[0] / F_DIM - s_mean * s_mean;
        s_rstd = rsqrtf(var + 1e-5f);
    }
    __syncthreads();
    for (int i = t; i < F_DIM; i += 256) {
        float tv = (row[i] - s_mean) * s_rstd * gg[i] + bb[i];
        row[i] = 0.5f * tv * (1.f + erff(tv * 0.70710678118654752f));
    }
}

// ---------------- host launcher ---------------------------------------------
extern "C" void kernel_launch(void* const* d_in, const int* in_sizes, int n_in,
                              void* d_out, int out_size)
{
    (void)in_sizes; (void)n_in; (void)out_size;
    const float* src        = (const float*)d_in[0];
    const float* q_w        = (const float*)d_in[1];
    const float* k_w        = (const float*)d_in[2];
    const float* v_w        = (const float*)d_in[3];
    const float* out_w      = (const float*)d_in[4];
    const float* gate_w     = (const float*)d_in[5];
    const float* gate_b     = (const float*)d_in[6];
    const float* scale_w    = (const float*)d_in[7];
    const float* n1_g       = (const float*)d_in[8];
    const float* n1_b       = (const float*)d_in[9];
    const float* n2_g       = (const float*)d_in[10];
    const float* n2_b       = (const float*)d_in[11];
    const float* moe_gate_w = (const float*)d_in[12];
    const float* moe_gate_b = (const float*)d_in[13];
    const float* w1         = (const float*)d_in[14];
    const float* b1         = (const float*)d_in[15];
    const float* ln_g       = (const float*)d_in[16];
    const float* ln_b       = (const float*)d_in[17];
    const float* w2         = (const float*)d_in[18];
    const float* b2         = (const float*)d_in[19];
    const float* res_scale  = (const float*)d_in[20];

    float *attnp, *xb, *hhb, *moeb;
    cudaGetSymbolAddress((void**)&attnp, g_attnp);
    cudaGetSymbolAddress((void**)&xb, g_x);
    cudaGetSymbolAddress((void**)&hhb, g_hh);
    cudaGetSymbolAddress((void**)&moeb, g_moe);

    unsigned short *acth, *actl, *wth, *wtl, *w1h, *w1l, *w2h, *w2l;
    unsigned short *qh, *ql, *kh, *kl, *vh, *vl, *ah, *al, *gh, *gl;
    cudaGetSymbolAddress((void**)&acth, g_act_h);
    cudaGetSymbolAddress((void**)&actl, g_act_l);
    cudaGetSymbolAddress((void**)&wth, g_wt_h);
    cudaGetSymbolAddress((void**)&wtl, g_wt_l);
    cudaGetSymbolAddress((void**)&w1h, g_w1_h);
    cudaGetSymbolAddress((void**)&w1l, g_w1_l);
    cudaGetSymbolAddress((void**)&w2h, g_w2_h);
    cudaGetSymbolAddress((void**)&w2l, g_w2_l);
    cudaGetSymbolAddress((void**)&qh, g_qh);  cudaGetSymbolAddress((void**)&ql, g_ql);
    cudaGetSymbolAddress((void**)&kh, g_kh);  cudaGetSymbolAddress((void**)&kl, g_kl);
    cudaGetSymbolAddress((void**)&vh, g_vh);  cudaGetSymbolAddress((void**)&vl, g_vl);
    cudaGetSymbolAddress((void**)&ah, g_ah);  cudaGetSymbolAddress((void**)&al, g_al);
    cudaGetSymbolAddress((void**)&gh, g_gh);  cudaGetSymbolAddress((void**)&gl, g_gl);

    cudaFuncSetAttribute(attn_mma, cudaFuncAttributeMaxDynamicSharedMemorySize, ATTN_SMEM);
    cudaFuncSetAttribute(gemm_mma_dense, cudaFuncAttributeMaxDynamicSharedMemorySize, MMA_SMEM);
    cudaFuncSetAttribute(gemm_mma_e1, cudaFuncAttributeMaxDynamicSharedMemorySize, MMA_SMEM);
    cudaFuncSetAttribute(gemm_mma_e2, cudaFuncAttributeMaxDynamicSharedMemorySize, MMA_SMEM);

    const size_t WSZ = (size_t)D_DIM * D_DIM;
    const int WN4 = (int)(WSZ / 4);

    // streaming weight splits (no transpose — GEMM consumes [K,N] via ldmatrix.trans)
    cvt_kernel<<<(WN4 + 255) / 256, 256>>>(q_w,    wth + 0 * WSZ, wtl + 0 * WSZ, WN4);
    cvt_kernel<<<(WN4 + 255) / 256, 256>>>(k_w,    wth + 1 * WSZ, wtl + 1 * WSZ, WN4);
    cvt_kernel<<<(WN4 + 255) / 256, 256>>>(v_w,    wth + 2 * WSZ, wtl + 2 * WSZ, WN4);
    cvt_kernel<<<(WN4 + 255) / 256, 256>>>(out_w,  wth + 3 * WSZ, wtl + 3 * WSZ, WN4);
    cvt_kernel<<<(WN4 + 255) / 256, 256>>>(gate_w, wth + 4 * WSZ, wtl + 4 * WSZ, WN4);
    {
        const int n4 = N_EXP * D_DIM * F_DIM / 4;
        cvt_kernel<<<(n4 + 255) / 256, 256>>>(w1, w1h, w1l, n4);
        cvt_kernel<<<(n4 + 255) / 256, 256>>>(w2, w2h, w2l, n4);
    }

    reset_kernel<<<1, 32>>>();

    // src split, then QKV (batched z=3, epilogue writes bf16 hi/lo)
    cvt_kernel<<<(N_TOK * D_DIM / 4 + 255) / 256, 256>>>(src, acth, actl, N_TOK * D_DIM / 4);
    {
        DenseArgs da = {};
        for (int z = 0; z < 3; ++z) {
            da.Bh[z] = wth + (size_t)z * WSZ;
            da.Bl[z] = wtl + (size_t)z * WSZ;
            da.mode[z] = 2;
        }
        da.Ch[0] = qh; da.Cl[0] = ql;
        da.Ch[1] = kh; da.Cl[1] = kl;
        da.Ch[2] = vh; da.Cl[2] = vl;
        gemm_mma_dense<<<dim3(8, 16, 3), 256, MMA_SMEM>>>(acth, actl, da, D_DIM, D_DIM);
    }

    // attention (bf16 MMA, split-compensated) -> attno splits
    attn_mma<<<dim3(8, 32), 256, ATTN_SMEM>>>(qh, ql, kh, kl, vh, vl, scale_w, ah, al);

    // gated = sigmoid(attno @ gate_w + gate_b) * attno  -> splits
    {
        DenseArgs da = {};
        da.Bh[0] = wth + 4 * WSZ; da.Bl[0] = wtl + 4 * WSZ;
        da.bias[0] = gate_b;
        da.auxh[0] = ah; da.auxl[0] = al;
        da.Ch[0] = gh; da.Cl[0] = gl;
        da.mode[0] = 1;
        gemm_mma_dense<<<dim3(8, 16, 1), 256, MMA_SMEM>>>(ah, al, da, D_DIM, D_DIM);
    }

    // attnp = gated @ out_w (fp32 out)
    {
        DenseArgs da = {};
        da.Bh[0] = wth + 3 * WSZ; da.Bl[0] = wtl + 3 * WSZ;
        da.C[0] = attnp;
        da.mode[0] = 0;
        gemm_mma_dense<<<dim3(8, 16, 1), 256, MMA_SMEM>>>(gh, gl, da, D_DIM, D_DIM);
    }

    ln2_kernel<<<N_TOK, 256>>>(src, attnp, n1_g, n1_b, xb, D_DIM);

    moe_gate_kernel<<<N_TOK, 256>>>(xb, moe_gate_w, moe_gate_b);
    scan_kernel<<<1, 32>>>();
    scatter_kernel<<<N_TOK / 256, 256>>>();

    cvt_kernel<<<(N_TOK * D_DIM / 4 + 255) / 256, 256>>>(xb, acth, actl, N_TOK * D_DIM / 4);
    gemm_mma_e1<<<dim3(F_DIM / 128, N_TOK / 128, N_EXP), 256, MMA_SMEM>>>(
        acth, actl, w1h, w1l, b1, hhb);
    ln_gelu_kernel<<<N_TOK, 256>>>(hhb, ln_g, ln_b);
    cvt_kernel<<<(N_TOK * F_DIM / 4 + 255) / 256, 256>>>(hhb, acth, actl, N_TOK * F_DIM / 4);
    gemm_mma_e2<<<dim3(D_DIM / 128, N_TOK / 128, N_EXP), 256, MMA_SMEM>>>(
        acth, actl, w2h, w2l, b2, res_scale, xb, moeb);

    ln2_kernel<<<N_TOK, 256>>>(xb, moeb, n2_g, n2_b, (float*)d_out, D_DIM);
}

// round 8
// speedup vs baseline: 2.0456x; 1.0071x over previous
#include <cuda_runtime.h>
#include <cuda_bf16.h>
#include <math.h>
#include <stdint.h>

#define N_TOK 2048
#define D_DIM 1024
#define F_DIM 2048
#define N_EXP 8
#define N_HEAD 16
#define S_LEN 1024

// ---------------- fp32 scratch ----------------------------------------------
__device__ float g_attnp[N_TOK * D_DIM];
__device__ float g_x[N_TOK * D_DIM];
__device__ float g_hh[N_TOK * F_DIM];
__device__ float g_moe[N_TOK * D_DIM];
__device__ int   g_chosen[N_TOK];
__device__ int   g_counts[N_EXP];
__device__ int   g_offsets[N_EXP];
__device__ int   g_cursor[N_EXP];
__device__ int   g_p2t[N_TOK];
__device__ int   g_p2e[N_TOK];

// ---------------- bf16 split scratch (ushort) --------------------------------
__device__ unsigned short g_act_h[N_TOK * F_DIM];
__device__ unsigned short g_act_l[N_TOK * F_DIM];
__device__ unsigned short g_qh[N_TOK * D_DIM];
__device__ unsigned short g_ql[N_TOK * D_DIM];
__device__ unsigned short g_kh[N_TOK * D_DIM];
__device__ unsigned short g_kl[N_TOK * D_DIM];
__device__ unsigned short g_vh[N_TOK * D_DIM];
__device__ unsigned short g_vl[N_TOK * D_DIM];
__device__ unsigned short g_ah[N_TOK * D_DIM];
__device__ unsigned short g_al[N_TOK * D_DIM];
__device__ unsigned short g_gh[N_TOK * D_DIM];
__device__ unsigned short g_gl[N_TOK * D_DIM];
__device__ unsigned short g_wt_h[5 * D_DIM * D_DIM];
__device__ unsigned short g_wt_l[5 * D_DIM * D_DIM];
__device__ unsigned short g_w1_h[N_EXP * D_DIM * F_DIM];
__device__ unsigned short g_w1_l[N_EXP * D_DIM * F_DIM];
__device__ unsigned short g_w2_h[N_EXP * F_DIM * D_DIM];
__device__ unsigned short g_w2_l[N_EXP * F_DIM * D_DIM];

// ================= helpers ====================================================
__device__ __forceinline__ uint32_t smem_u32(const void* p) {
    uint32_t a;
    asm("{ .reg .u64 t; cvta.to.shared.u64 t, %1; cvt.u32.u64 %0, t; }" : "=r"(a) : "l"(p));
    return a;
}
#define CP_ASYNC16(dst, src) \
    asm volatile("cp.async.cg.shared.global [%0], [%1], 16;" :: "r"(dst), "l"(src))
#define CP_COMMIT() asm volatile("cp.async.commit_group;" ::: "memory")
#define CP_WAIT0()  asm volatile("cp.async.wait_group 0;" ::: "memory")
#define CP_WAIT1()  asm volatile("cp.async.wait_group 1;" ::: "memory")

__device__ __forceinline__ void ldsm4(uint32_t* r, uint32_t addr) {
    asm volatile("ldmatrix.sync.aligned.m8n8.x4.shared.b16 {%0,%1,%2,%3}, [%4];"
        : "=r"(r[0]), "=r"(r[1]), "=r"(r[2]), "=r"(r[3]) : "r"(addr));
}
__device__ __forceinline__ void ldsm4t(uint32_t* r, uint32_t addr) {
    asm volatile("ldmatrix.sync.aligned.m8n8.x4.trans.shared.b16 {%0,%1,%2,%3}, [%4];"
        : "=r"(r[0]), "=r"(r[1]), "=r"(r[2]), "=r"(r[3]) : "r"(addr));
}
__device__ __forceinline__ void mma16816(float* c, const uint32_t* a, uint32_t b0, uint32_t b1) {
    asm volatile("mma.sync.aligned.m16n8k16.row.col.f32.bf16.bf16.f32 "
        "{%0,%1,%2,%3}, {%4,%5,%6,%7}, {%8,%9}, {%0,%1,%2,%3};"
        : "+f"(c[0]), "+f"(c[1]), "+f"(c[2]), "+f"(c[3])
        : "r"(a[0]), "r"(a[1]), "r"(a[2]), "r"(a[3]), "r"(b0), "r"(b1));
}
__device__ __forceinline__ uint32_t packbf(float lo, float hi) {
    uint32_t r;
    asm("cvt.rn.bf16x2.f32 %0, %1, %2;" : "=r"(r) : "f"(hi), "f"(lo));
    return r;
}
__device__ __forceinline__ float bfu(unsigned short u) {
    return __uint_as_float(((uint32_t)u) << 16);
}
__device__ __forceinline__ void split1(float v, unsigned short& h, unsigned short& l) {
    __nv_bfloat16 hb = __float2bfloat16(v);
    float r = v - __bfloat162float(hb);
    __nv_bfloat16 lb = __float2bfloat16(r);
    h = *(unsigned short*)&hb;
    l = *(unsigned short*)&lb;
}

// ================= GEMM: 128x128 tile, split-bf16, B in natural [K,N] ========
#define A_OFF_H 0
#define A_OFF_L 10240
#define B_OFF_H 20480
#define B_OFF_L 29184
#define STAGE_BYTES 37888
#define MMA_SMEM (2 * STAGE_BYTES)

template <class AROW, class EPI>
__device__ __forceinline__ void mma_body(const unsigned short* __restrict__ Ah,
                                         const unsigned short* __restrict__ Al,
                                         const unsigned short* __restrict__ Bh,
                                         const unsigned short* __restrict__ Bl,
                                         int K, int N, int col0, AROW arow, EPI epi)
{
    extern __shared__ char smem[];
    const uint32_t sb = smem_u32(smem);
    const int t = threadIdx.x;
    const int lane = t & 31, warp = t >> 5;
    const int warpM = warp >> 2, warpN = warp & 3;

    const int lrow = t >> 1, aseg = (t & 1) * 2;
    const int aRow = arow(lrow);
    const unsigned short* srcAh = Ah + (size_t)aRow * K + aseg * 8;
    const unsigned short* srcAl = Al + (size_t)aRow * K + aseg * 8;
    const uint32_t adst = lrow * 80 + aseg * 16;
    const int brow = t >> 3, bcol = (t & 7) * 16;
    const unsigned short* srcBh = Bh + (size_t)brow * N + col0 + bcol;
    const unsigned short* srcBl = Bl + (size_t)brow * N + col0 + bcol;
    const uint32_t bdst = brow * 272 + bcol * 2;

    auto issue_stage = [&](int k0, int buf) {
        const uint32_t s = sb + buf * STAGE_BYTES;
        CP_ASYNC16(s + A_OFF_H + adst,      srcAh + k0);
        CP_ASYNC16(s + A_OFF_H + adst + 16, srcAh + k0 + 8);
        CP_ASYNC16(s + A_OFF_L + adst,      srcAl + k0);
        CP_ASYNC16(s + A_OFF_L + adst + 16, srcAl + k0 + 8);
        const size_t bko = (size_t)k0 * N;
        CP_ASYNC16(s + B_OFF_H + bdst,      srcBh + bko);
        CP_ASYNC16(s + B_OFF_H + bdst + 16, srcBh + bko + 8);
        CP_ASYNC16(s + B_OFF_L + bdst,      srcBl + bko);
        CP_ASYNC16(s + B_OFF_L + bdst + 16, srcBl + bko + 8);
        CP_COMMIT();
    };

    const int mrow_l = (lane & 7) + ((lane >> 3) & 1) * 8;
    const int kcol_l = ((lane >> 4) & 1) * 8;

    float acc[4][4][4] = {};

    issue_stage(0, 0);
    const int NS = K >> 5;
    int buf = 0;
    for (int s = 0; s < NS; ++s) {
        CP_WAIT0();
        __syncthreads();
        if (s + 1 < NS) issue_stage((s + 1) * 32, buf ^ 1);

        const uint32_t sbase = sb + buf * STAGE_BYTES;
#pragma unroll
        for (int ks = 0; ks < 2; ++ks) {
            const int kb = ks * 16;
            uint32_t ah[4][4], al[4][4], bh4[2][4], bl4[2][4];
#pragma unroll
            for (int mi = 0; mi < 4; ++mi) {
                const uint32_t ro = (uint32_t)(warpM * 64 + mi * 16 + mrow_l) * 80 + (kb + kcol_l) * 2;
                ldsm4(ah[mi], sbase + A_OFF_H + ro);
                ldsm4(al[mi], sbase + A_OFF_L + ro);
            }
#pragma unroll
            for (int g = 0; g < 2; ++g) {
                const uint32_t ro = (uint32_t)(kb + (lane & 7) + ((lane >> 4) & 1) * 8) * 272
                                  + (uint32_t)(warpN * 32 + g * 16 + ((lane >> 3) & 1) * 8) * 2;
                ldsm4t(bh4[g], sbase + B_OFF_H + ro);
                ldsm4t(bl4[g], sbase + B_OFF_L + ro);
            }
#pragma unroll
            for (int mi = 0; mi < 4; ++mi)
#pragma unroll
                for (int nj = 0; nj < 4; ++nj) {
                    const int g = nj >> 1, hi = nj & 1;
                    mma16816(acc[mi][nj], ah[mi], bh4[g][hi], bh4[g][hi + 2]);
                    mma16816(acc[mi][nj], ah[mi], bl4[g][hi], bl4[g][hi + 2]);
                    mma16816(acc[mi][nj], al[mi], bh4[g][hi], bh4[g][hi + 2]);
                }
        }
        __syncthreads();
        buf ^= 1;
    }

#pragma unroll
    for (int mi = 0; mi < 4; ++mi)
#pragma unroll
        for (int nj = 0; nj < 4; ++nj) {
            const int r0 = warpM * 64 + mi * 16 + (lane >> 2);
            const int c  = warpN * 32 + nj * 8 + (lane & 3) * 2;
            epi(r0,     c, acc[mi][nj][0], acc[mi][nj][1]);
            epi(r0 + 8, c, acc[mi][nj][2], acc[mi][nj][3]);
        }
}

// ---------------- dense GEMM (batched up to 3 via z) -------------------------
struct DenseArgs {
    const unsigned short* Bh[3];
    const unsigned short* Bl[3];
    const float* bias[3];
    const unsigned short* auxh[3];
    const unsigned short* auxl[3];
    float* C[3];
    unsigned short* Ch[3];
    unsigned short* Cl[3];
    int mode[3];
};
__global__ __launch_bounds__(256, 2)
void gemm_mma_dense(const unsigned short* __restrict__ Ah, const unsigned short* __restrict__ Al,
                    DenseArgs da, int N, int K)
{
    const int z = blockIdx.z;
    const int row0 = blockIdx.y * 128, col0 = blockIdx.x * 128;
    const unsigned short* Bh = da.Bh[z];
    const unsigned short* Bl = da.Bl[z];
    const float* bias = da.bias[z];
    const unsigned short* auxh = da.auxh[z];
    const unsigned short* auxl = da.auxl[z];
    float* C = da.C[z];
    unsigned short* Ch = da.Ch[z];
    unsigned short* Cl = da.Cl[z];
    const int mode = da.mode[z];
    auto arow = [&](int r) { return row0 + r; };
    auto epi = [&](int m, int c, float v0, float v1) {
        const int gc = col0 + c;
        const size_t base = (size_t)(row0 + m) * N + gc;
        if (mode == 0) {
            if (bias) { v0 += bias[gc]; v1 += bias[gc + 1]; }
            *(float2*)&C[base] = make_float2(v0, v1);
        } else if (mode == 1) {
            v0 += bias[gc]; v1 += bias[gc + 1];
            float a0 = bfu(auxh[base]) + bfu(auxl[base]);
            float a1 = bfu(auxh[base + 1]) + bfu(auxl[base + 1]);
            v0 = a0 / (1.f + __expf(-v0));
            v1 = a1 / (1.f + __expf(-v1));
            unsigned short h0, l0, h1, l1;
            split1(v0, h0, l0); split1(v1, h1, l1);
            *(ushort2*)&Ch[base] = make_ushort2(h0, h1);
            *(ushort2*)&Cl[base] = make_ushort2(l0, l1);
        } else {
            unsigned short h0, l0, h1, l1;
            split1(v0, h0, l0); split1(v1, h1, l1);
            *(ushort2*)&Ch[base] = make_ushort2(h0, h1);
            *(ushort2*)&Cl[base] = make_ushort2(l0, l1);
        }
    };
    mma_body(Ah, Al, Bh, Bl, K, N, col0, arow, epi);
}

// ---------------- expert GEMM 1: hh = x @ w1[e] + b1 -------------------------
__global__ __launch_bounds__(256, 2)
void gemm_mma_e1(const unsigned short* __restrict__ xh, const unsigned short* __restrict__ xl,
                 const unsigned short* __restrict__ w1h, const unsigned short* __restrict__ w1l,
                 const float* __restrict__ b1, float* __restrict__ hh)
{
    const int e = blockIdx.z;
    const int cnt = g_counts[e];
    const int rt = blockIdx.y * 128;
    if (rt >= cnt) return;
    const int off = g_offsets[e];
    const int col0 = blockIdx.x * 128;
    const unsigned short* Bh = w1h + (size_t)e * D_DIM * F_DIM;
    const unsigned short* Bl = w1l + (size_t)e * D_DIM * F_DIM;
    const float* b1e = b1 + (size_t)e * F_DIM;
    auto arow = [&](int r) {
        int rr = rt + r; if (rr >= cnt) rr = cnt - 1;
        return g_p2t[off + rr];
    };
    auto epi = [&](int m, int c, float v0, float v1) {
        if (rt + m >= cnt) return;
        const int gc = col0 + c;
        const size_t base = (size_t)(off + rt + m) * F_DIM + gc;
        *(float2*)&hh[base] = make_float2(v0 + b1e[gc], v1 + b1e[gc + 1]);
    };
    mma_body(xh, xl, Bh, Bl, D_DIM, F_DIM, col0, arow, epi);
}

// ---------------- expert GEMM 2 + residual scatter ---------------------------
__global__ __launch_bounds__(256, 2)
void gemm_mma_e2(const unsigned short* __restrict__ hhh, const unsigned short* __restrict__ hhl,
                 const unsigned short* __restrict__ w2h, const unsigned short* __restrict__ w2l,
                 const float* __restrict__ b2, const float* __restrict__ res_scale,
                 const float* __restrict__ x, float* __restrict__ moe)
{
    const int e = blockIdx.z;
    const int cnt = g_counts[e];
    const int rt = blockIdx.y * 128;
    if (rt >= cnt) return;
    const int off = g_offsets[e];
    const int col0 = blockIdx.x * 128;
    const unsigned short* Bh = w2h + (size_t)e * F_DIM * D_DIM;
    const unsigned short* Bl = w2l + (size_t)e * F_DIM * D_DIM;
    const float* b2e = b2 + (size_t)e * D_DIM;
    const float rsc = res_scale[e];
    auto arow = [&](int r) {
        int rr = rt + r; if (rr >= cnt) rr = cnt - 1;
        return off + rr;
    };
    auto epi = [&](int m, int c, float v0, float v1) {
        if (rt + m >= cnt) return;
        const int tok = g_p2t[off + rt + m];
        const int gc = col0 + c;
        const size_t base = (size_t)tok * D_DIM + gc;
        float2 xr = *(const float2*)&x[base];
        *(float2*)&moe[base] = make_float2((v0 + b2e[gc]) * rsc + xr.x,
                                           (v1 + b2e[gc + 1]) * rsc + xr.y);
    };
    mma_body(hhh, hhl, Bh, Bl, F_DIM, D_DIM, col0, arow, epi);
}

// ================= bf16 MMA flash attention ==================================
#define AQH 0
#define AQL 18432
#define AKH(b) (36864 + (b) * 18432)
#define AKL(b) (46080 + (b) * 18432)
#define AVH(b) (73728 + (b) * 18432)
#define AVL(b) (82944 + (b) * 18432)
#define AQSC 110592
#define ATTN_SMEM (110592 + 512)

__global__ __launch_bounds__(256, 1)
void attn_mma(const unsigned short* __restrict__ qh, const unsigned short* __restrict__ ql,
              const unsigned short* __restrict__ kh, const unsigned short* __restrict__ kl,
              const unsigned short* __restrict__ vh, const unsigned short* __restrict__ vl,
              const float* __restrict__ scale_w,
              unsigned short* __restrict__ oh_, unsigned short* __restrict__ ol_)
{
    extern __shared__ char smem[];
    const uint32_t sb = smem_u32(smem);
    float* qsc = (float*)(smem + AQSC);
    const int t = threadIdx.x, lane = t & 31, warp = t >> 5;
    const int h = blockIdx.y & 15, b = blockIdx.y >> 4;
    const int qtok0 = b * S_LEN + blockIdx.x * 128;
    const size_t headoff = (size_t)h * 64;

    {
        const int row = t >> 1, half = t & 1;
        const size_t so = (size_t)(qtok0 + row) * D_DIM + headoff + half * 32;
        const uint32_t dq = (uint32_t)(row * 144 + half * 64);
#pragma unroll
        for (int i = 0; i < 4; ++i) {
            CP_ASYNC16(sb + AQH + dq + i * 16, qh + so + i * 8);
            CP_ASYNC16(sb + AQL + dq + i * 16, ql + so + i * 8);
        }
        CP_COMMIT();
    }
    auto issueKV = [&](int c, int buf) {
        const int row = t >> 2, q2 = t & 3;
        const size_t so = (size_t)(b * S_LEN + c * 64 + row) * D_DIM + headoff + q2 * 16;
        const uint32_t d = (uint32_t)(row * 144 + q2 * 32);
        CP_ASYNC16(sb + AKH(buf) + d,      kh + so);
        CP_ASYNC16(sb + AKH(buf) + d + 16, kh + so + 8);
        CP_ASYNC16(sb + AKL(buf) + d,      kl + so);
        CP_ASYNC16(sb + AKL(buf) + d + 16, kl + so + 8);
        CP_ASYNC16(sb + AVH(buf) + d,      vh + so);
        CP_ASYNC16(sb + AVH(buf) + d + 16, vh + so + 8);
        CP_ASYNC16(sb + AVL(buf) + d,      vl + so);
        CP_ASYNC16(sb + AVL(buf) + d + 16, vl + so + 8);
        CP_COMMIT();
    };
    issueKV(0, 0);
    CP_WAIT1();
    __syncthreads();

    if (t < 128) {
        float s = 0.f;
        const char* qrow = smem + AQH + t * 144;
        const char* qrowl = smem + AQL + t * 144;
        for (int d = 0; d < 64; ++d) {
            float qv = bfu(((const unsigned short*)qrow)[d]) + bfu(((const unsigned short*)qrowl)[d]);
            s += qv * __ldg(&scale_w[h * 64 + d]);
        }
        qsc[t] = 0.25f / (1.f + __expf(-s));
    }

    const int mrow_l = (lane & 7) + ((lane >> 3) & 1) * 8;
    const int kcol_l = ((lane >> 4) & 1) * 8;
    const int r0loc = warp * 16 + (lane >> 2);

    float s[8][4];
    float o[8][4] = {};
    float m0 = -1e30f, m1 = -1e30f, l0 = 0.f, l1 = 0.f;

    for (int c = 0; c < 16; ++c) {
        CP_WAIT0();
        __syncthreads();
        if (c < 15) issueKV(c + 1, (c + 1) & 1);
        const uint32_t kbh = sb + AKH(c & 1), kbl = sb + AKL(c & 1);
        const uint32_t vbh = sb + AVH(c & 1), vbl = sb + AVL(c & 1);

#pragma unroll
        for (int j = 0; j < 8; ++j) { s[j][0] = s[j][1] = s[j][2] = s[j][3] = 0.f; }
#pragma unroll
        for (int ks = 0; ks < 4; ++ks) {
            uint32_t ah[4], al[4];
            const uint32_t ao = (uint32_t)(warp * 16 + mrow_l) * 144 + (ks * 16 + kcol_l) * 2;
            ldsm4(ah, sb + AQH + ao);
            ldsm4(al, sb + AQL + ao);
#pragma unroll
            for (int g = 0; g < 4; ++g) {
                const uint32_t ro = (uint32_t)(g * 16 + mrow_l) * 144 + (ks * 16 + kcol_l) * 2;
                uint32_t bh4[4], bl4[4];
                ldsm4(bh4, kbh + ro);
                ldsm4(bl4, kbl + ro);
                mma16816(s[2 * g],     ah, bh4[0], bh4[2]);
                mma16816(s[2 * g],     ah, bl4[0], bl4[2]);
                mma16816(s[2 * g],     al, bh4[0], bh4[2]);
                mma16816(s[2 * g + 1], ah, bh4[1], bh4[3]);
                mma16816(s[2 * g + 1], ah, bl4[1], bl4[3]);
                mma16816(s[2 * g + 1], al, bh4[1], bh4[3]);
            }
        }
        const float f0 = qsc[r0loc], f1 = qsc[r0loc + 8];
#pragma unroll
        for (int j = 0; j < 8; ++j) { s[j][0] *= f0; s[j][1] *= f0; s[j][2] *= f1; s[j][3] *= f1; }
        float rm0 = -1e30f, rm1 = -1e30f;
#pragma unroll
        for (int j = 0; j < 8; ++j) {
            rm0 = fmaxf(rm0, fmaxf(s[j][0], s[j][1]));
            rm1 = fmaxf(rm1, fmaxf(s[j][2], s[j][3]));
        }
        rm0 = fmaxf(rm0, __shfl_xor_sync(0xffffffffu, rm0, 1));
        rm0 = fmaxf(rm0, __shfl_xor_sync(0xffffffffu, rm0, 2));
        rm1 = fmaxf(rm1, __shfl_xor_sync(0xffffffffu, rm1, 1));
        rm1 = fmaxf(rm1, __shfl_xor_sync(0xffffffffu, rm1, 2));
        const float nm0 = fmaxf(m0, rm0), nm1 = fmaxf(m1, rm1);
        const float e0 = __expf(m0 - nm0), e1v = __expf(m1 - nm1);
        float sum0 = 0.f, sum1 = 0.f;
#pragma unroll
        for (int j = 0; j < 8; ++j) {
            s[j][0] = __expf(s[j][0] - nm0); sum0 += s[j][0];
            s[j][1] = __expf(s[j][1] - nm0); sum0 += s[j][1];
            s[j][2] = __expf(s[j][2] - nm1); sum1 += s[j][2];
            s[j][3] = __expf(s[j][3] - nm1); sum1 += s[j][3];
        }
        sum0 += __shfl_xor_sync(0xffffffffu, sum0, 1);
        sum0 += __shfl_xor_sync(0xffffffffu, sum0, 2);
        sum1 += __shfl_xor_sync(0xffffffffu, sum1, 1);
        sum1 += __shfl_xor_sync(0xffffffffu, sum1, 2);
        l0 = l0 * e0 + sum0;
        l1 = l1 * e1v + sum1;
        m0 = nm0; m1 = nm1;
#pragma unroll
        for (int j = 0; j < 8; ++j) { o[j][0] *= e0; o[j][1] *= e0; o[j][2] *= e1v; o[j][3] *= e1v; }

#pragma unroll
        for (int kk = 0; kk < 4; ++kk) {
            uint32_t ph[4], pl[4];
            ph[0] = packbf(s[2 * kk][0],     s[2 * kk][1]);
            ph[1] = packbf(s[2 * kk][2],     s[2 * kk][3]);
            ph[2] = packbf(s[2 * kk + 1][0], s[2 * kk + 1][1]);
            ph[3] = packbf(s[2 * kk + 1][2], s[2 * kk + 1][3]);
#pragma unroll
            for (int q = 0; q < 4; ++q) {
                const int tj = 2 * kk + (q >> 1);
                const int c0i = (q & 1) * 2;
                const float h0 = __uint_as_float(ph[q] << 16);
                const float h1 = __uint_as_float(ph[q] & 0xffff0000u);
                pl[q] = packbf(s[tj][c0i] - h0, s[tj][c0i + 1] - h1);
            }
#pragma unroll
            for (int g = 0; g < 4; ++g) {
                const uint32_t ro = (uint32_t)(kk * 16 + (lane & 7) + ((lane >> 4) & 1) * 8) * 144
                                  + (uint32_t)(g * 16 + ((lane >> 3) & 1) * 8) * 2;
                uint32_t vh4[4], vl4[4];
                ldsm4t(vh4, vbh + ro);
                ldsm4t(vl4, vbl + ro);
                mma16816(o[2 * g],     ph, vh4[0], vh4[2]);
                mma16816(o[2 * g],     ph, vl4[0], vl4[2]);
                mma16816(o[2 * g],     pl, vh4[0], vh4[2]);
                mma16816(o[2 * g + 1], ph, vh4[1], vh4[3]);
                mma16816(o[2 * g + 1], ph, vl4[1], vl4[3]);
                mma16816(o[2 * g + 1], pl, vh4[1], vh4[3]);
            }
        }
    }

    const float inv0 = 1.f / l0, inv1 = 1.f / l1;
    const int tok0 = qtok0 + r0loc, tok1 = tok0 + 8;
#pragma unroll
    for (int j = 0; j < 8; ++j) {
        const size_t col = headoff + j * 8 + (lane & 3) * 2;
        unsigned short h0, lo0, h1, lo1;
        split1(o[j][0] * inv0, h0, lo0);
        split1(o[j][1] * inv0, h1, lo1);
        *(ushort2*)&oh_[(size_t)tok0 * D_DIM + col] = make_ushort2(h0, h1);
        *(ushort2*)&ol_[(size_t)tok0 * D_DIM + col] = make_ushort2(lo0, lo1);
        split1(o[j][2] * inv1, h0, lo0);
        split1(o[j][3] * inv1, h1, lo1);
        *(ushort2*)&oh_[(size_t)tok1 * D_DIM + col] = make_ushort2(h0, h1);
        *(ushort2*)&ol_[(size_t)tok1 * D_DIM + col] = make_ushort2(lo0, lo1);
    }
}

// ---------------- streaming fp32 -> hi/lo bf16 split (4x ILP) ----------------
// n4 must be a multiple of 4 (all call sites are powers of two >= 1024).
__global__ void cvt_kernel(const float* __restrict__ x, unsigned short* __restrict__ h,
                           unsigned short* __restrict__ l, int n4)
{
    const int base = blockIdx.x * 1024 + threadIdx.x;
    float4 v[4];
#pragma unroll
    for (int j = 0; j < 4; ++j) {
        const int i = base + j * 256;
        if (i < n4) v[j] = ((const float4*)x)[i];
    }
#pragma unroll
    for (int j = 0; j < 4; ++j) {
        const int i = base + j * 256;
        if (i >= n4) continue;
        ushort4 hv, lv;
        split1(v[j].x, hv.x, lv.x);
        split1(v[j].y, hv.y, lv.y);
        split1(v[j].z, hv.z, lv.z);
        split1(v[j].w, hv.w, lv.w);
        ((ushort4*)h)[i] = hv;
        ((ushort4*)l)[i] = lv;
    }
}
#define CVT_GRID(n4) (((n4) + 1023) / 1024)

// ---------------- layernorm over residual sum -------------------------------
__global__ void ln2_kernel(const float* __restrict__ a, const float* __restrict__ b,
                           const float* __restrict__ g, const float* __restrict__ be,
                           float* __restrict__ out, int D)
{
    const int row = blockIdx.x, t = threadIdx.x;
    __shared__ float red[256];
    __shared__ float s_mean, s_rstd;
    float s1 = 0.f, s2 = 0.f;
    for (int i = t; i < D; i += 256) {
        float v = a[(size_t)row * D + i] + b[(size_t)row * D + i];
        s1 += v; s2 += v * v;
    }
    red[t] = s1; __syncthreads();
    for (int o = 128; o; o >>= 1) { if (t < o) red[t] += red[t + o]; __syncthreads(); }
    if (t == 0) s_mean = red[0] / D;
    __syncthreads();
    red[t] = s2; __syncthreads();
    for (int o = 128; o; o >>= 1) { if (t < o) red[t] += red[t + o]; __syncthreads(); }
    if (t == 0) {
        float var = red[0] / D - s_mean * s_mean;
        s_rstd = rsqrtf(var + 1e-5f);
    }
    __syncthreads();
    for (int i = t; i < D; i += 256) {
        float v = a[(size_t)row * D + i] + b[(size_t)row * D + i];
        out[(size_t)row * D + i] = (v - s_mean) * s_rstd * g[i] + be[i];
    }
}

// ---------------- MoE routing ------------------------------------------------
__global__ void reset_kernel() { if (threadIdx.x < N_EXP) g_counts[threadIdx.x] = 0; }

__global__ void moe_gate_kernel(const float* __restrict__ x, const float* __restrict__ W,
                                const float* __restrict__ bias)
{
    const int n = blockIdx.x, t = threadIdx.x;
    const int e = t >> 5, lane = t & 31;
    float acc = 0.f;
    for (int d = lane; d < D_DIM; d += 32) acc += x[(size_t)n * D_DIM + d] * W[d * N_EXP + e];
    for (int o = 16; o; o >>= 1) acc += __shfl_down_sync(0xffffffffu, acc, o);
    __shared__ float lg[N_EXP];
    if (lane == 0) lg[e] = acc + bias[e];
    __syncthreads();
    if (t == 0) {
        int i1 = 0; float v1 = lg[0];
        for (int i = 1; i < N_EXP; ++i) if (lg[i] > v1) { v1 = lg[i]; i1 = i; }
        int i2 = -1; float v2 = -1e30f;
        for (int i = 0; i < N_EXP; ++i) {
            if (i == i1) continue;
            if (lg[i] > v2) { v2 = lg[i]; i2 = i; }
        }
        int c = (i1 > i2) ? i1 : i2;
        g_chosen[n] = c;
        atomicAdd(&g_counts[c], 1);
    }
}

__global__ void scan_kernel()
{
    if (threadIdx.x == 0) {
        int s = 0;
        for (int e = 0; e < N_EXP; ++e) { g_offsets[e] = s; g_cursor[e] = s; s += g_counts[e]; }
    }
}

__global__ void scatter_kernel()
{
    int n = blockIdx.x * 256 + threadIdx.x;
    if (n < N_TOK) {
        int c = g_chosen[n];
        int p = atomicAdd(&g_cursor[c], 1);
        g_p2t[p] = n;
        g_p2e[p] = c;
    }
}

// ---------------- per-expert LN + exact GELU ---------------------------------
__global__ void ln_gelu_kernel(float* __restrict__ hh, const float* __restrict__ ln_g,
                               const float* __restrict__ ln_b)
{
    const int p = blockIdx.x, t = threadIdx.x;
    const int e = g_p2e[p];
    float* row = hh + (size_t)p * F_DIM;
    const float* gg = ln_g + (size_t)e * F_DIM;
    const float* bb = ln_b + (size_t)e * F_DIM;
    __shared__ float red[256];
    __shared__ float s_mean, s_rstd;
    float s1 = 0.f, s2 = 0.f;
    for (int i = t; i < F_DIM; i += 256) { float v = row[i]; s1 += v; s2 += v * v; }
    red[t] = s1; __syncthreads();
    for (int o = 128; o; o >>= 1) { if (t < o) red[t] += red[t + o]; __syncthreads(); }
    if (t == 0) s_mean = red[0] / F_DIM;
    __syncthreads();
    red[t] = s2; __syncthreads();
    for (int o = 128; o; o >>= 1) { if (t < o) red[t] += red[t + o]; __syncthreads(); }
    if (t == 0) {
        float var = red[0] / F_DIM - s_mean * s_mean;
        s_rstd = rsqrtf(var + 1e-5f);
    }
    __syncthreads();
    for (int i = t; i < F_DIM; i += 256) {
        float tv = (row[i] - s_mean) * s_rstd * gg[i] + bb[i];
        row[i] = 0.5f * tv * (1.f + erff(tv * 0.70710678118654752f));
    }
}

// ---------------- host launcher ---------------------------------------------
extern "C" void kernel_launch(void* const* d_in, const int* in_sizes, int n_in,
                              void* d_out, int out_size)
{
    (void)in_sizes; (void)n_in; (void)out_size;
    const float* src        = (const float*)d_in[0];
    const float* q_w        = (const float*)d_in[1];
    const float* k_w        = (const float*)d_in[2];
    const float* v_w        = (const float*)d_in[3];
    const float* out_w      = (const float*)d_in[4];
    const float* gate_w     = (const float*)d_in[5];
    const float* gate_b     = (const float*)d_in[6];
    const float* scale_w    = (const float*)d_in[7];
    const float* n1_g       = (const float*)d_in[8];
    const float* n1_b       = (const float*)d_in[9];
    const float* n2_g       = (const float*)d_in[10];
    const float* n2_b       = (const float*)d_in[11];
    const float* moe_gate_w = (const float*)d_in[12];
    const float* moe_gate_b = (const float*)d_in[13];
    const float* w1         = (const float*)d_in[14];
    const float* b1         = (const float*)d_in[15];
    const float* ln_g       = (const float*)d_in[16];
    const float* ln_b       = (const float*)d_in[17];
    const float* w2         = (const float*)d_in[18];
    const float* b2         = (const float*)d_in[19];
    const float* res_scale  = (const float*)d_in[20];

    float *attnp, *xb, *hhb, *moeb;
    cudaGetSymbolAddress((void**)&attnp, g_attnp);
    cudaGetSymbolAddress((void**)&xb, g_x);
    cudaGetSymbolAddress((void**)&hhb, g_hh);
    cudaGetSymbolAddress((void**)&moeb, g_moe);

    unsigned short *acth, *actl, *wth, *wtl, *w1h, *w1l, *w2h, *w2l;
    unsigned short *qh, *ql, *kh, *kl, *vh, *vl, *ah, *al, *gh, *gl;
    cudaGetSymbolAddress((void**)&acth, g_act_h);
    cudaGetSymbolAddress((void**)&actl, g_act_l);
    cudaGetSymbolAddress((void**)&wth, g_wt_h);
    cudaGetSymbolAddress((void**)&wtl, g_wt_l);
    cudaGetSymbolAddress((void**)&w1h, g_w1_h);
    cudaGetSymbolAddress((void**)&w1l, g_w1_l);
    cudaGetSymbolAddress((void**)&w2h, g_w2_h);
    cudaGetSymbolAddress((void**)&w2l, g_w2_l);
    cudaGetSymbolAddress((void**)&qh, g_qh);  cudaGetSymbolAddress((void**)&ql, g_ql);
    cudaGetSymbolAddress((void**)&kh, g_kh);  cudaGetSymbolAddress((void**)&kl, g_kl);
    cudaGetSymbolAddress((void**)&vh, g_vh);  cudaGetSymbolAddress((void**)&vl, g_vl);
    cudaGetSymbolAddress((void**)&ah, g_ah);  cudaGetSymbolAddress((void**)&al, g_al);
    cudaGetSymbolAddress((void**)&gh, g_gh);  cudaGetSymbolAddress((void**)&gl, g_gl);

    cudaFuncSetAttribute(attn_mma, cudaFuncAttributeMaxDynamicSharedMemorySize, ATTN_SMEM);
    cudaFuncSetAttribute(gemm_mma_dense, cudaFuncAttributeMaxDynamicSharedMemorySize, MMA_SMEM);
    cudaFuncSetAttribute(gemm_mma_e1, cudaFuncAttributeMaxDynamicSharedMemorySize, MMA_SMEM);
    cudaFuncSetAttribute(gemm_mma_e2, cudaFuncAttributeMaxDynamicSharedMemorySize, MMA_SMEM);

    const size_t WSZ = (size_t)D_DIM * D_DIM;
    const int WN4 = (int)(WSZ / 4);

    // streaming weight splits
    cvt_kernel<<<CVT_GRID(WN4), 256>>>(q_w,    wth + 0 * WSZ, wtl + 0 * WSZ, WN4);
    cvt_kernel<<<CVT_GRID(WN4), 256>>>(k_w,    wth + 1 * WSZ, wtl + 1 * WSZ, WN4);
    cvt_kernel<<<CVT_GRID(WN4), 256>>>(v_w,    wth + 2 * WSZ, wtl + 2 * WSZ, WN4);
    cvt_kernel<<<CVT_GRID(WN4), 256>>>(out_w,  wth + 3 * WSZ, wtl + 3 * WSZ, WN4);
    cvt_kernel<<<CVT_GRID(WN4), 256>>>(gate_w, wth + 4 * WSZ, wtl + 4 * WSZ, WN4);
    {
        const int n4 = N_EXP * D_DIM * F_DIM / 4;
        cvt_kernel<<<CVT_GRID(n4), 256>>>(w1, w1h, w1l, n4);
        cvt_kernel<<<CVT_GRID(n4), 256>>>(w2, w2h, w2l, n4);
    }

    reset_kernel<<<1, 32>>>();

    // src split, then QKV (batched z=3, epilogue writes bf16 hi/lo)
    cvt_kernel<<<CVT_GRID(N_TOK * D_DIM / 4), 256>>>(src, acth, actl, N_TOK * D_DIM / 4);
    {
        DenseArgs da = {};
        for (int z = 0; z < 3; ++z) {
            da.Bh[z] = wth + (size_t)z * WSZ;
            da.Bl[z] = wtl + (size_t)z * WSZ;
            da.mode[z] = 2;
        }
        da.Ch[0] = qh; da.Cl[0] = ql;
        da.Ch[1] = kh; da.Cl[1] = kl;
        da.Ch[2] = vh; da.Cl[2] = vl;
        gemm_mma_dense<<<dim3(8, 16, 3), 256, MMA_SMEM>>>(acth, actl, da, D_DIM, D_DIM);
    }

    attn_mma<<<dim3(8, 32), 256, ATTN_SMEM>>>(qh, ql, kh, kl, vh, vl, scale_w, ah, al);

    {
        DenseArgs da = {};
        da.Bh[0] = wth + 4 * WSZ; da.Bl[0] = wtl + 4 * WSZ;
        da.bias[0] = gate_b;
        da.auxh[0] = ah; da.auxl[0] = al;
        da.Ch[0] = gh; da.Cl[0] = gl;
        da.mode[0] = 1;
        gemm_mma_dense<<<dim3(8, 16, 1), 256, MMA_SMEM>>>(ah, al, da, D_DIM, D_DIM);
    }

    {
        DenseArgs da = {};
        da.Bh[0] = wth + 3 * WSZ; da.Bl[0] = wtl + 3 * WSZ;
        da.C[0] = attnp;
        da.mode[0] = 0;
        gemm_mma_dense<<<dim3(8, 16, 1), 256, MMA_SMEM>>>(gh, gl, da, D_DIM, D_DIM);
    }

    ln2_kernel<<<N_TOK, 256>>>(src, attnp, n1_g, n1_b, xb, D_DIM);

    moe_gate_kernel<<<N_TOK, 256>>>(xb, moe_gate_w, moe_gate_b);
    scan_kernel<<<1, 32>>>();
    scatter_kernel<<<N_TOK / 256, 256>>>();

    cvt_kernel<<<CVT_GRID(N_TOK * D_DIM / 4), 256>>>(xb, acth, actl, N_TOK * D_DIM / 4);
    gemm_mma_e1<<<dim3(F_DIM / 128, N_TOK / 128, N_EXP), 256, MMA_SMEM>>>(
        acth, actl, w1h, w1l, b1, hhb);
    ln_gelu_kernel<<<N_TOK, 256>>>(hhb, ln_g, ln_b);
    cvt_kernel<<<CVT_GRID(N_TOK * F_DIM / 4), 256>>>(hhb, acth, actl, N_TOK * F_DIM / 4);
    gemm_mma_e2<<<dim3(D_DIM / 128, N_TOK / 128, N_EXP), 256, MMA_SMEM>>>(
        acth, actl, w2h, w2l, b2, res_scale, xb, moeb);

    ln2_kernel<<<N_TOK, 256>>>(xb, moeb, n2_g, n2_b, (float*)d_out, D_DIM);
}

// round 10
// speedup vs baseline: 2.0706x; 1.0122x over previous
#include <cuda_runtime.h>
#include <cuda_bf16.h>
#include <math.h>
#include <stdint.h>

#define N_TOK 2048
#define D_DIM 1024
#define F_DIM 2048
#define N_EXP 8
#define N_HEAD 16
#define S_LEN 1024

// ---------------- fp32 scratch ----------------------------------------------
__device__ float g_attnp[N_TOK * D_DIM];
__device__ float g_x[N_TOK * D_DIM];
__device__ float g_hh[N_TOK * F_DIM];
__device__ float g_moe[N_TOK * D_DIM];
__device__ int   g_chosen[N_TOK];
__device__ int   g_counts[N_EXP];
__device__ int   g_offsets[N_EXP];
__device__ int   g_cursor[N_EXP];
__device__ int   g_p2t[N_TOK];
__device__ int   g_p2e[N_TOK];

// ---------------- bf16 split scratch (ushort) --------------------------------
__device__ unsigned short g_act_h[N_TOK * F_DIM];
__device__ unsigned short g_act_l[N_TOK * F_DIM];
__device__ unsigned short g_qh[N_TOK * D_DIM];
__device__ unsigned short g_ql[N_TOK * D_DIM];
__device__ unsigned short g_kh[N_TOK * D_DIM];
__device__ unsigned short g_kl[N_TOK * D_DIM];
__device__ unsigned short g_vh[N_TOK * D_DIM];
__device__ unsigned short g_vl[N_TOK * D_DIM];
__device__ unsigned short g_ah[N_TOK * D_DIM];
__device__ unsigned short g_al[N_TOK * D_DIM];
__device__ unsigned short g_gh[N_TOK * D_DIM];
__device__ unsigned short g_gl[N_TOK * D_DIM];
__device__ unsigned short g_wt_h[5 * D_DIM * D_DIM];
__device__ unsigned short g_wt_l[5 * D_DIM * D_DIM];
__device__ unsigned short g_w1_h[N_EXP * D_DIM * F_DIM];
__device__ unsigned short g_w1_l[N_EXP * D_DIM * F_DIM];
__device__ unsigned short g_w2_h[N_EXP * F_DIM * D_DIM];
__device__ unsigned short g_w2_l[N_EXP * F_DIM * D_DIM];

// ================= helpers ====================================================
__device__ __forceinline__ uint32_t smem_u32(const void* p) {
    uint32_t a;
    asm("{ .reg .u64 t; cvta.to.shared.u64 t, %1; cvt.u32.u64 %0, t; }" : "=r"(a) : "l"(p));
    return a;
}
#define CP_ASYNC16(dst, src) \
    asm volatile("cp.async.cg.shared.global [%0], [%1], 16;" :: "r"(dst), "l"(src))
#define CP_COMMIT() asm volatile("cp.async.commit_group;" ::: "memory")
#define CP_WAIT0()  asm volatile("cp.async.wait_group 0;" ::: "memory")
#define CP_WAIT1()  asm volatile("cp.async.wait_group 1;" ::: "memory")

__device__ __forceinline__ void ldsm4(uint32_t* r, uint32_t addr) {
    asm volatile("ldmatrix.sync.aligned.m8n8.x4.shared.b16 {%0,%1,%2,%3}, [%4];"
        : "=r"(r[0]), "=r"(r[1]), "=r"(r[2]), "=r"(r[3]) : "r"(addr));
}
__device__ __forceinline__ void ldsm4t(uint32_t* r, uint32_t addr) {
    asm volatile("ldmatrix.sync.aligned.m8n8.x4.trans.shared.b16 {%0,%1,%2,%3}, [%4];"
        : "=r"(r[0]), "=r"(r[1]), "=r"(r[2]), "=r"(r[3]) : "r"(addr));
}
__device__ __forceinline__ void mma16816(float* c, const uint32_t* a, uint32_t b0, uint32_t b1) {
    asm volatile("mma.sync.aligned.m16n8k16.row.col.f32.bf16.bf16.f32 "
        "{%0,%1,%2,%3}, {%4,%5,%6,%7}, {%8,%9}, {%0,%1,%2,%3};"
        : "+f"(c[0]), "+f"(c[1]), "+f"(c[2]), "+f"(c[3])
        : "r"(a[0]), "r"(a[1]), "r"(a[2]), "r"(a[3]), "r"(b0), "r"(b1));
}
__device__ __forceinline__ uint32_t packbf(float lo, float hi) {
    uint32_t r;
    asm("cvt.rn.bf16x2.f32 %0, %1, %2;" : "=r"(r) : "f"(hi), "f"(lo));
    return r;
}
__device__ __forceinline__ float bfu(unsigned short u) {
    return __uint_as_float(((uint32_t)u) << 16);
}
__device__ __forceinline__ void split1(float v, unsigned short& h, unsigned short& l) {
    __nv_bfloat16 hb = __float2bfloat16(v);
    float r = v - __bfloat162float(hb);
    __nv_bfloat16 lb = __float2bfloat16(r);
    h = *(unsigned short*)&hb;
    l = *(unsigned short*)&lb;
}
// split two floats -> packed hi u32 and lo u32
__device__ __forceinline__ uint32_t split2(float a, float b, uint32_t& lo2) {
    unsigned short ha, la, hb, lb;
    split1(a, ha, la);
    split1(b, hb, lb);
    lo2 = (uint32_t)la | ((uint32_t)lb << 16);
    return (uint32_t)ha | ((uint32_t)hb << 16);
}

// ================= GEMM: 128x128 tile, split-bf16, B in natural [K,N] ========
#define A_OFF_H 0
#define A_OFF_L 10240
#define B_OFF_H 20480
#define B_OFF_L 29184
#define STAGE_BYTES 37888
#define MMA_SMEM (2 * STAGE_BYTES)

template <class AROW, class EPI>
__device__ __forceinline__ void mma_body(const unsigned short* __restrict__ Ah,
                                         const unsigned short* __restrict__ Al,
                                         const unsigned short* __restrict__ Bh,
                                         const unsigned short* __restrict__ Bl,
                                         int K, int N, int col0, AROW arow, EPI epi)
{
    extern __shared__ char smem[];
    const uint32_t sb = smem_u32(smem);
    const int t = threadIdx.x;
    const int lane = t & 31, warp = t >> 5;
    const int warpM = warp >> 2, warpN = warp & 3;

    const int lrow = t >> 1, aseg = (t & 1) * 2;
    const int aRow = arow(lrow);
    const unsigned short* srcAh = Ah + (size_t)aRow * K + aseg * 8;
    const unsigned short* srcAl = Al + (size_t)aRow * K + aseg * 8;
    const uint32_t adst = lrow * 80 + aseg * 16;
    const int brow = t >> 3, bcol = (t & 7) * 16;
    const unsigned short* srcBh = Bh + (size_t)brow * N + col0 + bcol;
    const unsigned short* srcBl = Bl + (size_t)brow * N + col0 + bcol;
    const uint32_t bdst = brow * 272 + bcol * 2;

    auto issue_stage = [&](int k0, int buf) {
        const uint32_t s = sb + buf * STAGE_BYTES;
        CP_ASYNC16(s + A_OFF_H + adst,      srcAh + k0);
        CP_ASYNC16(s + A_OFF_H + adst + 16, srcAh + k0 + 8);
        CP_ASYNC16(s + A_OFF_L + adst,      srcAl + k0);
        CP_ASYNC16(s + A_OFF_L + adst + 16, srcAl + k0 + 8);
        const size_t bko = (size_t)k0 * N;
        CP_ASYNC16(s + B_OFF_H + bdst,      srcBh + bko);
        CP_ASYNC16(s + B_OFF_H + bdst + 16, srcBh + bko + 8);
        CP_ASYNC16(s + B_OFF_L + bdst,      srcBl + bko);
        CP_ASYNC16(s + B_OFF_L + bdst + 16, srcBl + bko + 8);
        CP_COMMIT();
    };

    const int mrow_l = (lane & 7) + ((lane >> 3) & 1) * 8;
    const int kcol_l = ((lane >> 4) & 1) * 8;

    float acc[4][4][4] = {};

    issue_stage(0, 0);
    const int NS = K >> 5;
    int buf = 0;
    for (int s = 0; s < NS; ++s) {
        CP_WAIT0();
        __syncthreads();
        if (s + 1 < NS) issue_stage((s + 1) * 32, buf ^ 1);

        const uint32_t sbase = sb + buf * STAGE_BYTES;
#pragma unroll
        for (int ks = 0; ks < 2; ++ks) {
            const int kb = ks * 16;
            uint32_t ah[4][4], al[4][4], bh4[2][4], bl4[2][4];
#pragma unroll
            for (int mi = 0; mi < 4; ++mi) {
                const uint32_t ro = (uint32_t)(warpM * 64 + mi * 16 + mrow_l) * 80 + (kb + kcol_l) * 2;
                ldsm4(ah[mi], sbase + A_OFF_H + ro);
                ldsm4(al[mi], sbase + A_OFF_L + ro);
            }
#pragma unroll
            for (int g = 0; g < 2; ++g) {
                const uint32_t ro = (uint32_t)(kb + (lane & 7) + ((lane >> 4) & 1) * 8) * 272
                                  + (uint32_t)(warpN * 32 + g * 16 + ((lane >> 3) & 1) * 8) * 2;
                ldsm4t(bh4[g], sbase + B_OFF_H + ro);
                ldsm4t(bl4[g], sbase + B_OFF_L + ro);
            }
#pragma unroll
            for (int mi = 0; mi < 4; ++mi)
#pragma unroll
                for (int nj = 0; nj < 4; ++nj) {
                    const int g = nj >> 1, hi = nj & 1;
                    mma16816(acc[mi][nj], ah[mi], bh4[g][hi], bh4[g][hi + 2]);
                    mma16816(acc[mi][nj], ah[mi], bl4[g][hi], bl4[g][hi + 2]);
                    mma16816(acc[mi][nj], al[mi], bh4[g][hi], bh4[g][hi + 2]);
                }
        }
        __syncthreads();
        buf ^= 1;
    }

#pragma unroll
    for (int mi = 0; mi < 4; ++mi)
#pragma unroll
        for (int nj = 0; nj < 4; ++nj) {
            const int r0 = warpM * 64 + mi * 16 + (lane >> 2);
            const int c  = warpN * 32 + nj * 8 + (lane & 3) * 2;
            epi(r0,     c, acc[mi][nj][0], acc[mi][nj][1]);
            epi(r0 + 8, c, acc[mi][nj][2], acc[mi][nj][3]);
        }
}

// ---------------- dense GEMM (batched up to 3 via z) -------------------------
struct DenseArgs {
    const unsigned short* Bh[3];
    const unsigned short* Bl[3];
    const float* bias[3];
    const unsigned short* auxh[3];
    const unsigned short* auxl[3];
    float* C[3];
    unsigned short* Ch[3];
    unsigned short* Cl[3];
    int mode[3];
};
__global__ __launch_bounds__(256, 2)
void gemm_mma_dense(const unsigned short* __restrict__ Ah, const unsigned short* __restrict__ Al,
                    DenseArgs da, int N, int K)
{
    const int z = blockIdx.z;
    const int row0 = blockIdx.y * 128, col0 = blockIdx.x * 128;
    const unsigned short* Bh = da.Bh[z];
    const unsigned short* Bl = da.Bl[z];
    const float* bias = da.bias[z];
    const unsigned short* auxh = da.auxh[z];
    const unsigned short* auxl = da.auxl[z];
    float* C = da.C[z];
    unsigned short* Ch = da.Ch[z];
    unsigned short* Cl = da.Cl[z];
    const int mode = da.mode[z];
    auto arow = [&](int r) { return row0 + r; };
    auto epi = [&](int m, int c, float v0, float v1) {
        const int gc = col0 + c;
        const size_t base = (size_t)(row0 + m) * N + gc;
        if (mode == 0) {
            if (bias) { v0 += bias[gc]; v1 += bias[gc + 1]; }
            *(float2*)&C[base] = make_float2(v0, v1);
        } else if (mode == 1) {
            v0 += bias[gc]; v1 += bias[gc + 1];
            float a0 = bfu(auxh[base]) + bfu(auxl[base]);
            float a1 = bfu(auxh[base + 1]) + bfu(auxl[base + 1]);
            v0 = a0 / (1.f + __expf(-v0));
            v1 = a1 / (1.f + __expf(-v1));
            uint32_t lo2, hi2 = split2(v0, v1, lo2);
            *(uint32_t*)&Ch[base] = hi2;
            *(uint32_t*)&Cl[base] = lo2;
        } else {
            uint32_t lo2, hi2 = split2(v0, v1, lo2);
            *(uint32_t*)&Ch[base] = hi2;
            *(uint32_t*)&Cl[base] = lo2;
        }
    };
    mma_body(Ah, Al, Bh, Bl, K, N, col0, arow, epi);
}

// ---------------- expert GEMM 1: hh = x @ w1[e] + b1 -------------------------
__global__ __launch_bounds__(256, 2)
void gemm_mma_e1(const unsigned short* __restrict__ xh, const unsigned short* __restrict__ xl,
                 const unsigned short* __restrict__ w1h, const unsigned short* __restrict__ w1l,
                 const float* __restrict__ b1, float* __restrict__ hh)
{
    const int e = blockIdx.z;
    const int cnt = g_counts[e];
    const int rt = blockIdx.y * 128;
    if (rt >= cnt) return;
    const int off = g_offsets[e];
    const int col0 = blockIdx.x * 128;
    const unsigned short* Bh = w1h + (size_t)e * D_DIM * F_DIM;
    const unsigned short* Bl = w1l + (size_t)e * D_DIM * F_DIM;
    const float* b1e = b1 + (size_t)e * F_DIM;
    auto arow = [&](int r) {
        int rr = rt + r; if (rr >= cnt) rr = cnt - 1;
        return g_p2t[off + rr];
    };
    auto epi = [&](int m, int c, float v0, float v1) {
        if (rt + m >= cnt) return;
        const int gc = col0 + c;
        const size_t base = (size_t)(off + rt + m) * F_DIM + gc;
        *(float2*)&hh[base] = make_float2(v0 + b1e[gc], v1 + b1e[gc + 1]);
    };
    mma_body(xh, xl, Bh, Bl, D_DIM, F_DIM, col0, arow, epi);
}

// ---------------- expert GEMM 2 + residual scatter ---------------------------
__global__ __launch_bounds__(256, 2)
void gemm_mma_e2(const unsigned short* __restrict__ hhh, const unsigned short* __restrict__ hhl,
                 const unsigned short* __restrict__ w2h, const unsigned short* __restrict__ w2l,
                 const float* __restrict__ b2, const float* __restrict__ res_scale,
                 const float* __restrict__ x, float* __restrict__ moe)
{
    const int e = blockIdx.z;
    const int cnt = g_counts[e];
    const int rt = blockIdx.y * 128;
    if (rt >= cnt) return;
    const int off = g_offsets[e];
    const int col0 = blockIdx.x * 128;
    const unsigned short* Bh = w2h + (size_t)e * F_DIM * D_DIM;
    const unsigned short* Bl = w2l + (size_t)e * F_DIM * D_DIM;
    const float* b2e = b2 + (size_t)e * D_DIM;
    const float rsc = res_scale[e];
    auto arow = [&](int r) {
        int rr = rt + r; if (rr >= cnt) rr = cnt - 1;
        return off + rr;
    };
    auto epi = [&](int m, int c, float v0, float v1) {
        if (rt + m >= cnt) return;
        const int tok = g_p2t[off + rt + m];
        const int gc = col0 + c;
        const size_t base = (size_t)tok * D_DIM + gc;
        float2 xr = *(const float2*)&x[base];
        *(float2*)&moe[base] = make_float2((v0 + b2e[gc]) * rsc + xr.x,
                                           (v1 + b2e[gc + 1]) * rsc + xr.y);
    };
    mma_body(hhh, hhl, Bh, Bl, F_DIM, D_DIM, col0, arow, epi);
}

// ================= bf16 MMA flash attention ==================================
#define AQH 0
#define AQL 18432
#define AKH(b) (36864 + (b) * 18432)
#define AKL(b) (46080 + (b) * 18432)
#define AVH(b) (73728 + (b) * 18432)
#define AVL(b) (82944 + (b) * 18432)
#define AQSC 110592
#define ATTN_SMEM (110592 + 512)

__global__ __launch_bounds__(256, 1)
void attn_mma(const unsigned short* __restrict__ qh, const unsigned short* __restrict__ ql,
              const unsigned short* __restrict__ kh, const unsigned short* __restrict__ kl,
              const unsigned short* __restrict__ vh, const unsigned short* __restrict__ vl,
              const float* __restrict__ scale_w,
              unsigned short* __restrict__ oh_, unsigned short* __restrict__ ol_)
{
    extern __shared__ char smem[];
    const uint32_t sb = smem_u32(smem);
    float* qsc = (float*)(smem + AQSC);
    const int t = threadIdx.x, lane = t & 31, warp = t >> 5;
    const int h = blockIdx.y & 15, b = blockIdx.y >> 4;
    const int qtok0 = b * S_LEN + blockIdx.x * 128;
    const size_t headoff = (size_t)h * 64;

    {
        const int row = t >> 1, half = t & 1;
        const size_t so = (size_t)(qtok0 + row) * D_DIM + headoff + half * 32;
        const uint32_t dq = (uint32_t)(row * 144 + half * 64);
#pragma unroll
        for (int i = 0; i < 4; ++i) {
            CP_ASYNC16(sb + AQH + dq + i * 16, qh + so + i * 8);
            CP_ASYNC16(sb + AQL + dq + i * 16, ql + so + i * 8);
        }
        CP_COMMIT();
    }
    auto issueKV = [&](int c, int buf) {
        const int row = t >> 2, q2 = t & 3;
        const size_t so = (size_t)(b * S_LEN + c * 64 + row) * D_DIM + headoff + q2 * 16;
        const uint32_t d = (uint32_t)(row * 144 + q2 * 32);
        CP_ASYNC16(sb + AKH(buf) + d,      kh + so);
        CP_ASYNC16(sb + AKH(buf) + d + 16, kh + so + 8);
        CP_ASYNC16(sb + AKL(buf) + d,      kl + so);
        CP_ASYNC16(sb + AKL(buf) + d + 16, kl + so + 8);
        CP_ASYNC16(sb + AVH(buf) + d,      vh + so);
        CP_ASYNC16(sb + AVH(buf) + d + 16, vh + so + 8);
        CP_ASYNC16(sb + AVL(buf) + d,      vl + so);
        CP_ASYNC16(sb + AVL(buf) + d + 16, vl + so + 8);
        CP_COMMIT();
    };
    issueKV(0, 0);
    CP_WAIT1();
    __syncthreads();

    if (t < 128) {
        float s = 0.f;
        const char* qrow = smem + AQH + t * 144;
        const char* qrowl = smem + AQL + t * 144;
        for (int d = 0; d < 64; ++d) {
            float qv = bfu(((const unsigned short*)qrow)[d]) + bfu(((const unsigned short*)qrowl)[d]);
            s += qv * __ldg(&scale_w[h * 64 + d]);
        }
        qsc[t] = 0.25f / (1.f + __expf(-s));
    }

    const int mrow_l = (lane & 7) + ((lane >> 3) & 1) * 8;
    const int kcol_l = ((lane >> 4) & 1) * 8;
    const int r0loc = warp * 16 + (lane >> 2);

    float s[8][4];
    float o[8][4] = {};
    float m0 = -1e30f, m1 = -1e30f, l0 = 0.f, l1 = 0.f;

    for (int c = 0; c < 16; ++c) {
        CP_WAIT0();
        __syncthreads();
        if (c < 15) issueKV(c + 1, (c + 1) & 1);
        const uint32_t kbh = sb + AKH(c & 1), kbl = sb + AKL(c & 1);
        const uint32_t vbh = sb + AVH(c & 1), vbl = sb + AVL(c & 1);

#pragma unroll
        for (int j = 0; j < 8; ++j) { s[j][0] = s[j][1] = s[j][2] = s[j][3] = 0.f; }
#pragma unroll
        for (int ks = 0; ks < 4; ++ks) {
            uint32_t ah[4], al[4];
            const uint32_t ao = (uint32_t)(warp * 16 + mrow_l) * 144 + (ks * 16 + kcol_l) * 2;
            ldsm4(ah, sb + AQH + ao);
            ldsm4(al, sb + AQL + ao);
#pragma unroll
            for (int g = 0; g < 4; ++g) {
                const uint32_t ro = (uint32_t)(g * 16 + mrow_l) * 144 + (ks * 16 + kcol_l) * 2;
                uint32_t bh4[4], bl4[4];
                ldsm4(bh4, kbh + ro);
                ldsm4(bl4, kbl + ro);
                mma16816(s[2 * g],     ah, bh4[0], bh4[2]);
                mma16816(s[2 * g],     ah, bl4[0], bl4[2]);
                mma16816(s[2 * g],     al, bh4[0], bh4[2]);
                mma16816(s[2 * g + 1], ah, bh4[1], bh4[3]);
                mma16816(s[2 * g + 1], ah, bl4[1], bl4[3]);
                mma16816(s[2 * g + 1], al, bh4[1], bh4[3]);
            }
        }
        const float f0 = qsc[r0loc], f1 = qsc[r0loc + 8];
#pragma unroll
        for (int j = 0; j < 8; ++j) { s[j][0] *= f0; s[j][1] *= f0; s[j][2] *= f1; s[j][3] *= f1; }
        float rm0 = -1e30f, rm1 = -1e30f;
#pragma unroll
        for (int j = 0; j < 8; ++j) {
            rm0 = fmaxf(rm0, fmaxf(s[j][0], s[j][1]));
            rm1 = fmaxf(rm1, fmaxf(s[j][2], s[j][3]));
        }
        rm0 = fmaxf(rm0, __shfl_xor_sync(0xffffffffu, rm0, 1));
        rm0 = fmaxf(rm0, __shfl_xor_sync(0xffffffffu, rm0, 2));
        rm1 = fmaxf(rm1, __shfl_xor_sync(0xffffffffu, rm1, 1));
        rm1 = fmaxf(rm1, __shfl_xor_sync(0xffffffffu, rm1, 2));
        const float nm0 = fmaxf(m0, rm0), nm1 = fmaxf(m1, rm1);
        const float e0 = __expf(m0 - nm0), e1v = __expf(m1 - nm1);
        float sum0 = 0.f, sum1 = 0.f;
#pragma unroll
        for (int j = 0; j < 8; ++j) {
            s[j][0] = __expf(s[j][0] - nm0); sum0 += s[j][0];
            s[j][1] = __expf(s[j][1] - nm0); sum0 += s[j][1];
            s[j][2] = __expf(s[j][2] - nm1); sum1 += s[j][2];
            s[j][3] = __expf(s[j][3] - nm1); sum1 += s[j][3];
        }
        sum0 += __shfl_xor_sync(0xffffffffu, sum0, 1);
        sum0 += __shfl_xor_sync(0xffffffffu, sum0, 2);
        sum1 += __shfl_xor_sync(0xffffffffu, sum1, 1);
        sum1 += __shfl_xor_sync(0xffffffffu, sum1, 2);
        l0 = l0 * e0 + sum0;
        l1 = l1 * e1v + sum1;
        m0 = nm0; m1 = nm1;
#pragma unroll
        for (int j = 0; j < 8; ++j) { o[j][0] *= e0; o[j][1] *= e0; o[j][2] *= e1v; o[j][3] *= e1v; }

#pragma unroll
        for (int kk = 0; kk < 4; ++kk) {
            uint32_t ph[4], pl[4];
            ph[0] = packbf(s[2 * kk][0],     s[2 * kk][1]);
            ph[1] = packbf(s[2 * kk][2],     s[2 * kk][3]);
            ph[2] = packbf(s[2 * kk + 1][0], s[2 * kk + 1][1]);
            ph[3] = packbf(s[2 * kk + 1][2], s[2 * kk + 1][3]);
#pragma unroll
            for (int q = 0; q < 4; ++q) {
                const int tj = 2 * kk + (q >> 1);
                const int c0i = (q & 1) * 2;
                const float h0 = __uint_as_float(ph[q] << 16);
                const float h1 = __uint_as_float(ph[q] & 0xffff0000u);
                pl[q] = packbf(s[tj][c0i] - h0, s[tj][c0i + 1] - h1);
            }
#pragma unroll
            for (int g = 0; g < 4; ++g) {
                const uint32_t ro = (uint32_t)(kk * 16 + (lane & 7) + ((lane >> 4) & 1) * 8) * 144
                                  + (uint32_t)(g * 16 + ((lane >> 3) & 1) * 8) * 2;
                uint32_t vh4[4], vl4[4];
                ldsm4t(vh4, vbh + ro);
                ldsm4t(vl4, vbl + ro);
                mma16816(o[2 * g],     ph, vh4[0], vh4[2]);
                mma16816(o[2 * g],     ph, vl4[0], vl4[2]);
                mma16816(o[2 * g],     pl, vh4[0], vh4[2]);
                mma16816(o[2 * g + 1], ph, vh4[1], vh4[3]);
                mma16816(o[2 * g + 1], ph, vl4[1], vl4[3]);
                mma16816(o[2 * g + 1], pl, vh4[1], vh4[3]);
            }
        }
    }

    const float inv0 = 1.f / l0, inv1 = 1.f / l1;
    const int tok0 = qtok0 + r0loc, tok1 = tok0 + 8;
#pragma unroll
    for (int j = 0; j < 8; ++j) {
        const size_t col = headoff + j * 8 + (lane & 3) * 2;
        uint32_t lo2, hi2;
        hi2 = split2(o[j][0] * inv0, o[j][1] * inv0, lo2);
        *(uint32_t*)&oh_[(size_t)tok0 * D_DIM + col] = hi2;
        *(uint32_t*)&ol_[(size_t)tok0 * D_DIM + col] = lo2;
        hi2 = split2(o[j][2] * inv1, o[j][3] * inv1, lo2);
        *(uint32_t*)&oh_[(size_t)tok1 * D_DIM + col] = hi2;
        *(uint32_t*)&ol_[(size_t)tok1 * D_DIM + col] = lo2;
    }
}

// ---------------- wide streaming fp32 -> hi/lo bf16 split --------------------
// processes groups of 8 floats; each thread: 2x LDG.128 -> 1x STG.128 hi + lo.
// n8 = element_count / 8 (all call sites are multiples of 8).
__global__ void cvt8_kernel(const float* __restrict__ x, unsigned short* __restrict__ h,
                            unsigned short* __restrict__ l, int n8)
{
    const int base = blockIdx.x * 1024 + threadIdx.x;
    float4 va[4], vb[4];
#pragma unroll
    for (int j = 0; j < 4; ++j) {
        const int i = base + j * 256;
        if (i < n8) {
            va[j] = ((const float4*)x)[2 * i];
            vb[j] = ((const float4*)x)[2 * i + 1];
        }
    }
#pragma unroll
    for (int j = 0; j < 4; ++j) {
        const int i = base + j * 256;
        if (i >= n8) continue;
        uint4 hv, lv;
        hv.x = split2(va[j].x, va[j].y, lv.x);
        hv.y = split2(va[j].z, va[j].w, lv.y);
        hv.z = split2(vb[j].x, vb[j].y, lv.z);
        hv.w = split2(vb[j].z, vb[j].w, lv.w);
        ((uint4*)h)[i] = hv;
        ((uint4*)l)[i] = lv;
    }
}
#define CVT8_GRID(n8) (((n8) + 1023) / 1024)

// batched variant for the 5 dense weight matrices (same size each)
struct Cvt5Args { const float* src[5]; };
__global__ void cvt8x5_kernel(Cvt5Args ca, unsigned short* __restrict__ h,
                              unsigned short* __restrict__ l, int n8)
{
    const float* x = ca.src[blockIdx.y];
    unsigned short* hz = h + (size_t)blockIdx.y * n8 * 8;
    unsigned short* lz = l + (size_t)blockIdx.y * n8 * 8;
    const int base = blockIdx.x * 1024 + threadIdx.x;
    float4 va[4], vb[4];
#pragma unroll
    for (int j = 0; j < 4; ++j) {
        const int i = base + j * 256;
        if (i < n8) {
            va[j] = ((const float4*)x)[2 * i];
            vb[j] = ((const float4*)x)[2 * i + 1];
        }
    }
#pragma unroll
    for (int j = 0; j < 4; ++j) {
        const int i = base + j * 256;
        if (i >= n8) continue;
        uint4 hv, lv;
        hv.x = split2(va[j].x, va[j].y, lv.x);
        hv.y = split2(va[j].z, va[j].w, lv.y);
        hv.z = split2(vb[j].x, vb[j].y, lv.z);
        hv.w = split2(vb[j].z, vb[j].w, lv.w);
        ((uint4*)hz)[i] = hv;
        ((uint4*)lz)[i] = lv;
    }
}

// ---------------- layernorm over residual sum (optional split out) -----------
__global__ void ln2_kernel(const float* __restrict__ a, const float* __restrict__ b,
                           const float* __restrict__ g, const float* __restrict__ be,
                           float* __restrict__ out,
                           unsigned short* __restrict__ oh, unsigned short* __restrict__ ol,
                           int D)
{
    const int row = blockIdx.x, t = threadIdx.x;
    __shared__ float red[256];
    __shared__ float s_mean, s_rstd;
    float s1 = 0.f, s2 = 0.f;
    for (int i = t; i < D; i += 256) {
        float v = a[(size_t)row * D + i] + b[(size_t)row * D + i];
        s1 += v; s2 += v * v;
    }
    red[t] = s1; __syncthreads();
    for (int o = 128; o; o >>= 1) { if (t < o) red[t] += red[t + o]; __syncthreads(); }
    if (t == 0) s_mean = red[0] / D;
    __syncthreads();
    red[t] = s2; __syncthreads();
    for (int o = 128; o; o >>= 1) { if (t < o) red[t] += red[t + o]; __syncthreads(); }
    if (t == 0) {
        float var = red[0] / D - s_mean * s_mean;
        s_rstd = rsqrtf(var + 1e-5f);
    }
    __syncthreads();
    for (int i = t; i < D; i += 256) {
        float v = a[(size_t)row * D + i] + b[(size_t)row * D + i];
        float r = (v - s_mean) * s_rstd * g[i] + be[i];
        out[(size_t)row * D + i] = r;
        if (oh) {
            unsigned short hh_, ll_;
            split1(r, hh_, ll_);
            oh[(size_t)row * D + i] = hh_;
            ol[(size_t)row * D + i] = ll_;
        }
    }
}

// ---------------- MoE routing ------------------------------------------------
__global__ void reset_kernel() { if (threadIdx.x < N_EXP) g_counts[threadIdx.x] = 0; }

__global__ void moe_gate_kernel(const float* __restrict__ x, const float* __restrict__ W,
                                const float* __restrict__ bias)
{
    const int n = blockIdx.x, t = threadIdx.x;
    const int e = t >> 5, lane = t & 31;
    float acc = 0.f;
    for (int d = lane; d < D_DIM; d += 32) acc += x[(size_t)n * D_DIM + d] * W[d * N_EXP + e];
    for (int o = 16; o; o >>= 1) acc += __shfl_down_sync(0xffffffffu, acc, o);
    __shared__ float lg[N_EXP];
    if (lane == 0) lg[e] = acc + bias[e];
    __syncthreads();
    if (t == 0) {
        int i1 = 0; float v1 = lg[0];
        for (int i = 1; i < N_EXP; ++i) if (lg[i] > v1) { v1 = lg[i]; i1 = i; }
        int i2 = -1; float v2 = -1e30f;
        for (int i = 0; i < N_EXP; ++i) {
            if (i == i1) continue;
            if (lg[i] > v2) { v2 = lg[i]; i2 = i; }
        }
        int c = (i1 > i2) ? i1 : i2;
        g_chosen[n] = c;
        atomicAdd(&g_counts[c], 1);
    }
}

__global__ void scan_kernel()
{
    if (threadIdx.x == 0) {
        int s = 0;
        for (int e = 0; e < N_EXP; ++e) { g_offsets[e] = s; g_cursor[e] = s; s += g_counts[e]; }
    }
}

__global__ void scatter_kernel()
{
    int n = blockIdx.x * 256 + threadIdx.x;
    if (n < N_TOK) {
        int c = g_chosen[n];
        int p = atomicAdd(&g_cursor[c], 1);
        g_p2t[p] = n;
        g_p2e[p] = c;
    }
}

// ------- per-expert LN + exact GELU; writes split bf16 directly --------------
__global__ void ln_gelu_kernel(const float* __restrict__ hh, const float* __restrict__ ln_g,
                               const float* __restrict__ ln_b,
                               unsigned short* __restrict__ oh, unsigned short* __restrict__ ol)
{
    const int p = blockIdx.x, t = threadIdx.x;
    const int e = g_p2e[p];
    const float* row = hh + (size_t)p * F_DIM;
    const float* gg = ln_g + (size_t)e * F_DIM;
    const float* bb = ln_b + (size_t)e * F_DIM;
    __shared__ float red[256];
    __shared__ float s_mean, s_rstd;
    float s1 = 0.f, s2 = 0.f;
    for (int i = t; i < F_DIM; i += 256) { float v = row[i]; s1 += v; s2 += v * v; }
    red[t] = s1; __syncthreads();
    for (int o = 128; o; o >>= 1) { if (t < o) red[t] += red[t + o]; __syncthreads(); }
    if (t == 0) s_mean = red[0] / F_DIM;
    __syncthreads();
    red[t] = s2; __syncthreads();
    for (int o = 128; o; o >>= 1) { if (t < o) red[t] += red[t + o]; __syncthreads(); }
    if (t == 0) {
        float var = red[0] / F_DIM - s_mean * s_mean;
        s_rstd = rsqrtf(var + 1e-5f);
    }
    __syncthreads();
    for (int i = t; i < F_DIM; i += 256) {
        float tv = (row[i] - s_mean) * s_rstd * gg[i] + bb[i];
        float r = 0.5f * tv * (1.f + erff(tv * 0.70710678118654752f));
        unsigned short hh_, ll_;
        split1(r, hh_, ll_);
        oh[(size_t)p * F_DIM + i] = hh_;
        ol[(size_t)p * F_DIM + i] = ll_;
    }
}

// ---------------- host launcher ---------------------------------------------
extern "C" void kernel_launch(void* const* d_in, const int* in_sizes, int n_in,
                              void* d_out, int out_size)
{
    (void)in_sizes; (void)n_in; (void)out_size;
    const float* src        = (const float*)d_in[0];
    const float* q_w        = (const float*)d_in[1];
    const float* k_w        = (const float*)d_in[2];
    const float* v_w        = (const float*)d_in[3];
    const float* out_w      = (const float*)d_in[4];
    const float* gate_w     = (const float*)d_in[5];
    const float* gate_b     = (const float*)d_in[6];
    const float* scale_w    = (const float*)d_in[7];
    const float* n1_g       = (const float*)d_in[8];
    const float* n1_b       = (const float*)d_in[9];
    const float* n2_g       = (const float*)d_in[10];
    const float* n2_b       = (const float*)d_in[11];
    const float* moe_gate_w = (const float*)d_in[12];
    const float* moe_gate_b = (const float*)d_in[13];
    const float* w1         = (const float*)d_in[14];
    const float* b1         = (const float*)d_in[15];
    const float* ln_g       = (const float*)d_in[16];
    const float* ln_b       = (const float*)d_in[17];
    const float* w2         = (const float*)d_in[18];
    const float* b2         = (const float*)d_in[19];
    const float* res_scale  = (const float*)d_in[20];

    float *attnp, *xb, *hhb, *moeb;
    cudaGetSymbolAddress((void**)&attnp, g_attnp);
    cudaGetSymbolAddress((void**)&xb, g_x);
    cudaGetSymbolAddress((void**)&hhb, g_hh);
    cudaGetSymbolAddress((void**)&moeb, g_moe);

    unsigned short *acth, *actl, *wth, *wtl, *w1h, *w1l, *w2h, *w2l;
    unsigned short *qh, *ql, *kh, *kl, *vh, *vl, *ah, *al, *gh, *gl;
    cudaGetSymbolAddress((void**)&acth, g_act_h);
    cudaGetSymbolAddress((void**)&actl, g_act_l);
    cudaGetSymbolAddress((void**)&wth, g_wt_h);
    cudaGetSymbolAddress((void**)&wtl, g_wt_l);
    cudaGetSymbolAddress((void**)&w1h, g_w1_h);
    cudaGetSymbolAddress((void**)&w1l, g_w1_l);
    cudaGetSymbolAddress((void**)&w2h, g_w2_h);
    cudaGetSymbolAddress((void**)&w2l, g_w2_l);
    cudaGetSymbolAddress((void**)&qh, g_qh);  cudaGetSymbolAddress((void**)&ql, g_ql);
    cudaGetSymbolAddress((void**)&kh, g_kh);  cudaGetSymbolAddress((void**)&kl, g_kl);
    cudaGetSymbolAddress((void**)&vh, g_vh);  cudaGetSymbolAddress((void**)&vl, g_vl);
    cudaGetSymbolAddress((void**)&ah, g_ah);  cudaGetSymbolAddress((void**)&al, g_al);
    cudaGetSymbolAddress((void**)&gh, g_gh);  cudaGetSymbolAddress((void**)&gl, g_gl);

    cudaFuncSetAttribute(attn_mma, cudaFuncAttributeMaxDynamicSharedMemorySize, ATTN_SMEM);
    cudaFuncSetAttribute(gemm_mma_dense, cudaFuncAttributeMaxDynamicSharedMemorySize, MMA_SMEM);
    cudaFuncSetAttribute(gemm_mma_e1, cudaFuncAttributeMaxDynamicSharedMemorySize, MMA_SMEM);
    cudaFuncSetAttribute(gemm_mma_e2, cudaFuncAttributeMaxDynamicSharedMemorySize, MMA_SMEM);

    const size_t WSZ = (size_t)D_DIM * D_DIM;
    const int WN8 = (int)(WSZ / 8);

    // weight splits: one batched launch for the 5 dense weights, two for experts
    {
        Cvt5Args ca;
        ca.src[0] = q_w; ca.src[1] = k_w; ca.src[2] = v_w; ca.src[3] = out_w; ca.src[4] = gate_w;
        cvt8x5_kernel<<<dim3(CVT8_GRID(WN8), 5), 256>>>(ca, wth, wtl, WN8);
    }
    {
        const int n8 = N_EXP * D_DIM * F_DIM / 8;
        cvt8_kernel<<<CVT8_GRID(n8), 256>>>(w1, w1h, w1l, n8);
        cvt8_kernel<<<CVT8_GRID(n8), 256>>>(w2, w2h, w2l, n8);
    }

    reset_kernel<<<1, 32>>>();

    // src split, then QKV (batched z=3)
    cvt8_kernel<<<CVT8_GRID(N_TOK * D_DIM / 8), 256>>>(src, acth, actl, N_TOK * D_DIM / 8);
    {
        DenseArgs da = {};
        for (int z = 0; z < 3; ++z) {
            da.Bh[z] = wth + (size_t)z * WSZ;
            da.Bl[z] = wtl + (size_t)z * WSZ;
            da.mode[z] = 2;
        }
        da.Ch[0] = qh; da.Cl[0] = ql;
        da.Ch[1] = kh; da.Cl[1] = kl;
        da.Ch[2] = vh; da.Cl[2] = vl;
        gemm_mma_dense<<<dim3(8, 16, 3), 256, MMA_SMEM>>>(acth, actl, da, D_DIM, D_DIM);
    }

    attn_mma<<<dim3(8, 32), 256, ATTN_SMEM>>>(qh, ql, kh, kl, vh, vl, scale_w, ah, al);

    {
        DenseArgs da = {};
        da.Bh[0] = wth + 4 * WSZ; da.Bl[0] = wtl + 4 * WSZ;
        da.bias[0] = gate_b;
        da.auxh[0] = ah; da.auxl[0] = al;
        da.Ch[0] = gh; da.Cl[0] = gl;
        da.mode[0] = 1;
        gemm_mma_dense<<<dim3(8, 16, 1), 256, MMA_SMEM>>>(ah, al, da, D_DIM, D_DIM);
    }

    {
        DenseArgs da = {};
        da.Bh[0] = wth + 3 * WSZ; da.Bl[0] = wtl + 3 * WSZ;
        da.C[0] = attnp;
        da.mode[0] = 0;
        gemm_mma_dense<<<dim3(8, 16, 1), 256, MMA_SMEM>>>(gh, gl, da, D_DIM, D_DIM);
    }

    // x = LN(src + attn); also emit x splits for expert GEMM 1 + moe gate input
    ln2_kernel<<<N_TOK, 256>>>(src, attnp, n1_g, n1_b, xb, acth, actl, D_DIM);

    moe_gate_kernel<<<N_TOK, 256>>>(xb, moe_gate_w, moe_gate_b);
    scan_kernel<<<1, 32>>>();
    scatter_kernel<<<N_TOK / 256, 256>>>();

    gemm_mma_e1<<<dim3(F_DIM / 128, N_TOK / 128, N_EXP), 256, MMA_SMEM>>>(
        acth, actl, w1h, w1l, b1, hhb);
    // LN+GELU writes hh splits directly (acth/actl reused; e1 already consumed x splits)
    ln_gelu_kernel<<<N_TOK, 256>>>(hhb, ln_g, ln_b, acth, actl);
    gemm_mma_e2<<<dim3(D_DIM / 128, N_TOK / 128, N_EXP), 256, MMA_SMEM>>>(
        acth, actl, w2h, w2l, b2, res_scale, xb, moeb);

    // final LN (no split out)
    ln2_kernel<<<N_TOK, 256>>>(xb, moeb, n2_g, n2_b, (float*)d_out, nullptr, nullptr, D_DIM);
}